// round 6
// baseline (speedup 1.0000x reference)
#include <cuda_runtime.h>
#include <cuda_bf16.h>
#include <math.h>
#include <stdint.h>

#define NN      60000
#define IN_C    128
#define HID     512
#define D_CAT   1024
#define D_FC    2048
#define D_L1    4096
#define OUT_C   64
#define BN_EPS  1e-5f

#define EPI_NONE    0
#define EPI_RELU    1
#define EPI_BNRELU  2
#define EPI_LEAKY   3
#define EPI_SIGMOID 4

typedef __nv_bfloat16 bf16;

// ---------------------------------------------------------------------------
// Scratch (__device__ globals; no allocations allowed)
// ---------------------------------------------------------------------------
__device__ float g_h[(size_t)NN * IN_C];              // x + agg (fp32, atomics)
__device__ bf16  g_h_hi [(size_t)NN * IN_C ],  g_h_lo [(size_t)NN * IN_C ];
__device__ bf16  g_t_hi [(size_t)NN * HID  ],  g_t_lo [(size_t)NN * HID  ];
__device__ bf16  g_c_hi [(size_t)NN * D_CAT],  g_c_lo [(size_t)NN * D_CAT];
__device__ bf16  g_fc_hi[(size_t)NN * D_FC ],  g_fc_lo[(size_t)NN * D_FC ];
__device__ bf16  g_l1_hi[(size_t)NN * D_L1 ],  g_l1_lo[(size_t)NN * D_L1 ];
__device__ bf16  g_l2_hi[(size_t)NN * D_FC ],  g_l2_lo[(size_t)NN * D_FC ];
// transposed weights [N,K] hi/lo
__device__ bf16 g_w1a_hi[HID * IN_C],   g_w1a_lo[HID * IN_C];
__device__ bf16 g_w2a_hi[HID * HID],    g_w2a_lo[HID * HID];
__device__ bf16 g_w1b_hi[HID * IN_C],   g_w1b_lo[HID * IN_C];
__device__ bf16 g_w2b_hi[HID * HID],    g_w2b_lo[HID * HID];
__device__ bf16 g_wfc_hi[D_FC * D_CAT], g_wfc_lo[D_FC * D_CAT];
__device__ bf16 g_wl1_hi[(size_t)D_L1 * D_FC], g_wl1_lo[(size_t)D_L1 * D_FC];
__device__ bf16 g_wl2_hi[(size_t)D_FC * D_L1], g_wl2_lo[(size_t)D_FC * D_L1];
__device__ bf16 g_wo_hi [OUT_C * D_FC], g_wo_lo [OUT_C * D_FC];

// ---------------------------------------------------------------------------
// helpers
// ---------------------------------------------------------------------------
__device__ __forceinline__ uint32_t smem_u32(const void* p) {
    uint32_t a;
    asm("{ .reg .u64 t; cvta.to.shared.u64 t, %1; cvt.u32.u64 %0, t; }" : "=r"(a) : "l"(p));
    return a;
}

#define LDSM4(r, a) \
    asm volatile("ldmatrix.sync.aligned.m8n8.x4.shared.b16 {%0,%1,%2,%3}, [%4];" \
        : "=r"((r)[0]), "=r"((r)[1]), "=r"((r)[2]), "=r"((r)[3]) : "r"(a))

#define MMA_BF16(d, a, b) \
    asm volatile("mma.sync.aligned.m16n8k16.row.col.f32.bf16.bf16.f32 " \
        "{%0,%1,%2,%3}, {%4,%5,%6,%7}, {%8,%9}, {%0,%1,%2,%3};" \
        : "+f"((d)[0]), "+f"((d)[1]), "+f"((d)[2]), "+f"((d)[3]) \
        : "r"((a)[0]), "r"((a)[1]), "r"((a)[2]), "r"((a)[3]), "r"((b)[0]), "r"((b)[1]))

#define CP_ASYNC(dst, src, ok) \
    asm volatile("cp.async.cg.shared.global [%0], [%1], 16, %2;" \
        :: "r"(dst), "l"(src), "r"(ok) : "memory")
#define CP_COMMIT()  asm volatile("cp.async.commit_group;" ::: "memory")
#define CP_WAIT2()   asm volatile("cp.async.wait_group 2;" ::: "memory")

// ---------------------------------------------------------------------------
// small kernels
// ---------------------------------------------------------------------------
__global__ void copy_x_kernel(const float4* __restrict__ x, float4* __restrict__ h, int n4) {
    int i = blockIdx.x * blockDim.x + threadIdx.x;
    if (i < n4) h[i] = x[i];
}

__global__ void edge_agg_kernel(const float* __restrict__ x, const int* __restrict__ ei,
                                float* __restrict__ h, int n_edges) {
    int warp = (blockIdx.x * blockDim.x + threadIdx.x) >> 5;
    int lane = threadIdx.x & 31;
    if (warp >= n_edges) return;
    int src = ei[warp];
    int dst = ei[n_edges + warp];
    const float4 v = *reinterpret_cast<const float4*>(x + (size_t)src * IN_C + lane * 4);
    float* d = h + (size_t)dst * IN_C + lane * 4;
    atomicAdd(d + 0, v.x); atomicAdd(d + 1, v.y);
    atomicAdd(d + 2, v.z); atomicAdd(d + 3, v.w);
}

__global__ void split_kernel(const float* __restrict__ in, bf16* __restrict__ hi,
                             bf16* __restrict__ lo, int n) {
    int i = blockIdx.x * blockDim.x + threadIdx.x;
    if (i >= n) return;
    float v = in[i];
    bf16 h = __float2bfloat16(v);
    hi[i] = h;
    lo[i] = __float2bfloat16(v - __bfloat162float(h));
}

// W[K,N] fp32 -> Wt[N,K] hi/lo bf16
__global__ void wtrans_kernel(const float* __restrict__ W, bf16* __restrict__ hi,
                              bf16* __restrict__ lo, int K, int N) {
    __shared__ float t[32][33];
    int n0 = blockIdx.x * 32, k0 = blockIdx.y * 32;
#pragma unroll
    for (int dy = 0; dy < 32; dy += 8) {
        int k = k0 + threadIdx.y + dy, n = n0 + threadIdx.x;
        t[threadIdx.y + dy][threadIdx.x] = (k < K && n < N) ? W[(size_t)k * N + n] : 0.f;
    }
    __syncthreads();
#pragma unroll
    for (int dy = 0; dy < 32; dy += 8) {
        int n = n0 + threadIdx.y + dy, k = k0 + threadIdx.x;
        if (n < N && k < K) {
            float v = t[threadIdx.x][threadIdx.y + dy];
            bf16 h = __float2bfloat16(v);
            hi[(size_t)n * K + k] = h;
            lo[(size_t)n * K + k] = __float2bfloat16(v - __bfloat162float(h));
        }
    }
}

// ---------------------------------------------------------------------------
// bf16x3 mma.sync GEMM: C[M,N] = A[M,K] @ Bt[N,K]^T
// BM=256, BN=128, BK=32, 256 threads (warp grid 4Mx2N, warp tile 64x64), 4 stages
// smem tile layout: rows of 64B (32 bf16), chunk swizzle c ^= (row>>1)&3
// Mainloop: term-major MMA ordering (no same-acc RAW chains) + lo-frag loads
// interleaved under term-1 compute.
// ---------------------------------------------------------------------------
#define STAGES    4
#define A_BYTES   16384             // 256 rows * 64 B
#define B_BYTES   8192              // 128 rows * 64 B
#define STAGE_B   (2 * A_BYTES + 2 * B_BYTES)   // Ah, Al, Bh, Bl = 49152
#define OFF_AL    16384
#define OFF_BH    32768
#define OFF_BL    40960
#define SMEM_DYN  (STAGES * STAGE_B)            // 196608

__global__ __launch_bounds__(256, 1)
void gemm_mma_kernel(const bf16* __restrict__ Ah_g, const bf16* __restrict__ Al_g,
                     const bf16* __restrict__ Bh_g, const bf16* __restrict__ Bl_g,
                     bf16* __restrict__ Ch, bf16* __restrict__ Cl,
                     float* __restrict__ Cf,
                     const float* __restrict__ bias,
                     const float* __restrict__ gamma, const float* __restrict__ beta,
                     const float* __restrict__ mean,  const float* __restrict__ var,
                     int M, int N, int K, int ldc, int epi)
{
    extern __shared__ __align__(128) char smem[];
    const uint32_t sb = smem_u32(smem);
    const int tid = threadIdx.x;
    const int lid = tid & 31, wid = tid >> 5;
    const int warpM = wid >> 1, warpN = wid & 1;
    const int m0 = blockIdx.y * 256, n0 = blockIdx.x * 128;
    const int NC = K >> 5;

    float acc[4][8][4];
#pragma unroll
    for (int i = 0; i < 4; i++)
#pragma unroll
        for (int j = 0; j < 8; j++)
#pragma unroll
            for (int q = 0; q < 4; q++) acc[i][j][q] = 0.0f;

    // ---- stage loader: 3072 16B-chunks / 256 threads = 12 per thread ----
    auto issue_stage = [&](int c, int s) {
        const int k0 = c << 5;
        const uint32_t stb = sb + s * STAGE_B;
#pragma unroll
        for (int q = 0; q < 12; q++) {
            int id = q * 256 + tid;
            const bf16* base;
            uint32_t toff;
            int row, ch, gr, rmax;
            if (id < 2048) {                  // A: hi then lo, 256 rows x 4 chunks
                int half = id >> 10;
                int idx = id & 1023;
                row = idx >> 2; ch = idx & 3;
                base = half ? Al_g : Ah_g;
                toff = half ? OFF_AL : 0u;
                gr = m0 + row; rmax = M;
            } else {                          // B: hi then lo, 128 rows x 4 chunks
                int idB = id - 2048;
                int half = idB >> 9;
                int idx = idB & 511;
                row = idx >> 2; ch = idx & 3;
                base = half ? Bl_g : Bh_g;
                toff = half ? (uint32_t)OFF_BL : (uint32_t)OFF_BH;
                gr = n0 + row; rmax = N;
            }
            unsigned ok = (gr < rmax) ? 16u : 0u;
            int rc = (gr < rmax) ? gr : 0;
            const char* src = (const char*)(base + (size_t)rc * K + k0) + ch * 16;
            uint32_t dst = stb + toff + row * 64 + ((ch ^ ((row >> 1) & 3)) << 4);
            CP_ASYNC(dst, src, ok);
        }
        CP_COMMIT();
    };

    issue_stage(0, 0);
    issue_stage(1, 1);
    issue_stage(2, 2);

    const int grp = lid >> 3, lr = lid & 7;

    int s = 0;
    for (int c = 0; c < NC; c++) {
        CP_WAIT2();
        __syncthreads();
        if (c + 3 < NC) issue_stage(c + 3, (s + 3) & 3);
        else CP_COMMIT();

        const uint32_t stb = sb + s * STAGE_B;
#pragma unroll
        for (int ks = 0; ks < 2; ks++) {
            // ---- hi frags first ----
            uint32_t ah[4][4];
#pragma unroll
            for (int i = 0; i < 4; i++) {
                int row = warpM * 64 + i * 16 + lr + ((grp & 1) << 3);
                int chk = 2 * ks + (grp >> 1);
                uint32_t ad = stb + row * 64 + ((chk ^ ((row >> 1) & 3)) << 4);
                LDSM4(ah[i], ad);
            }
            uint32_t bh[8][2];
#pragma unroll
            for (int jj = 0; jj < 4; jj++) {
                int row = warpN * 64 + jj * 16 + lr + ((grp >= 2) ? 8 : 0);
                int chk = 2 * ks + (grp & 1);
                uint32_t bd = stb + OFF_BH + row * 64 + ((chk ^ ((row >> 1) & 3)) << 4);
                uint32_t r[4];
                LDSM4(r, bd);
                bh[2 * jj][0] = r[0]; bh[2 * jj][1] = r[1];
                bh[2 * jj + 1][0] = r[2]; bh[2 * jj + 1][1] = r[3];
            }
            // ---- term 1: ah*bh (32 independent accs) ----
#pragma unroll
            for (int i = 0; i < 4; i++)
#pragma unroll
                for (int j = 0; j < 8; j++)
                    MMA_BF16(acc[i][j], ah[i], bh[j]);
            // ---- lo frags (overlap with term-1 MMAs) ----
            uint32_t al[4][4];
#pragma unroll
            for (int i = 0; i < 4; i++) {
                int row = warpM * 64 + i * 16 + lr + ((grp & 1) << 3);
                int chk = 2 * ks + (grp >> 1);
                uint32_t ad = stb + OFF_AL + row * 64 + ((chk ^ ((row >> 1) & 3)) << 4);
                LDSM4(al[i], ad);
            }
            uint32_t bl[8][2];
#pragma unroll
            for (int jj = 0; jj < 4; jj++) {
                int row = warpN * 64 + jj * 16 + lr + ((grp >= 2) ? 8 : 0);
                int chk = 2 * ks + (grp & 1);
                uint32_t bd = stb + OFF_BL + row * 64 + ((chk ^ ((row >> 1) & 3)) << 4);
                uint32_t r[4];
                LDSM4(r, bd);
                bl[2 * jj][0] = r[0]; bl[2 * jj][1] = r[1];
                bl[2 * jj + 1][0] = r[2]; bl[2 * jj + 1][1] = r[3];
            }
            // ---- term 2: ah*bl ----
#pragma unroll
            for (int i = 0; i < 4; i++)
#pragma unroll
                for (int j = 0; j < 8; j++)
                    MMA_BF16(acc[i][j], ah[i], bl[j]);
            // ---- term 3: al*bh ----
#pragma unroll
            for (int i = 0; i < 4; i++)
#pragma unroll
                for (int j = 0; j < 8; j++)
                    MMA_BF16(acc[i][j], al[i], bh[j]);
        }
        s = (s + 1) & 3;
    }

    // ---- epilogue ----
    const int r_base = m0 + warpM * 64 + (lid >> 2);
    const int c_base = n0 + warpN * 64 + (lid & 3) * 2;
#pragma unroll
    for (int i = 0; i < 4; i++) {
#pragma unroll
        for (int half = 0; half < 2; half++) {
            int row = r_base + i * 16 + half * 8;
            if (row >= M) continue;
#pragma unroll
            for (int j = 0; j < 8; j++) {
                int col = c_base + j * 8;
                if (col >= N) continue;
                float v0 = acc[i][j][half * 2 + 0] + bias[col];
                float v1 = acc[i][j][half * 2 + 1] + bias[col + 1];
                if (epi == EPI_BNRELU) {
                    v0 = (v0 - mean[col])     * rsqrtf(var[col] + BN_EPS)     * gamma[col]     + beta[col];
                    v1 = (v1 - mean[col + 1]) * rsqrtf(var[col + 1] + BN_EPS) * gamma[col + 1] + beta[col + 1];
                    v0 = fmaxf(v0, 0.0f); v1 = fmaxf(v1, 0.0f);
                } else if (epi == EPI_RELU) {
                    v0 = fmaxf(v0, 0.0f); v1 = fmaxf(v1, 0.0f);
                } else if (epi == EPI_LEAKY) {
                    v0 = (v0 > 0.0f) ? v0 : 0.01f * v0;
                    v1 = (v1 > 0.0f) ? v1 : 0.01f * v1;
                }
                if (epi == EPI_SIGMOID) {
                    float2 o;
                    o.x = 1.0f / (1.0f + expf(-v0));
                    o.y = 1.0f / (1.0f + expf(-v1));
                    *(float2*)(Cf + (size_t)row * ldc + col) = o;
                } else {
                    bf16 h0 = __float2bfloat16(v0);
                    bf16 h1 = __float2bfloat16(v1);
                    *(__nv_bfloat162*)(Ch + (size_t)row * ldc + col) = __nv_bfloat162(h0, h1);
                    *(__nv_bfloat162*)(Cl + (size_t)row * ldc + col) = __nv_bfloat162(
                        __float2bfloat16(v0 - __bfloat162float(h0)),
                        __float2bfloat16(v1 - __bfloat162float(h1)));
                }
            }
        }
    }
}

// ---------------------------------------------------------------------------
// launch
// ---------------------------------------------------------------------------
static void launch_gemm(const bf16* Ah, const bf16* Al, const bf16* Bh, const bf16* Bl,
                        bf16* Ch, bf16* Cl, float* Cf, const float* bias,
                        const float* ga, const float* be, const float* me, const float* va,
                        int M, int N, int K, int ldc, int epi) {
    dim3 grid((N + 127) / 128, (M + 255) / 256);
    gemm_mma_kernel<<<grid, 256, SMEM_DYN>>>(Ah, Al, Bh, Bl, Ch, Cl, Cf, bias,
                                             ga, be, me, va, M, N, K, ldc, epi);
}

template <typename T> static T* sym(T* symbol) {
    void* p = nullptr;
    cudaGetSymbolAddress(&p, (const void*)symbol);
    return (T*)p;
}

extern "C" void kernel_launch(void* const* d_in, const int* in_sizes, int n_in,
                              void* d_out, int out_size) {
    const float* x  = (const float*)d_in[0];
    const int*   ei = (const int*)d_in[1];
    const float *w1a = (const float*)d_in[2],  *b1a = (const float*)d_in[3];
    const float *ga  = (const float*)d_in[4],  *bea = (const float*)d_in[5];
    const float *ma  = (const float*)d_in[6],  *va  = (const float*)d_in[7];
    const float *w2a = (const float*)d_in[8],  *b2a = (const float*)d_in[9];
    const float *w1b = (const float*)d_in[10], *b1b = (const float*)d_in[11];
    const float *gb  = (const float*)d_in[12], *beb = (const float*)d_in[13];
    const float *mb  = (const float*)d_in[14], *vb  = (const float*)d_in[15];
    const float *w2b = (const float*)d_in[16], *b2b = (const float*)d_in[17];
    const float *fcw = (const float*)d_in[18], *fcb = (const float*)d_in[19];
    const float *l1w = (const float*)d_in[20], *l1b = (const float*)d_in[21];
    const float *l2w = (const float*)d_in[22], *l2b = (const float*)d_in[23];
    const float *ow  = (const float*)d_in[24], *ob  = (const float*)d_in[25];
    float* out = (float*)d_out;

    cudaFuncSetAttribute(gemm_mma_kernel,
                         cudaFuncAttributeMaxDynamicSharedMemorySize, SMEM_DYN);

    float* h = sym(g_h);
    bf16 *hhi = sym(g_h_hi), *hlo = sym(g_h_lo);
    bf16 *thi = sym(g_t_hi), *tlo = sym(g_t_lo);
    bf16 *chi = sym(g_c_hi), *clo = sym(g_c_lo);
    bf16 *fhi = sym(g_fc_hi), *flo = sym(g_fc_lo);
    bf16 *l1hi = sym(g_l1_hi), *l1lo = sym(g_l1_lo);
    bf16 *l2hi = sym(g_l2_hi), *l2lo = sym(g_l2_lo);
    bf16 *w1ah = sym(g_w1a_hi), *w1al = sym(g_w1a_lo);
    bf16 *w2ah = sym(g_w2a_hi), *w2al = sym(g_w2a_lo);
    bf16 *w1bh = sym(g_w1b_hi), *w1bl = sym(g_w1b_lo);
    bf16 *w2bh = sym(g_w2b_hi), *w2bl = sym(g_w2b_lo);
    bf16 *wfh = sym(g_wfc_hi), *wfl = sym(g_wfc_lo);
    bf16 *wl1h = sym(g_wl1_hi), *wl1l = sym(g_wl1_lo);
    bf16 *wl2h = sym(g_wl2_hi), *wl2l = sym(g_wl2_lo);
    bf16 *woh = sym(g_wo_hi), *wol = sym(g_wo_lo);

    const int n_edges = in_sizes[1] / 2;

    // aggregation (fp32) + split
    {
        int n4 = NN * IN_C / 4;
        copy_x_kernel<<<(n4 + 255) / 256, 256>>>((const float4*)x, (float4*)h, n4);
        long long nthreads = (long long)n_edges * 32;
        edge_agg_kernel<<<(int)((nthreads + 255) / 256), 256>>>(x, ei, h, n_edges);
        int n = NN * IN_C;
        split_kernel<<<(n + 255) / 256, 256>>>(h, hhi, hlo, n);
    }
    // weight transpose + split
    {
        dim3 b(32, 8);
        wtrans_kernel<<<dim3(HID / 32,  IN_C / 32), b>>>(w1a, w1ah, w1al, IN_C, HID);
        wtrans_kernel<<<dim3(HID / 32,  HID / 32), b>>>(w2a, w2ah, w2al, HID, HID);
        wtrans_kernel<<<dim3(HID / 32,  IN_C / 32), b>>>(w1b, w1bh, w1bl, IN_C, HID);
        wtrans_kernel<<<dim3(HID / 32,  HID / 32), b>>>(w2b, w2bh, w2bl, HID, HID);
        wtrans_kernel<<<dim3(D_FC / 32, D_CAT / 32), b>>>(fcw, wfh, wfl, D_CAT, D_FC);
        wtrans_kernel<<<dim3(D_L1 / 32, D_FC / 32), b>>>(l1w, wl1h, wl1l, D_FC, D_L1);
        wtrans_kernel<<<dim3(D_FC / 32, D_L1 / 32), b>>>(l2w, wl2h, wl2l, D_L1, D_FC);
        wtrans_kernel<<<dim3(OUT_C / 32, D_FC / 32), b>>>(ow, woh, wol, D_FC, OUT_C);
    }

    // conv A
    launch_gemm(hhi, hlo, w1ah, w1al, thi, tlo, 0, b1a, ga, bea, ma, va,
                NN, HID, IN_C, HID, EPI_BNRELU);
    launch_gemm(thi, tlo, w2ah, w2al, chi, clo, 0, b2a, 0, 0, 0, 0,
                NN, HID, HID, D_CAT, EPI_RELU);
    // conv B
    launch_gemm(hhi, hlo, w1bh, w1bl, thi, tlo, 0, b1b, gb, beb, mb, vb,
                NN, HID, IN_C, HID, EPI_BNRELU);
    launch_gemm(thi, tlo, w2bh, w2bl, chi + HID, clo + HID, 0, b2b, 0, 0, 0, 0,
                NN, HID, HID, D_CAT, EPI_RELU);
    // head
    launch_gemm(chi, clo, wfh, wfl, fhi, flo, 0, fcb, 0, 0, 0, 0,
                NN, D_FC, D_CAT, D_FC, EPI_LEAKY);
    launch_gemm(fhi, flo, wl1h, wl1l, l1hi, l1lo, 0, l1b, 0, 0, 0, 0,
                NN, D_L1, D_FC, D_L1, EPI_NONE);
    launch_gemm(l1hi, l1lo, wl2h, wl2l, l2hi, l2lo, 0, l2b, 0, 0, 0, 0,
                NN, D_FC, D_L1, D_FC, EPI_NONE);
    launch_gemm(l2hi, l2lo, woh, wol, 0, 0, out, ob, 0, 0, 0, 0,
                NN, OUT_C, D_FC, OUT_C, EPI_SIGMOID);
}

// round 7
// speedup vs baseline: 2.3037x; 2.3037x over previous
#include <cuda_runtime.h>
#include <cuda_bf16.h>
#include <math.h>
#include <stdint.h>

#define NN      60000
#define IN_C    128
#define HID     512
#define D_CAT   1024
#define D_FC    2048
#define D_L1    4096
#define OUT_C   64
#define BN_EPS  1e-5f

#define EPI_NONE    0
#define EPI_RELU    1
#define EPI_BNRELU  2
#define EPI_LEAKY   3
#define EPI_SIGMOID 4

typedef __nv_bfloat16 bf16;

// ---------------------------------------------------------------------------
// Scratch (__device__ globals; no allocations allowed)
// ---------------------------------------------------------------------------
__device__ float g_h[(size_t)NN * IN_C];              // x + agg (fp32, atomics)
__device__ bf16  g_h_hi [(size_t)NN * IN_C ],  g_h_lo [(size_t)NN * IN_C ];
__device__ bf16  g_t_hi [(size_t)NN * HID  ],  g_t_lo [(size_t)NN * HID  ];
__device__ bf16  g_c_hi [(size_t)NN * D_CAT],  g_c_lo [(size_t)NN * D_CAT];
__device__ bf16  g_fc_hi[(size_t)NN * D_FC ],  g_fc_lo[(size_t)NN * D_FC ];
__device__ bf16  g_l2_hi[(size_t)NN * D_FC ],  g_l2_lo[(size_t)NN * D_FC ];
// transposed weights [N,K] hi/lo
__device__ bf16 g_w1a_hi[HID * IN_C],   g_w1a_lo[HID * IN_C];
__device__ bf16 g_w2a_hi[HID * HID],    g_w2a_lo[HID * HID];
__device__ bf16 g_w1b_hi[HID * IN_C],   g_w1b_lo[HID * IN_C];
__device__ bf16 g_w2b_hi[HID * HID],    g_w2b_lo[HID * HID];
__device__ bf16 g_wfc_hi[D_FC * D_CAT], g_wfc_lo[D_FC * D_CAT];
__device__ bf16 g_wl1_hi[(size_t)D_L1 * D_FC], g_wl1_lo[(size_t)D_L1 * D_FC]; // plain split of l1_w [2048,4096]
__device__ bf16 g_wl2_hi[(size_t)D_FC * D_L1], g_wl2_lo[(size_t)D_FC * D_L1]; // l2_w^T [2048,4096]
__device__ bf16 g_wo_hi [OUT_C * D_FC], g_wo_lo [OUT_C * D_FC];
// folded l1@l2 weight: W'^T [2048 (n), 2048 (k)] split, + folded bias
__device__ bf16  g_wc_hi[(size_t)D_FC * D_FC], g_wc_lo[(size_t)D_FC * D_FC];
__device__ float g_biasc[D_FC];
__device__ float g_zerobias[D_FC];   // stays zero (module-load zero-init, never written)

// ---------------------------------------------------------------------------
// helpers
// ---------------------------------------------------------------------------
__device__ __forceinline__ uint32_t smem_u32(const void* p) {
    uint32_t a;
    asm("{ .reg .u64 t; cvta.to.shared.u64 t, %1; cvt.u32.u64 %0, t; }" : "=r"(a) : "l"(p));
    return a;
}

#define LDSM4(r, a) \
    asm volatile("ldmatrix.sync.aligned.m8n8.x4.shared.b16 {%0,%1,%2,%3}, [%4];" \
        : "=r"((r)[0]), "=r"((r)[1]), "=r"((r)[2]), "=r"((r)[3]) : "r"(a))

#define MMA_BF16(d, a, b) \
    asm volatile("mma.sync.aligned.m16n8k16.row.col.f32.bf16.bf16.f32 " \
        "{%0,%1,%2,%3}, {%4,%5,%6,%7}, {%8,%9}, {%0,%1,%2,%3};" \
        : "+f"((d)[0]), "+f"((d)[1]), "+f"((d)[2]), "+f"((d)[3]) \
        : "r"((a)[0]), "r"((a)[1]), "r"((a)[2]), "r"((a)[3]), "r"((b)[0]), "r"((b)[1]))

#define CP_ASYNC(dst, src, ok) \
    asm volatile("cp.async.cg.shared.global [%0], [%1], 16, %2;" \
        :: "r"(dst), "l"(src), "r"(ok) : "memory")
#define CP_COMMIT()  asm volatile("cp.async.commit_group;" ::: "memory")
#define CP_WAIT2()   asm volatile("cp.async.wait_group 2;" ::: "memory")

// ---------------------------------------------------------------------------
// small kernels
// ---------------------------------------------------------------------------
__global__ void copy_x_kernel(const float4* __restrict__ x, float4* __restrict__ h, int n4) {
    int i = blockIdx.x * blockDim.x + threadIdx.x;
    if (i < n4) h[i] = x[i];
}

__global__ void edge_agg_kernel(const float* __restrict__ x, const int* __restrict__ ei,
                                float* __restrict__ h, int n_edges) {
    int warp = (blockIdx.x * blockDim.x + threadIdx.x) >> 5;
    int lane = threadIdx.x & 31;
    if (warp >= n_edges) return;
    int src = ei[warp];
    int dst = ei[n_edges + warp];
    const float4 v = *reinterpret_cast<const float4*>(x + (size_t)src * IN_C + lane * 4);
    float* d = h + (size_t)dst * IN_C + lane * 4;
    atomicAdd(d + 0, v.x); atomicAdd(d + 1, v.y);
    atomicAdd(d + 2, v.z); atomicAdd(d + 3, v.w);
}

__global__ void split_kernel(const float* __restrict__ in, bf16* __restrict__ hi,
                             bf16* __restrict__ lo, int n) {
    int i = blockIdx.x * blockDim.x + threadIdx.x;
    if (i >= n) return;
    float v = in[i];
    bf16 h = __float2bfloat16(v);
    hi[i] = h;
    lo[i] = __float2bfloat16(v - __bfloat162float(h));
}

// W[K,N] fp32 -> Wt[N,K] hi/lo bf16
__global__ void wtrans_kernel(const float* __restrict__ W, bf16* __restrict__ hi,
                              bf16* __restrict__ lo, int K, int N) {
    __shared__ float t[32][33];
    int n0 = blockIdx.x * 32, k0 = blockIdx.y * 32;
#pragma unroll
    for (int dy = 0; dy < 32; dy += 8) {
        int k = k0 + threadIdx.y + dy, n = n0 + threadIdx.x;
        t[threadIdx.y + dy][threadIdx.x] = (k < K && n < N) ? W[(size_t)k * N + n] : 0.f;
    }
    __syncthreads();
#pragma unroll
    for (int dy = 0; dy < 32; dy += 8) {
        int n = n0 + threadIdx.y + dy, k = k0 + threadIdx.x;
        if (n < N && k < K) {
            float v = t[threadIdx.x][threadIdx.y + dy];
            bf16 h = __float2bfloat16(v);
            hi[(size_t)n * K + k] = h;
            lo[(size_t)n * K + k] = __float2bfloat16(v - __bfloat162float(h));
        }
    }
}

// b'[n] = l2_b[n] + sum_k l1_b[k] * l2_w[k,n]
__global__ void bias_fold_kernel(const float* __restrict__ l1b,
                                 const float* __restrict__ l2w,
                                 const float* __restrict__ l2b,
                                 float* __restrict__ outb) {
    int n = blockIdx.x * blockDim.x + threadIdx.x;
    if (n >= D_FC) return;
    float s = l2b[n];
    for (int k = 0; k < D_L1; k++)
        s += l1b[k] * l2w[(size_t)k * D_FC + n];
    outb[n] = s;
}

// ---------------------------------------------------------------------------
// bf16x3 mma.sync GEMM: C[M,N] = A[M,K] @ Bt[N,K]^T
// BM=256, BN=128, BK=32, 256 threads (warp grid 4Mx2N, warp tile 64x64), 4 stages
// ---------------------------------------------------------------------------
#define STAGES    4
#define A_BYTES   16384             // 256 rows * 64 B
#define B_BYTES   8192              // 128 rows * 64 B
#define STAGE_B   (2 * A_BYTES + 2 * B_BYTES)   // Ah, Al, Bh, Bl = 49152
#define OFF_AL    16384
#define OFF_BH    32768
#define OFF_BL    40960
#define SMEM_DYN  (STAGES * STAGE_B)            // 196608

__global__ __launch_bounds__(256, 1)
void gemm_mma_kernel(const bf16* __restrict__ Ah_g, const bf16* __restrict__ Al_g,
                     const bf16* __restrict__ Bh_g, const bf16* __restrict__ Bl_g,
                     bf16* __restrict__ Ch, bf16* __restrict__ Cl,
                     float* __restrict__ Cf,
                     const float* __restrict__ bias,
                     const float* __restrict__ gamma, const float* __restrict__ beta,
                     const float* __restrict__ mean,  const float* __restrict__ var,
                     int M, int N, int K, int ldc, int epi)
{
    extern __shared__ __align__(128) char smem[];
    const uint32_t sb = smem_u32(smem);
    const int tid = threadIdx.x;
    const int lid = tid & 31, wid = tid >> 5;
    const int warpM = wid >> 1, warpN = wid & 1;
    const int m0 = blockIdx.y * 256, n0 = blockIdx.x * 128;
    const int NC = K >> 5;

    float acc[4][8][4];
#pragma unroll
    for (int i = 0; i < 4; i++)
#pragma unroll
        for (int j = 0; j < 8; j++)
#pragma unroll
            for (int q = 0; q < 4; q++) acc[i][j][q] = 0.0f;

    // ---- stage loader: 3072 16B-chunks / 256 threads = 12 per thread ----
    auto issue_stage = [&](int c, int s) {
        const int k0 = c << 5;
        const uint32_t stb = sb + s * STAGE_B;
#pragma unroll
        for (int q = 0; q < 12; q++) {
            int id = q * 256 + tid;
            const bf16* base;
            uint32_t toff;
            int row, ch, gr, rmax;
            if (id < 2048) {                  // A: hi then lo, 256 rows x 4 chunks
                int half = id >> 10;
                int idx = id & 1023;
                row = idx >> 2; ch = idx & 3;
                base = half ? Al_g : Ah_g;
                toff = half ? OFF_AL : 0u;
                gr = m0 + row; rmax = M;
            } else {                          // B: hi then lo, 128 rows x 4 chunks
                int idB = id - 2048;
                int half = idB >> 9;
                int idx = idB & 511;
                row = idx >> 2; ch = idx & 3;
                base = half ? Bl_g : Bh_g;
                toff = half ? (uint32_t)OFF_BL : (uint32_t)OFF_BH;
                gr = n0 + row; rmax = N;
            }
            unsigned ok = (gr < rmax) ? 16u : 0u;
            int rc = (gr < rmax) ? gr : 0;
            const char* src = (const char*)(base + (size_t)rc * K + k0) + ch * 16;
            uint32_t dst = stb + toff + row * 64 + ((ch ^ ((row >> 1) & 3)) << 4);
            CP_ASYNC(dst, src, ok);
        }
        CP_COMMIT();
    };

    issue_stage(0, 0);
    issue_stage(1, 1);
    issue_stage(2, 2);

    const int grp = lid >> 3, lr = lid & 7;

    int s = 0;
    for (int c = 0; c < NC; c++) {
        CP_WAIT2();
        __syncthreads();
        if (c + 3 < NC) issue_stage(c + 3, (s + 3) & 3);
        else CP_COMMIT();

        const uint32_t stb = sb + s * STAGE_B;
#pragma unroll
        for (int ks = 0; ks < 2; ks++) {
            uint32_t ah[4][4];
#pragma unroll
            for (int i = 0; i < 4; i++) {
                int row = warpM * 64 + i * 16 + lr + ((grp & 1) << 3);
                int chk = 2 * ks + (grp >> 1);
                uint32_t ad = stb + row * 64 + ((chk ^ ((row >> 1) & 3)) << 4);
                LDSM4(ah[i], ad);
            }
            uint32_t bh[8][2];
#pragma unroll
            for (int jj = 0; jj < 4; jj++) {
                int row = warpN * 64 + jj * 16 + lr + ((grp >= 2) ? 8 : 0);
                int chk = 2 * ks + (grp & 1);
                uint32_t bd = stb + OFF_BH + row * 64 + ((chk ^ ((row >> 1) & 3)) << 4);
                uint32_t r[4];
                LDSM4(r, bd);
                bh[2 * jj][0] = r[0]; bh[2 * jj][1] = r[1];
                bh[2 * jj + 1][0] = r[2]; bh[2 * jj + 1][1] = r[3];
            }
#pragma unroll
            for (int i = 0; i < 4; i++)
#pragma unroll
                for (int j = 0; j < 8; j++)
                    MMA_BF16(acc[i][j], ah[i], bh[j]);
            uint32_t al[4][4];
#pragma unroll
            for (int i = 0; i < 4; i++) {
                int row = warpM * 64 + i * 16 + lr + ((grp & 1) << 3);
                int chk = 2 * ks + (grp >> 1);
                uint32_t ad = stb + OFF_AL + row * 64 + ((chk ^ ((row >> 1) & 3)) << 4);
                LDSM4(al[i], ad);
            }
            uint32_t bl[8][2];
#pragma unroll
            for (int jj = 0; jj < 4; jj++) {
                int row = warpN * 64 + jj * 16 + lr + ((grp >= 2) ? 8 : 0);
                int chk = 2 * ks + (grp & 1);
                uint32_t bd = stb + OFF_BL + row * 64 + ((chk ^ ((row >> 1) & 3)) << 4);
                uint32_t r[4];
                LDSM4(r, bd);
                bl[2 * jj][0] = r[0]; bl[2 * jj][1] = r[1];
                bl[2 * jj + 1][0] = r[2]; bl[2 * jj + 1][1] = r[3];
            }
#pragma unroll
            for (int i = 0; i < 4; i++)
#pragma unroll
                for (int j = 0; j < 8; j++) {
                    MMA_BF16(acc[i][j], ah[i], bl[j]);
                    MMA_BF16(acc[i][j], al[i], bh[j]);
                }
        }
        s = (s + 1) & 3;
    }

    // ---- epilogue ----
    const int r_base = m0 + warpM * 64 + (lid >> 2);
    const int c_base = n0 + warpN * 64 + (lid & 3) * 2;
#pragma unroll
    for (int i = 0; i < 4; i++) {
#pragma unroll
        for (int half = 0; half < 2; half++) {
            int row = r_base + i * 16 + half * 8;
            if (row >= M) continue;
#pragma unroll
            for (int j = 0; j < 8; j++) {
                int col = c_base + j * 8;
                if (col >= N) continue;
                float v0 = acc[i][j][half * 2 + 0] + bias[col];
                float v1 = acc[i][j][half * 2 + 1] + bias[col + 1];
                if (epi == EPI_BNRELU) {
                    v0 = (v0 - mean[col])     * rsqrtf(var[col] + BN_EPS)     * gamma[col]     + beta[col];
                    v1 = (v1 - mean[col + 1]) * rsqrtf(var[col + 1] + BN_EPS) * gamma[col + 1] + beta[col + 1];
                    v0 = fmaxf(v0, 0.0f); v1 = fmaxf(v1, 0.0f);
                } else if (epi == EPI_RELU) {
                    v0 = fmaxf(v0, 0.0f); v1 = fmaxf(v1, 0.0f);
                } else if (epi == EPI_LEAKY) {
                    v0 = (v0 > 0.0f) ? v0 : 0.01f * v0;
                    v1 = (v1 > 0.0f) ? v1 : 0.01f * v1;
                }
                if (epi == EPI_SIGMOID) {
                    float2 o;
                    o.x = 1.0f / (1.0f + expf(-v0));
                    o.y = 1.0f / (1.0f + expf(-v1));
                    *(float2*)(Cf + (size_t)row * ldc + col) = o;
                } else {
                    bf16 h0 = __float2bfloat16(v0);
                    bf16 h1 = __float2bfloat16(v1);
                    *(__nv_bfloat162*)(Ch + (size_t)row * ldc + col) = __nv_bfloat162(h0, h1);
                    *(__nv_bfloat162*)(Cl + (size_t)row * ldc + col) = __nv_bfloat162(
                        __float2bfloat16(v0 - __bfloat162float(h0)),
                        __float2bfloat16(v1 - __bfloat162float(h1)));
                }
            }
        }
    }
}

// ---------------------------------------------------------------------------
// launch
// ---------------------------------------------------------------------------
static void launch_gemm(const bf16* Ah, const bf16* Al, const bf16* Bh, const bf16* Bl,
                        bf16* Ch, bf16* Cl, float* Cf, const float* bias,
                        const float* ga, const float* be, const float* me, const float* va,
                        int M, int N, int K, int ldc, int epi) {
    dim3 grid((N + 127) / 128, (M + 255) / 256);
    gemm_mma_kernel<<<grid, 256, SMEM_DYN>>>(Ah, Al, Bh, Bl, Ch, Cl, Cf, bias,
                                             ga, be, me, va, M, N, K, ldc, epi);
}

template <typename T> static T* sym(T* symbol) {
    void* p = nullptr;
    cudaGetSymbolAddress(&p, (const void*)symbol);
    return (T*)p;
}

extern "C" void kernel_launch(void* const* d_in, const int* in_sizes, int n_in,
                              void* d_out, int out_size) {
    const float* x  = (const float*)d_in[0];
    const int*   ei = (const int*)d_in[1];
    const float *w1a = (const float*)d_in[2],  *b1a = (const float*)d_in[3];
    const float *ga  = (const float*)d_in[4],  *bea = (const float*)d_in[5];
    const float *ma  = (const float*)d_in[6],  *va  = (const float*)d_in[7];
    const float *w2a = (const float*)d_in[8],  *b2a = (const float*)d_in[9];
    const float *w1b = (const float*)d_in[10], *b1b = (const float*)d_in[11];
    const float *gb  = (const float*)d_in[12], *beb = (const float*)d_in[13];
    const float *mb  = (const float*)d_in[14], *vb  = (const float*)d_in[15];
    const float *w2b = (const float*)d_in[16], *b2b = (const float*)d_in[17];
    const float *fcw = (const float*)d_in[18], *fcb = (const float*)d_in[19];
    const float *l1w = (const float*)d_in[20], *l1b = (const float*)d_in[21];
    const float *l2w = (const float*)d_in[22], *l2b = (const float*)d_in[23];
    const float *ow  = (const float*)d_in[24], *ob  = (const float*)d_in[25];
    float* out = (float*)d_out;

    cudaFuncSetAttribute(gemm_mma_kernel,
                         cudaFuncAttributeMaxDynamicSharedMemorySize, SMEM_DYN);

    float* h = sym(g_h);
    bf16 *hhi = sym(g_h_hi), *hlo = sym(g_h_lo);
    bf16 *thi = sym(g_t_hi), *tlo = sym(g_t_lo);
    bf16 *chi = sym(g_c_hi), *clo = sym(g_c_lo);
    bf16 *fhi = sym(g_fc_hi), *flo = sym(g_fc_lo);
    bf16 *l2hi = sym(g_l2_hi), *l2lo = sym(g_l2_lo);
    bf16 *w1ah = sym(g_w1a_hi), *w1al = sym(g_w1a_lo);
    bf16 *w2ah = sym(g_w2a_hi), *w2al = sym(g_w2a_lo);
    bf16 *w1bh = sym(g_w1b_hi), *w1bl = sym(g_w1b_lo);
    bf16 *w2bh = sym(g_w2b_hi), *w2bl = sym(g_w2b_lo);
    bf16 *wfh = sym(g_wfc_hi), *wfl = sym(g_wfc_lo);
    bf16 *wl1h = sym(g_wl1_hi), *wl1l = sym(g_wl1_lo);
    bf16 *wl2h = sym(g_wl2_hi), *wl2l = sym(g_wl2_lo);
    bf16 *woh = sym(g_wo_hi), *wol = sym(g_wo_lo);
    bf16 *wch = sym(g_wc_hi), *wcl = sym(g_wc_lo);
    float *biasc = sym(g_biasc), *zerob = sym(g_zerobias);

    const int n_edges = in_sizes[1] / 2;

    // aggregation (fp32) + split
    {
        int n4 = NN * IN_C / 4;
        copy_x_kernel<<<(n4 + 255) / 256, 256>>>((const float4*)x, (float4*)h, n4);
        long long nthreads = (long long)n_edges * 32;
        edge_agg_kernel<<<(int)((nthreads + 255) / 256), 256>>>(x, ei, h, n_edges);
        int n = NN * IN_C;
        split_kernel<<<(n + 255) / 256, 256>>>(h, hhi, hlo, n);
    }
    // weight transpose + split
    {
        dim3 b(32, 8);
        wtrans_kernel<<<dim3(HID / 32,  IN_C / 32), b>>>(w1a, w1ah, w1al, IN_C, HID);
        wtrans_kernel<<<dim3(HID / 32,  HID / 32), b>>>(w2a, w2ah, w2al, HID, HID);
        wtrans_kernel<<<dim3(HID / 32,  IN_C / 32), b>>>(w1b, w1bh, w1bl, IN_C, HID);
        wtrans_kernel<<<dim3(HID / 32,  HID / 32), b>>>(w2b, w2bh, w2bl, HID, HID);
        wtrans_kernel<<<dim3(D_FC / 32, D_CAT / 32), b>>>(fcw, wfh, wfl, D_CAT, D_FC);
        // l2_w^T [D_FC, D_L1] (A operand of the fold GEMM)
        wtrans_kernel<<<dim3(D_FC / 32, D_L1 / 32), b>>>(l2w, wl2h, wl2l, D_L1, D_FC);
        wtrans_kernel<<<dim3(OUT_C / 32, D_FC / 32), b>>>(ow, woh, wol, D_FC, OUT_C);
        // plain split of l1_w [D_FC, D_L1] row-major (B operand of the fold GEMM)
        int n = D_FC * D_L1;
        split_kernel<<<(n + 255) / 256, 256>>>(l1w, wl1h, wl1l, n);
        // folded bias b' = l1_b @ l2_w + l2_b
        bias_fold_kernel<<<D_FC / 256, 256>>>(l1b, l2w, l2b, biasc);
    }

    // Fold l1@l2: C'[i,j] = sum_k l2_w[k,i] * l1_w[j,k] = W'^T[i,j]
    // A = l2_w^T [2048,4096], B(t-format) = l1_w [2048,4096]  ->  g_wc = W'^T split
    launch_gemm(wl2h, wl2l, wl1h, wl1l, wch, wcl, 0, zerob, 0, 0, 0, 0,
                D_FC, D_FC, D_L1, D_FC, EPI_NONE);

    // conv A
    launch_gemm(hhi, hlo, w1ah, w1al, thi, tlo, 0, b1a, ga, bea, ma, va,
                NN, HID, IN_C, HID, EPI_BNRELU);
    launch_gemm(thi, tlo, w2ah, w2al, chi, clo, 0, b2a, 0, 0, 0, 0,
                NN, HID, HID, D_CAT, EPI_RELU);
    // conv B
    launch_gemm(hhi, hlo, w1bh, w1bl, thi, tlo, 0, b1b, gb, beb, mb, vb,
                NN, HID, IN_C, HID, EPI_BNRELU);
    launch_gemm(thi, tlo, w2bh, w2bl, chi + HID, clo + HID, 0, b2b, 0, 0, 0, 0,
                NN, HID, HID, D_CAT, EPI_RELU);
    // head
    launch_gemm(chi, clo, wfh, wfl, fhi, flo, 0, fcb, 0, 0, 0, 0,
                NN, D_FC, D_CAT, D_FC, EPI_LEAKY);
    // combined l1+l2 layer (exact algebraic fold)
    launch_gemm(fhi, flo, wch, wcl, l2hi, l2lo, 0, biasc, 0, 0, 0, 0,
                NN, D_FC, D_FC, D_FC, EPI_NONE);
    launch_gemm(l2hi, l2lo, woh, wol, 0, 0, out, ob, 0, 0, 0, 0,
                NN, OUT_C, D_FC, OUT_C, EPI_SIGMOID);
}

// round 8
// speedup vs baseline: 4.1855x; 1.8169x over previous
#include <cuda_runtime.h>
#include <cuda_bf16.h>
#include <math.h>
#include <stdint.h>

#define NN      60000
#define IN_C    128
#define HID     512
#define D_CAT   1024
#define D_FC    2048
#define D_L1    4096
#define OUT_C   64
#define BN_EPS  1e-5f

#define EPI_NONE    0
#define EPI_RELU    1
#define EPI_BNRELU  2
#define EPI_LEAKY   3
#define EPI_SIGMOID 4

typedef __nv_bfloat16 bf16;

// ---------------------------------------------------------------------------
// Scratch (__device__ globals; no allocations allowed)
// ---------------------------------------------------------------------------
__device__ float g_h[(size_t)NN * IN_C];              // x + agg (fp32, atomics)
__device__ bf16  g_h_hi [(size_t)NN * IN_C ],  g_h_lo [(size_t)NN * IN_C ];
__device__ bf16  g_t_hi [(size_t)NN * HID  ],  g_t_lo [(size_t)NN * HID  ];
__device__ bf16  g_c_hi [(size_t)NN * D_CAT],  g_c_lo [(size_t)NN * D_CAT];
__device__ bf16  g_fc_hi[(size_t)NN * D_FC ],  g_fc_lo[(size_t)NN * D_FC ];
// transposed weights [N,K] hi/lo
__device__ bf16 g_w1a_hi[HID * IN_C],   g_w1a_lo[HID * IN_C];
__device__ bf16 g_w2a_hi[HID * HID],    g_w2a_lo[HID * HID];
__device__ bf16 g_w1b_hi[HID * IN_C],   g_w1b_lo[HID * IN_C];
__device__ bf16 g_w2b_hi[HID * HID],    g_w2b_lo[HID * HID];
__device__ bf16 g_wfc_hi[D_FC * D_CAT], g_wfc_lo[D_FC * D_CAT];
__device__ bf16 g_wl1_hi[(size_t)D_FC * D_L1], g_wl1_lo[(size_t)D_FC * D_L1]; // plain split of l1_w [2048,4096]
__device__ bf16 g_wl2_hi[(size_t)D_L1 * D_FC], g_wl2_lo[(size_t)D_L1 * D_FC]; // plain split of l2_w [4096,2048]
__device__ bf16 g_wo_hi [OUT_C * D_FC], g_wo_lo [OUT_C * D_FC];               // out_w^T [64,2048]
// fold intermediates / results
__device__ bf16  g_w2c_hi [OUT_C * D_L1],  g_w2c_lo [OUT_C * D_L1];   // (l2@out)^T [64,4096]
__device__ bf16  g_wall_hi[OUT_C * D_FC],  g_wall_lo[OUT_C * D_FC];   // W_all^T   [64,2048]
__device__ float g_bias1[D_FC];      // l1_b@l2_w + l2_b
__device__ float g_ball [OUT_C];     // folded final bias
__device__ float g_zerobias[D_L1];   // stays zero (module-load zero-init, never written)

// ---------------------------------------------------------------------------
// helpers
// ---------------------------------------------------------------------------
__device__ __forceinline__ uint32_t smem_u32(const void* p) {
    uint32_t a;
    asm("{ .reg .u64 t; cvta.to.shared.u64 t, %1; cvt.u32.u64 %0, t; }" : "=r"(a) : "l"(p));
    return a;
}

#define LDSM4(r, a) \
    asm volatile("ldmatrix.sync.aligned.m8n8.x4.shared.b16 {%0,%1,%2,%3}, [%4];" \
        : "=r"((r)[0]), "=r"((r)[1]), "=r"((r)[2]), "=r"((r)[3]) : "r"(a))

#define MMA_BF16(d, a, b) \
    asm volatile("mma.sync.aligned.m16n8k16.row.col.f32.bf16.bf16.f32 " \
        "{%0,%1,%2,%3}, {%4,%5,%6,%7}, {%8,%9}, {%0,%1,%2,%3};" \
        : "+f"((d)[0]), "+f"((d)[1]), "+f"((d)[2]), "+f"((d)[3]) \
        : "r"((a)[0]), "r"((a)[1]), "r"((a)[2]), "r"((a)[3]), "r"((b)[0]), "r"((b)[1]))

#define CP_ASYNC(dst, src, ok) \
    asm volatile("cp.async.cg.shared.global [%0], [%1], 16, %2;" \
        :: "r"(dst), "l"(src), "r"(ok) : "memory")
#define CP_COMMIT()  asm volatile("cp.async.commit_group;" ::: "memory")
#define CP_WAIT2()   asm volatile("cp.async.wait_group 2;" ::: "memory")

// ---------------------------------------------------------------------------
// small kernels
// ---------------------------------------------------------------------------
__global__ void copy_x_kernel(const float4* __restrict__ x, float4* __restrict__ h, int n4) {
    int i = blockIdx.x * blockDim.x + threadIdx.x;
    if (i < n4) h[i] = x[i];
}

__global__ void edge_agg_kernel(const float* __restrict__ x, const int* __restrict__ ei,
                                float* __restrict__ h, int n_edges) {
    int warp = (blockIdx.x * blockDim.x + threadIdx.x) >> 5;
    int lane = threadIdx.x & 31;
    if (warp >= n_edges) return;
    int src = ei[warp];
    int dst = ei[n_edges + warp];
    const float4 v = *reinterpret_cast<const float4*>(x + (size_t)src * IN_C + lane * 4);
    float* d = h + (size_t)dst * IN_C + lane * 4;
    atomicAdd(d + 0, v.x); atomicAdd(d + 1, v.y);
    atomicAdd(d + 2, v.z); atomicAdd(d + 3, v.w);
}

__global__ void split_kernel(const float* __restrict__ in, bf16* __restrict__ hi,
                             bf16* __restrict__ lo, int n) {
    int i = blockIdx.x * blockDim.x + threadIdx.x;
    if (i >= n) return;
    float v = in[i];
    bf16 h = __float2bfloat16(v);
    hi[i] = h;
    lo[i] = __float2bfloat16(v - __bfloat162float(h));
}

// W[K,N] fp32 -> Wt[N,K] hi/lo bf16
__global__ void wtrans_kernel(const float* __restrict__ W, bf16* __restrict__ hi,
                              bf16* __restrict__ lo, int K, int N) {
    __shared__ float t[32][33];
    int n0 = blockIdx.x * 32, k0 = blockIdx.y * 32;
#pragma unroll
    for (int dy = 0; dy < 32; dy += 8) {
        int k = k0 + threadIdx.y + dy, n = n0 + threadIdx.x;
        t[threadIdx.y + dy][threadIdx.x] = (k < K && n < N) ? W[(size_t)k * N + n] : 0.f;
    }
    __syncthreads();
#pragma unroll
    for (int dy = 0; dy < 32; dy += 8) {
        int n = n0 + threadIdx.y + dy, k = k0 + threadIdx.x;
        if (n < N && k < K) {
            float v = t[threadIdx.x][threadIdx.y + dy];
            bf16 h = __float2bfloat16(v);
            hi[(size_t)n * K + k] = h;
            lo[(size_t)n * K + k] = __float2bfloat16(v - __bfloat162float(h));
        }
    }
}

// b1[n] = l2_b[n] + sum_k l1_b[k] * l2_w[k,n]
__global__ void bias_fold_kernel(const float* __restrict__ l1b,
                                 const float* __restrict__ l2w,
                                 const float* __restrict__ l2b,
                                 float* __restrict__ outb) {
    int n = blockIdx.x * blockDim.x + threadIdx.x;
    if (n >= D_FC) return;
    float s = l2b[n];
    for (int k = 0; k < D_L1; k++)
        s += l1b[k] * l2w[(size_t)k * D_FC + n];
    outb[n] = s;
}

// b_all[j] = out_b[j] + sum_n b1[n] * out_w[n,j]
__global__ void bias_fold2_kernel(const float* __restrict__ b1,
                                  const float* __restrict__ ow,
                                  const float* __restrict__ outb,
                                  float* __restrict__ ball) {
    int j = threadIdx.x;
    if (j >= OUT_C) return;
    float s = outb[j];
    for (int n = 0; n < D_FC; n++)
        s += b1[n] * ow[(size_t)n * OUT_C + j];
    ball[j] = s;
}

// ---------------------------------------------------------------------------
// bf16x3 mma.sync GEMM: C[M,N] = A[M,K] @ Bt[N,K]^T
// BM=256, BN=128, BK=32, 256 threads (warp grid 4Mx2N, warp tile 64x64), 4 stages
// ---------------------------------------------------------------------------
#define STAGES    4
#define A_BYTES   16384             // 256 rows * 64 B
#define B_BYTES   8192              // 128 rows * 64 B
#define STAGE_B   (2 * A_BYTES + 2 * B_BYTES)   // Ah, Al, Bh, Bl = 49152
#define OFF_AL    16384
#define OFF_BH    32768
#define OFF_BL    40960
#define SMEM_DYN  (STAGES * STAGE_B)            // 196608

__global__ __launch_bounds__(256, 1)
void gemm_mma_kernel(const bf16* __restrict__ Ah_g, const bf16* __restrict__ Al_g,
                     const bf16* __restrict__ Bh_g, const bf16* __restrict__ Bl_g,
                     bf16* __restrict__ Ch, bf16* __restrict__ Cl,
                     float* __restrict__ Cf,
                     const float* __restrict__ bias,
                     const float* __restrict__ gamma, const float* __restrict__ beta,
                     const float* __restrict__ mean,  const float* __restrict__ var,
                     int M, int N, int K, int ldc, int epi)
{
    extern __shared__ __align__(128) char smem[];
    const uint32_t sb = smem_u32(smem);
    const int tid = threadIdx.x;
    const int lid = tid & 31, wid = tid >> 5;
    const int warpM = wid >> 1, warpN = wid & 1;
    const int m0 = blockIdx.y * 256, n0 = blockIdx.x * 128;
    const int NC = K >> 5;

    float acc[4][8][4];
#pragma unroll
    for (int i = 0; i < 4; i++)
#pragma unroll
        for (int j = 0; j < 8; j++)
#pragma unroll
            for (int q = 0; q < 4; q++) acc[i][j][q] = 0.0f;

    // ---- stage loader: 3072 16B-chunks / 256 threads = 12 per thread ----
    auto issue_stage = [&](int c, int s) {
        const int k0 = c << 5;
        const uint32_t stb = sb + s * STAGE_B;
#pragma unroll
        for (int q = 0; q < 12; q++) {
            int id = q * 256 + tid;
            const bf16* base;
            uint32_t toff;
            int row, ch, gr, rmax;
            if (id < 2048) {                  // A: hi then lo, 256 rows x 4 chunks
                int half = id >> 10;
                int idx = id & 1023;
                row = idx >> 2; ch = idx & 3;
                base = half ? Al_g : Ah_g;
                toff = half ? OFF_AL : 0u;
                gr = m0 + row; rmax = M;
            } else {                          // B: hi then lo, 128 rows x 4 chunks
                int idB = id - 2048;
                int half = idB >> 9;
                int idx = idB & 511;
                row = idx >> 2; ch = idx & 3;
                base = half ? Bl_g : Bh_g;
                toff = half ? (uint32_t)OFF_BL : (uint32_t)OFF_BH;
                gr = n0 + row; rmax = N;
            }
            unsigned ok = (gr < rmax) ? 16u : 0u;
            int rc = (gr < rmax) ? gr : 0;
            const char* src = (const char*)(base + (size_t)rc * K + k0) + ch * 16;
            uint32_t dst = stb + toff + row * 64 + ((ch ^ ((row >> 1) & 3)) << 4);
            CP_ASYNC(dst, src, ok);
        }
        CP_COMMIT();
    };

    issue_stage(0, 0);
    issue_stage(1, 1);
    issue_stage(2, 2);

    const int grp = lid >> 3, lr = lid & 7;

    int s = 0;
    for (int c = 0; c < NC; c++) {
        CP_WAIT2();
        __syncthreads();
        if (c + 3 < NC) issue_stage(c + 3, (s + 3) & 3);
        else CP_COMMIT();

        const uint32_t stb = sb + s * STAGE_B;
#pragma unroll
        for (int ks = 0; ks < 2; ks++) {
            uint32_t ah[4][4];
#pragma unroll
            for (int i = 0; i < 4; i++) {
                int row = warpM * 64 + i * 16 + lr + ((grp & 1) << 3);
                int chk = 2 * ks + (grp >> 1);
                uint32_t ad = stb + row * 64 + ((chk ^ ((row >> 1) & 3)) << 4);
                LDSM4(ah[i], ad);
            }
            uint32_t bh[8][2];
#pragma unroll
            for (int jj = 0; jj < 4; jj++) {
                int row = warpN * 64 + jj * 16 + lr + ((grp >= 2) ? 8 : 0);
                int chk = 2 * ks + (grp & 1);
                uint32_t bd = stb + OFF_BH + row * 64 + ((chk ^ ((row >> 1) & 3)) << 4);
                uint32_t r[4];
                LDSM4(r, bd);
                bh[2 * jj][0] = r[0]; bh[2 * jj][1] = r[1];
                bh[2 * jj + 1][0] = r[2]; bh[2 * jj + 1][1] = r[3];
            }
#pragma unroll
            for (int i = 0; i < 4; i++)
#pragma unroll
                for (int j = 0; j < 8; j++)
                    MMA_BF16(acc[i][j], ah[i], bh[j]);
            uint32_t al[4][4];
#pragma unroll
            for (int i = 0; i < 4; i++) {
                int row = warpM * 64 + i * 16 + lr + ((grp & 1) << 3);
                int chk = 2 * ks + (grp >> 1);
                uint32_t ad = stb + OFF_AL + row * 64 + ((chk ^ ((row >> 1) & 3)) << 4);
                LDSM4(al[i], ad);
            }
            uint32_t bl[8][2];
#pragma unroll
            for (int jj = 0; jj < 4; jj++) {
                int row = warpN * 64 + jj * 16 + lr + ((grp >= 2) ? 8 : 0);
                int chk = 2 * ks + (grp & 1);
                uint32_t bd = stb + OFF_BL + row * 64 + ((chk ^ ((row >> 1) & 3)) << 4);
                uint32_t r[4];
                LDSM4(r, bd);
                bl[2 * jj][0] = r[0]; bl[2 * jj][1] = r[1];
                bl[2 * jj + 1][0] = r[2]; bl[2 * jj + 1][1] = r[3];
            }
#pragma unroll
            for (int i = 0; i < 4; i++)
#pragma unroll
                for (int j = 0; j < 8; j++) {
                    MMA_BF16(acc[i][j], ah[i], bl[j]);
                    MMA_BF16(acc[i][j], al[i], bh[j]);
                }
        }
        s = (s + 1) & 3;
    }

    // ---- epilogue ----
    const int r_base = m0 + warpM * 64 + (lid >> 2);
    const int c_base = n0 + warpN * 64 + (lid & 3) * 2;
#pragma unroll
    for (int i = 0; i < 4; i++) {
#pragma unroll
        for (int half = 0; half < 2; half++) {
            int row = r_base + i * 16 + half * 8;
            if (row >= M) continue;
#pragma unroll
            for (int j = 0; j < 8; j++) {
                int col = c_base + j * 8;
                if (col >= N) continue;
                float v0 = acc[i][j][half * 2 + 0] + bias[col];
                float v1 = acc[i][j][half * 2 + 1] + bias[col + 1];
                if (epi == EPI_BNRELU) {
                    v0 = (v0 - mean[col])     * rsqrtf(var[col] + BN_EPS)     * gamma[col]     + beta[col];
                    v1 = (v1 - mean[col + 1]) * rsqrtf(var[col + 1] + BN_EPS) * gamma[col + 1] + beta[col + 1];
                    v0 = fmaxf(v0, 0.0f); v1 = fmaxf(v1, 0.0f);
                } else if (epi == EPI_RELU) {
                    v0 = fmaxf(v0, 0.0f); v1 = fmaxf(v1, 0.0f);
                } else if (epi == EPI_LEAKY) {
                    v0 = (v0 > 0.0f) ? v0 : 0.01f * v0;
                    v1 = (v1 > 0.0f) ? v1 : 0.01f * v1;
                }
                if (epi == EPI_SIGMOID) {
                    float2 o;
                    o.x = 1.0f / (1.0f + expf(-v0));
                    o.y = 1.0f / (1.0f + expf(-v1));
                    *(float2*)(Cf + (size_t)row * ldc + col) = o;
                } else {
                    bf16 h0 = __float2bfloat16(v0);
                    bf16 h1 = __float2bfloat16(v1);
                    *(__nv_bfloat162*)(Ch + (size_t)row * ldc + col) = __nv_bfloat162(h0, h1);
                    *(__nv_bfloat162*)(Cl + (size_t)row * ldc + col) = __nv_bfloat162(
                        __float2bfloat16(v0 - __bfloat162float(h0)),
                        __float2bfloat16(v1 - __bfloat162float(h1)));
                }
            }
        }
    }
}

// ---------------------------------------------------------------------------
// launch
// ---------------------------------------------------------------------------
static void launch_gemm(const bf16* Ah, const bf16* Al, const bf16* Bh, const bf16* Bl,
                        bf16* Ch, bf16* Cl, float* Cf, const float* bias,
                        const float* ga, const float* be, const float* me, const float* va,
                        int M, int N, int K, int ldc, int epi) {
    dim3 grid((N + 127) / 128, (M + 255) / 256);
    gemm_mma_kernel<<<grid, 256, SMEM_DYN>>>(Ah, Al, Bh, Bl, Ch, Cl, Cf, bias,
                                             ga, be, me, va, M, N, K, ldc, epi);
}

template <typename T> static T* sym(T* symbol) {
    void* p = nullptr;
    cudaGetSymbolAddress(&p, (const void*)symbol);
    return (T*)p;
}

extern "C" void kernel_launch(void* const* d_in, const int* in_sizes, int n_in,
                              void* d_out, int out_size) {
    const float* x  = (const float*)d_in[0];
    const int*   ei = (const int*)d_in[1];
    const float *w1a = (const float*)d_in[2],  *b1a = (const float*)d_in[3];
    const float *ga  = (const float*)d_in[4],  *bea = (const float*)d_in[5];
    const float *ma  = (const float*)d_in[6],  *va  = (const float*)d_in[7];
    const float *w2a = (const float*)d_in[8],  *b2a = (const float*)d_in[9];
    const float *w1b = (const float*)d_in[10], *b1b = (const float*)d_in[11];
    const float *gb  = (const float*)d_in[12], *beb = (const float*)d_in[13];
    const float *mb  = (const float*)d_in[14], *vb  = (const float*)d_in[15];
    const float *w2b = (const float*)d_in[16], *b2b = (const float*)d_in[17];
    const float *fcw = (const float*)d_in[18], *fcb = (const float*)d_in[19];
    const float *l1w = (const float*)d_in[20], *l1b = (const float*)d_in[21];
    const float *l2w = (const float*)d_in[22], *l2b = (const float*)d_in[23];
    const float *ow  = (const float*)d_in[24], *ob  = (const float*)d_in[25];
    float* out = (float*)d_out;

    cudaFuncSetAttribute(gemm_mma_kernel,
                         cudaFuncAttributeMaxDynamicSharedMemorySize, SMEM_DYN);

    float* h = sym(g_h);
    bf16 *hhi = sym(g_h_hi), *hlo = sym(g_h_lo);
    bf16 *thi = sym(g_t_hi), *tlo = sym(g_t_lo);
    bf16 *chi = sym(g_c_hi), *clo = sym(g_c_lo);
    bf16 *fhi = sym(g_fc_hi), *flo = sym(g_fc_lo);
    bf16 *w1ah = sym(g_w1a_hi), *w1al = sym(g_w1a_lo);
    bf16 *w2ah = sym(g_w2a_hi), *w2al = sym(g_w2a_lo);
    bf16 *w1bh = sym(g_w1b_hi), *w1bl = sym(g_w1b_lo);
    bf16 *w2bh = sym(g_w2b_hi), *w2bl = sym(g_w2b_lo);
    bf16 *wfh = sym(g_wfc_hi), *wfl = sym(g_wfc_lo);
    bf16 *wl1h = sym(g_wl1_hi), *wl1l = sym(g_wl1_lo);
    bf16 *wl2h = sym(g_wl2_hi), *wl2l = sym(g_wl2_lo);
    bf16 *woh = sym(g_wo_hi), *wol = sym(g_wo_lo);
    bf16 *w2ch = sym(g_w2c_hi), *w2cl = sym(g_w2c_lo);
    bf16 *wallh = sym(g_wall_hi), *walll = sym(g_wall_lo);
    float *bias1 = sym(g_bias1), *ball = sym(g_ball), *zerob = sym(g_zerobias);

    const int n_edges = in_sizes[1] / 2;

    // aggregation (fp32) + split
    {
        int n4 = NN * IN_C / 4;
        copy_x_kernel<<<(n4 + 255) / 256, 256>>>((const float4*)x, (float4*)h, n4);
        long long nthreads = (long long)n_edges * 32;
        edge_agg_kernel<<<(int)((nthreads + 255) / 256), 256>>>(x, ei, h, n_edges);
        int n = NN * IN_C;
        split_kernel<<<(n + 255) / 256, 256>>>(h, hhi, hlo, n);
    }
    // weight transpose + split
    {
        dim3 b(32, 8);
        wtrans_kernel<<<dim3(HID / 32,  IN_C / 32), b>>>(w1a, w1ah, w1al, IN_C, HID);
        wtrans_kernel<<<dim3(HID / 32,  HID / 32), b>>>(w2a, w2ah, w2al, HID, HID);
        wtrans_kernel<<<dim3(HID / 32,  IN_C / 32), b>>>(w1b, w1bh, w1bl, IN_C, HID);
        wtrans_kernel<<<dim3(HID / 32,  HID / 32), b>>>(w2b, w2bh, w2bl, HID, HID);
        wtrans_kernel<<<dim3(D_FC / 32, D_CAT / 32), b>>>(fcw, wfh, wfl, D_CAT, D_FC);
        wtrans_kernel<<<dim3(OUT_C / 32, D_FC / 32), b>>>(ow, woh, wol, D_FC, OUT_C);
        // plain splits for the fold operands
        int n1 = D_FC * D_L1;
        split_kernel<<<(n1 + 255) / 256, 256>>>(l1w, wl1h, wl1l, n1);   // l1_w [2048,4096]
        split_kernel<<<(n1 + 255) / 256, 256>>>(l2w, wl2h, wl2l, n1);   // l2_w [4096,2048]
        // folded biases
        bias_fold_kernel<<<D_FC / 256, 256>>>(l1b, l2w, l2b, bias1);
        bias_fold2_kernel<<<1, OUT_C>>>(bias1, ow, ob, ball);
    }

    // Fold step 1: T2 = (l2_w @ out_w)^T [64,4096]
    //   A = out_w^T [64,2048], Bt = l2_w plain [4096,2048]
    launch_gemm(woh, wol, wl2h, wl2l, w2ch, w2cl, 0, zerob, 0, 0, 0, 0,
                OUT_C, D_L1, D_FC, D_L1, EPI_NONE);
    // Fold step 2: W_all^T = T2 @ l1_w^T [64,2048]
    //   A = T2 [64,4096], Bt = l1_w plain [2048,4096]
    launch_gemm(w2ch, w2cl, wl1h, wl1l, wallh, walll, 0, zerob, 0, 0, 0, 0,
                OUT_C, D_FC, D_L1, D_FC, EPI_NONE);

    // conv A
    launch_gemm(hhi, hlo, w1ah, w1al, thi, tlo, 0, b1a, ga, bea, ma, va,
                NN, HID, IN_C, HID, EPI_BNRELU);
    launch_gemm(thi, tlo, w2ah, w2al, chi, clo, 0, b2a, 0, 0, 0, 0,
                NN, HID, HID, D_CAT, EPI_RELU);
    // conv B
    launch_gemm(hhi, hlo, w1bh, w1bl, thi, tlo, 0, b1b, gb, beb, mb, vb,
                NN, HID, IN_C, HID, EPI_BNRELU);
    launch_gemm(thi, tlo, w2bh, w2bl, chi + HID, clo + HID, 0, b2b, 0, 0, 0, 0,
                NN, HID, HID, D_CAT, EPI_RELU);
    // head
    launch_gemm(chi, clo, wfh, wfl, fhi, flo, 0, fcb, 0, 0, 0, 0,
                NN, D_FC, D_CAT, D_FC, EPI_LEAKY);
    // entire folded tail: fc_out @ W_all + b_all, sigmoid
    launch_gemm(fhi, flo, wallh, walll, 0, 0, out, ball, 0, 0, 0, 0,
                NN, OUT_C, D_FC, OUT_C, EPI_SIGMOID);
}

// round 9
// speedup vs baseline: 4.5349x; 1.0835x over previous
#include <cuda_runtime.h>
#include <cuda_bf16.h>
#include <math.h>
#include <stdint.h>

#define NN      60000
#define IN_C    128
#define HID     512
#define D_CAT   1024
#define D_FC    2048
#define D_L1    4096
#define OUT_C   64
#define BN_EPS  1e-5f

#define EPI_NONE    0
#define EPI_RELU    1
#define EPI_BNRELU  2
#define EPI_LEAKY   3
#define EPI_SIGMOID 4

typedef __nv_bfloat16 bf16;

// ---------------------------------------------------------------------------
// Scratch (__device__ globals; no allocations allowed)
// ---------------------------------------------------------------------------
__device__ float g_h[(size_t)NN * IN_C];              // x + agg (fp32, atomics)
__device__ bf16  g_h_hi [(size_t)NN * IN_C ],  g_h_lo [(size_t)NN * IN_C ];
__device__ bf16  g_t_hi [(size_t)NN * D_CAT],  g_t_lo [(size_t)NN * D_CAT];   // merged mm1 out [ta|tb]
__device__ bf16  g_c_hi [(size_t)NN * D_CAT],  g_c_lo [(size_t)NN * D_CAT];
__device__ bf16  g_fc_hi[(size_t)NN * D_FC ],  g_fc_lo[(size_t)NN * D_FC ];
// transposed weights [N,K] hi/lo
__device__ bf16 g_w1ab_hi[D_CAT * IN_C], g_w1ab_lo[D_CAT * IN_C];  // stacked w1a^T | w1b^T
__device__ bf16 g_w2a_hi[HID * HID],    g_w2a_lo[HID * HID];
__device__ bf16 g_w2b_hi[HID * HID],    g_w2b_lo[HID * HID];
__device__ bf16 g_wfc_hi[D_FC * D_CAT], g_wfc_lo[D_FC * D_CAT];
__device__ bf16 g_wl1_hi[(size_t)D_FC * D_L1], g_wl1_lo[(size_t)D_FC * D_L1]; // plain split of l1_w
__device__ bf16 g_wl2_hi[(size_t)D_L1 * D_FC], g_wl2_lo[(size_t)D_L1 * D_FC]; // plain split of l2_w
__device__ bf16 g_wo_hi [OUT_C * D_FC], g_wo_lo [OUT_C * D_FC];               // out_w^T
// fold intermediates / results
__device__ bf16  g_w2c_hi [OUT_C * D_L1],  g_w2c_lo [OUT_C * D_L1];   // (l2@out)^T [64,4096]
__device__ bf16  g_wall_hi[OUT_C * D_FC],  g_wall_lo[OUT_C * D_FC];   // W_all^T   [64,2048]
__device__ float g_bias1[D_FC];
__device__ float g_ball [OUT_C];
__device__ float g_zerobias[D_L1];   // stays zero
// concatenated BN params for merged mm1
__device__ float g_bnb[D_CAT], g_bng[D_CAT], g_bnbt[D_CAT], g_bnm[D_CAT], g_bnv[D_CAT];

// ---------------------------------------------------------------------------
// helpers
// ---------------------------------------------------------------------------
__device__ __forceinline__ uint32_t smem_u32(const void* p) {
    uint32_t a;
    asm("{ .reg .u64 t; cvta.to.shared.u64 t, %1; cvt.u32.u64 %0, t; }" : "=r"(a) : "l"(p));
    return a;
}

#define LDSM4(r, a) \
    asm volatile("ldmatrix.sync.aligned.m8n8.x4.shared.b16 {%0,%1,%2,%3}, [%4];" \
        : "=r"((r)[0]), "=r"((r)[1]), "=r"((r)[2]), "=r"((r)[3]) : "r"(a))

#define MMA_BF16(d, a, b) \
    asm volatile("mma.sync.aligned.m16n8k16.row.col.f32.bf16.bf16.f32 " \
        "{%0,%1,%2,%3}, {%4,%5,%6,%7}, {%8,%9}, {%0,%1,%2,%3};" \
        : "+f"((d)[0]), "+f"((d)[1]), "+f"((d)[2]), "+f"((d)[3]) \
        : "r"((a)[0]), "r"((a)[1]), "r"((a)[2]), "r"((a)[3]), "r"((b)[0]), "r"((b)[1]))

#define CP_ASYNC(dst, src, ok) \
    asm volatile("cp.async.cg.shared.global [%0], [%1], 16, %2;" \
        :: "r"(dst), "l"(src), "r"(ok) : "memory")
#define CP_COMMIT()  asm volatile("cp.async.commit_group;" ::: "memory")
#define CP_WAIT2()   asm volatile("cp.async.wait_group 2;" ::: "memory")

// ---------------------------------------------------------------------------
// small kernels
// ---------------------------------------------------------------------------
__global__ void copy_x_kernel(const float4* __restrict__ x, float4* __restrict__ h, int n4) {
    int i = blockIdx.x * blockDim.x + threadIdx.x;
    if (i < n4) h[i] = x[i];
}

__global__ void edge_agg_kernel(const float* __restrict__ x, const int* __restrict__ ei,
                                float* __restrict__ h, int n_edges) {
    int warp = (blockIdx.x * blockDim.x + threadIdx.x) >> 5;
    int lane = threadIdx.x & 31;
    if (warp >= n_edges) return;
    int src = ei[warp];
    int dst = ei[n_edges + warp];
    const float4 v = *reinterpret_cast<const float4*>(x + (size_t)src * IN_C + lane * 4);
    float* d = h + (size_t)dst * IN_C + lane * 4;
    asm volatile("red.global.add.v4.f32 [%0], {%1, %2, %3, %4};"
                 :: "l"(d), "f"(v.x), "f"(v.y), "f"(v.z), "f"(v.w) : "memory");
}

__global__ void split_kernel(const float* __restrict__ in, bf16* __restrict__ hi,
                             bf16* __restrict__ lo, int n) {
    int i = blockIdx.x * blockDim.x + threadIdx.x;
    if (i >= n) return;
    float v = in[i];
    bf16 h = __float2bfloat16(v);
    hi[i] = h;
    lo[i] = __float2bfloat16(v - __bfloat162float(h));
}

// W[K,N] fp32 -> Wt[N,K] hi/lo bf16
__global__ void wtrans_kernel(const float* __restrict__ W, bf16* __restrict__ hi,
                              bf16* __restrict__ lo, int K, int N) {
    __shared__ float t[32][33];
    int n0 = blockIdx.x * 32, k0 = blockIdx.y * 32;
#pragma unroll
    for (int dy = 0; dy < 32; dy += 8) {
        int k = k0 + threadIdx.y + dy, n = n0 + threadIdx.x;
        t[threadIdx.y + dy][threadIdx.x] = (k < K && n < N) ? W[(size_t)k * N + n] : 0.f;
    }
    __syncthreads();
#pragma unroll
    for (int dy = 0; dy < 32; dy += 8) {
        int n = n0 + threadIdx.y + dy, k = k0 + threadIdx.x;
        if (n < N && k < K) {
            float v = t[threadIdx.x][threadIdx.y + dy];
            bf16 h = __float2bfloat16(v);
            hi[(size_t)n * K + k] = h;
            lo[(size_t)n * K + k] = __float2bfloat16(v - __bfloat162float(h));
        }
    }
}

// concat the 5 BN/bias param pairs (a: cols 0..511, b: cols 512..1023)
__global__ void concat_bn_kernel(const float* b1a, const float* b1b,
                                 const float* ga,  const float* gb,
                                 const float* bea, const float* beb,
                                 const float* ma,  const float* mb,
                                 const float* va,  const float* vb) {
    int i = threadIdx.x + blockIdx.x * blockDim.x;
    if (i >= HID) return;
    g_bnb [i] = b1a[i];  g_bnb [HID + i] = b1b[i];
    g_bng [i] = ga[i];   g_bng [HID + i] = gb[i];
    g_bnbt[i] = bea[i];  g_bnbt[HID + i] = beb[i];
    g_bnm [i] = ma[i];   g_bnm [HID + i] = mb[i];
    g_bnv [i] = va[i];   g_bnv [HID + i] = vb[i];
}

// b1[n] = l2_b[n] + sum_k l1_b[k] * l2_w[k,n]
__global__ void bias_fold_kernel(const float* __restrict__ l1b,
                                 const float* __restrict__ l2w,
                                 const float* __restrict__ l2b,
                                 float* __restrict__ outb) {
    int n = blockIdx.x * blockDim.x + threadIdx.x;
    if (n >= D_FC) return;
    float s = l2b[n];
    for (int k = 0; k < D_L1; k++)
        s += l1b[k] * l2w[(size_t)k * D_FC + n];
    outb[n] = s;
}

// b_all[j] = out_b[j] + sum_n b1[n] * out_w[n,j]
__global__ void bias_fold2_kernel(const float* __restrict__ b1,
                                  const float* __restrict__ ow,
                                  const float* __restrict__ outb,
                                  float* __restrict__ ball) {
    int j = threadIdx.x;
    if (j >= OUT_C) return;
    float s = outb[j];
    for (int n = 0; n < D_FC; n++)
        s += b1[n] * ow[(size_t)n * OUT_C + j];
    ball[j] = s;
}

// ---------------------------------------------------------------------------
// bf16x3 mma.sync GEMM: C[M,N] = A[M,K](lda) @ Bt[N,K]^T
// BM=256, BN_T in {128,64}, BK=32, 256 threads, warp grid 4Mx2N, 4 stages
// ---------------------------------------------------------------------------
#define STAGES 4

template <int BN_T>
__global__ __launch_bounds__(256, 1)
void gemm_mma_kernel(const bf16* __restrict__ Ah_g, const bf16* __restrict__ Al_g,
                     const bf16* __restrict__ Bh_g, const bf16* __restrict__ Bl_g,
                     bf16* __restrict__ Ch, bf16* __restrict__ Cl,
                     float* __restrict__ Cf,
                     const float* __restrict__ bias,
                     const float* __restrict__ gamma, const float* __restrict__ beta,
                     const float* __restrict__ mean,  const float* __restrict__ var,
                     int M, int N, int K, int lda, int ldc, int epi)
{
    constexpr int B_BY   = BN_T * 64;             // B tile bytes per half
    constexpr int OFF_AL = 16384;
    constexpr int OFF_BH = 32768;
    constexpr int OFF_BL = 32768 + B_BY;
    constexpr int STG_B  = 32768 + 2 * B_BY;      // stage bytes
    constexpr int NJ     = BN_T / 16;             // j-frags per warp
    constexpr int NJJ    = BN_T / 32;             // ldsm x4 loads per half
    constexpr int PER    = (2048 + 8 * BN_T) / 256;   // cp.async per thread

    extern __shared__ __align__(128) char smem[];
    const uint32_t sb = smem_u32(smem);
    const int tid = threadIdx.x;
    const int lid = tid & 31, wid = tid >> 5;
    const int warpM = wid >> 1, warpN = wid & 1;
    const int m0 = blockIdx.y * 256, n0 = blockIdx.x * BN_T;
    const int NC = K >> 5;

    float acc[4][NJ][4];
#pragma unroll
    for (int i = 0; i < 4; i++)
#pragma unroll
        for (int j = 0; j < NJ; j++)
#pragma unroll
            for (int q = 0; q < 4; q++) acc[i][j][q] = 0.0f;

    auto issue_stage = [&](int c, int s) {
        const int k0 = c << 5;
        const uint32_t stb = sb + s * STG_B;
#pragma unroll
        for (int q = 0; q < PER; q++) {
            int id = q * 256 + tid;
            const bf16* base;
            uint32_t toff;
            int row, ch, gr, rmax, ld;
            if (id < 2048) {                  // A: hi then lo, 256 rows x 4 chunks
                int half = id >> 10;
                int idx = id & 1023;
                row = idx >> 2; ch = idx & 3;
                base = half ? Al_g : Ah_g;
                toff = half ? OFF_AL : 0u;
                gr = m0 + row; rmax = M; ld = lda;
            } else {                          // B: hi then lo, BN_T rows x 4 chunks
                int idB = id - 2048;
                int half = idB / (BN_T * 4);
                int idx = idB % (BN_T * 4);
                row = idx >> 2; ch = idx & 3;
                base = half ? Bl_g : Bh_g;
                toff = half ? (uint32_t)OFF_BL : (uint32_t)OFF_BH;
                gr = n0 + row; rmax = N; ld = K;
            }
            unsigned ok = (gr < rmax) ? 16u : 0u;
            int rc = (gr < rmax) ? gr : 0;
            const char* src = (const char*)(base + (size_t)rc * ld + k0) + ch * 16;
            uint32_t dst = stb + toff + row * 64 + ((ch ^ ((row >> 1) & 3)) << 4);
            CP_ASYNC(dst, src, ok);
        }
        CP_COMMIT();
    };

    issue_stage(0, 0);
    issue_stage(1, 1);
    issue_stage(2, 2);

    const int grp = lid >> 3, lr = lid & 7;

    int s = 0;
    for (int c = 0; c < NC; c++) {
        CP_WAIT2();
        __syncthreads();
        if (c + 3 < NC) issue_stage(c + 3, (s + 3) & 3);
        else CP_COMMIT();

        const uint32_t stb = sb + s * STG_B;
#pragma unroll
        for (int ks = 0; ks < 2; ks++) {
            uint32_t ah[4][4];
#pragma unroll
            for (int i = 0; i < 4; i++) {
                int row = warpM * 64 + i * 16 + lr + ((grp & 1) << 3);
                int chk = 2 * ks + (grp >> 1);
                uint32_t ad = stb + row * 64 + ((chk ^ ((row >> 1) & 3)) << 4);
                LDSM4(ah[i], ad);
            }
            uint32_t bh[NJ][2];
#pragma unroll
            for (int jj = 0; jj < NJJ; jj++) {
                int row = warpN * (BN_T / 2) + jj * 16 + lr + ((grp >= 2) ? 8 : 0);
                int chk = 2 * ks + (grp & 1);
                uint32_t bd = stb + OFF_BH + row * 64 + ((chk ^ ((row >> 1) & 3)) << 4);
                uint32_t r[4];
                LDSM4(r, bd);
                bh[2 * jj][0] = r[0]; bh[2 * jj][1] = r[1];
                bh[2 * jj + 1][0] = r[2]; bh[2 * jj + 1][1] = r[3];
            }
#pragma unroll
            for (int i = 0; i < 4; i++)
#pragma unroll
                for (int j = 0; j < NJ; j++)
                    MMA_BF16(acc[i][j], ah[i], bh[j]);
            uint32_t al[4][4];
#pragma unroll
            for (int i = 0; i < 4; i++) {
                int row = warpM * 64 + i * 16 + lr + ((grp & 1) << 3);
                int chk = 2 * ks + (grp >> 1);
                uint32_t ad = stb + OFF_AL + row * 64 + ((chk ^ ((row >> 1) & 3)) << 4);
                LDSM4(al[i], ad);
            }
            uint32_t bl[NJ][2];
#pragma unroll
            for (int jj = 0; jj < NJJ; jj++) {
                int row = warpN * (BN_T / 2) + jj * 16 + lr + ((grp >= 2) ? 8 : 0);
                int chk = 2 * ks + (grp & 1);
                uint32_t bd = stb + OFF_BL + row * 64 + ((chk ^ ((row >> 1) & 3)) << 4);
                uint32_t r[4];
                LDSM4(r, bd);
                bl[2 * jj][0] = r[0]; bl[2 * jj][1] = r[1];
                bl[2 * jj + 1][0] = r[2]; bl[2 * jj + 1][1] = r[3];
            }
#pragma unroll
            for (int i = 0; i < 4; i++)
#pragma unroll
                for (int j = 0; j < NJ; j++) {
                    MMA_BF16(acc[i][j], ah[i], bl[j]);
                    MMA_BF16(acc[i][j], al[i], bh[j]);
                }
        }
        s = (s + 1) & 3;
    }

    // ---- epilogue ----
    const int r_base = m0 + warpM * 64 + (lid >> 2);
    const int c_base = n0 + warpN * (BN_T / 2) + (lid & 3) * 2;
#pragma unroll
    for (int i = 0; i < 4; i++) {
#pragma unroll
        for (int half = 0; half < 2; half++) {
            int row = r_base + i * 16 + half * 8;
            if (row >= M) continue;
#pragma unroll
            for (int j = 0; j < NJ; j++) {
                int col = c_base + j * 8;
                if (col >= N) continue;
                float v0 = acc[i][j][half * 2 + 0] + bias[col];
                float v1 = acc[i][j][half * 2 + 1] + bias[col + 1];
                if (epi == EPI_BNRELU) {
                    v0 = (v0 - mean[col])     * rsqrtf(var[col] + BN_EPS)     * gamma[col]     + beta[col];
                    v1 = (v1 - mean[col + 1]) * rsqrtf(var[col + 1] + BN_EPS) * gamma[col + 1] + beta[col + 1];
                    v0 = fmaxf(v0, 0.0f); v1 = fmaxf(v1, 0.0f);
                } else if (epi == EPI_RELU) {
                    v0 = fmaxf(v0, 0.0f); v1 = fmaxf(v1, 0.0f);
                } else if (epi == EPI_LEAKY) {
                    v0 = (v0 > 0.0f) ? v0 : 0.01f * v0;
                    v1 = (v1 > 0.0f) ? v1 : 0.01f * v1;
                }
                if (epi == EPI_SIGMOID) {
                    float2 o;
                    o.x = 1.0f / (1.0f + expf(-v0));
                    o.y = 1.0f / (1.0f + expf(-v1));
                    *(float2*)(Cf + (size_t)row * ldc + col) = o;
                } else {
                    bf16 h0 = __float2bfloat16(v0);
                    bf16 h1 = __float2bfloat16(v1);
                    *(__nv_bfloat162*)(Ch + (size_t)row * ldc + col) = __nv_bfloat162(h0, h1);
                    *(__nv_bfloat162*)(Cl + (size_t)row * ldc + col) = __nv_bfloat162(
                        __float2bfloat16(v0 - __bfloat162float(h0)),
                        __float2bfloat16(v1 - __bfloat162float(h1)));
                }
            }
        }
    }
}

// ---------------------------------------------------------------------------
// launch helpers
// ---------------------------------------------------------------------------
template <int BN_T>
static void launch_gemm(const bf16* Ah, const bf16* Al, const bf16* Bh, const bf16* Bl,
                        bf16* Ch, bf16* Cl, float* Cf, const float* bias,
                        const float* ga, const float* be, const float* me, const float* va,
                        int M, int N, int K, int lda, int ldc, int epi) {
    dim3 grid((N + BN_T - 1) / BN_T, (M + 255) / 256);
    int smem = STAGES * (32768 + 2 * BN_T * 64);
    gemm_mma_kernel<BN_T><<<grid, 256, smem>>>(Ah, Al, Bh, Bl, Ch, Cl, Cf, bias,
                                               ga, be, me, va, M, N, K, lda, ldc, epi);
}

template <typename T> static T* sym(T* symbol) {
    void* p = nullptr;
    cudaGetSymbolAddress(&p, (const void*)symbol);
    return (T*)p;
}

extern "C" void kernel_launch(void* const* d_in, const int* in_sizes, int n_in,
                              void* d_out, int out_size) {
    const float* x  = (const float*)d_in[0];
    const int*   ei = (const int*)d_in[1];
    const float *w1a = (const float*)d_in[2],  *b1a = (const float*)d_in[3];
    const float *ga  = (const float*)d_in[4],  *bea = (const float*)d_in[5];
    const float *ma  = (const float*)d_in[6],  *va  = (const float*)d_in[7];
    const float *w2a = (const float*)d_in[8],  *b2a = (const float*)d_in[9];
    const float *w1b = (const float*)d_in[10], *b1b = (const float*)d_in[11];
    const float *gb  = (const float*)d_in[12], *beb = (const float*)d_in[13];
    const float *mb  = (const float*)d_in[14], *vb  = (const float*)d_in[15];
    const float *w2b = (const float*)d_in[16], *b2b = (const float*)d_in[17];
    const float *fcw = (const float*)d_in[18], *fcb = (const float*)d_in[19];
    const float *l1w = (const float*)d_in[20], *l1b = (const float*)d_in[21];
    const float *l2w = (const float*)d_in[22], *l2b = (const float*)d_in[23];
    const float *ow  = (const float*)d_in[24], *ob  = (const float*)d_in[25];
    float* out = (float*)d_out;

    cudaFuncSetAttribute(gemm_mma_kernel<128>,
                         cudaFuncAttributeMaxDynamicSharedMemorySize,
                         STAGES * (32768 + 2 * 128 * 64));
    cudaFuncSetAttribute(gemm_mma_kernel<64>,
                         cudaFuncAttributeMaxDynamicSharedMemorySize,
                         STAGES * (32768 + 2 * 64 * 64));

    float* h = sym(g_h);
    bf16 *hhi = sym(g_h_hi), *hlo = sym(g_h_lo);
    bf16 *thi = sym(g_t_hi), *tlo = sym(g_t_lo);
    bf16 *chi = sym(g_c_hi), *clo = sym(g_c_lo);
    bf16 *fhi = sym(g_fc_hi), *flo = sym(g_fc_lo);
    bf16 *w1h = sym(g_w1ab_hi), *w1l = sym(g_w1ab_lo);
    bf16 *w2ah = sym(g_w2a_hi), *w2al = sym(g_w2a_lo);
    bf16 *w2bh = sym(g_w2b_hi), *w2bl = sym(g_w2b_lo);
    bf16 *wfh = sym(g_wfc_hi), *wfl = sym(g_wfc_lo);
    bf16 *wl1h = sym(g_wl1_hi), *wl1l = sym(g_wl1_lo);
    bf16 *wl2h = sym(g_wl2_hi), *wl2l = sym(g_wl2_lo);
    bf16 *woh = sym(g_wo_hi), *wol = sym(g_wo_lo);
    bf16 *w2ch = sym(g_w2c_hi), *w2cl = sym(g_w2c_lo);
    bf16 *wallh = sym(g_wall_hi), *walll = sym(g_wall_lo);
    float *bias1 = sym(g_bias1), *ball = sym(g_ball), *zerob = sym(g_zerobias);
    float *bnb = sym(g_bnb), *bng = sym(g_bng), *bnbt = sym(g_bnbt);
    float *bnm = sym(g_bnm), *bnv = sym(g_bnv);

    const int n_edges = in_sizes[1] / 2;

    // aggregation (fp32) + split
    {
        int n4 = NN * IN_C / 4;
        copy_x_kernel<<<(n4 + 255) / 256, 256>>>((const float4*)x, (float4*)h, n4);
        long long nthreads = (long long)n_edges * 32;
        edge_agg_kernel<<<(int)((nthreads + 255) / 256), 256>>>(x, ei, h, n_edges);
        int n = NN * IN_C;
        split_kernel<<<(n + 255) / 256, 256>>>(h, hhi, hlo, n);
    }
    // weight transpose + split + param concat
    {
        dim3 b(32, 8);
        // stacked w1 = [w1a^T ; w1b^T] : [1024, 128]
        wtrans_kernel<<<dim3(HID / 32,  IN_C / 32), b>>>(w1a, w1h, w1l, IN_C, HID);
        wtrans_kernel<<<dim3(HID / 32,  IN_C / 32), b>>>(w1b, w1h + HID * IN_C,
                                                         w1l + HID * IN_C, IN_C, HID);
        wtrans_kernel<<<dim3(HID / 32,  HID / 32), b>>>(w2a, w2ah, w2al, HID, HID);
        wtrans_kernel<<<dim3(HID / 32,  HID / 32), b>>>(w2b, w2bh, w2bl, HID, HID);
        wtrans_kernel<<<dim3(D_FC / 32, D_CAT / 32), b>>>(fcw, wfh, wfl, D_CAT, D_FC);
        wtrans_kernel<<<dim3(OUT_C / 32, D_FC / 32), b>>>(ow, woh, wol, D_FC, OUT_C);
        int n1 = D_FC * D_L1;
        split_kernel<<<(n1 + 255) / 256, 256>>>(l1w, wl1h, wl1l, n1);
        split_kernel<<<(n1 + 255) / 256, 256>>>(l2w, wl2h, wl2l, n1);
        concat_bn_kernel<<<2, 256>>>(b1a, b1b, ga, gb, bea, beb, ma, mb, va, vb);
        bias_fold_kernel<<<D_FC / 256, 256>>>(l1b, l2w, l2b, bias1);
        bias_fold2_kernel<<<1, OUT_C>>>(bias1, ow, ob, ball);
    }

    // Fold: W_all^T = out_w^T @ l2_w^T @ l1_w^T  (two small GEMMs)
    launch_gemm<128>(woh, wol, wl2h, wl2l, w2ch, w2cl, 0, zerob, 0, 0, 0, 0,
                     OUT_C, D_L1, D_FC, D_FC, D_L1, EPI_NONE);
    launch_gemm<128>(w2ch, w2cl, wl1h, wl1l, wallh, walll, 0, zerob, 0, 0, 0, 0,
                     OUT_C, D_FC, D_L1, D_L1, D_FC, EPI_NONE);

    // merged conv mm1 (A and B): t = BNReLU(h @ [w1a|w1b])   [NN, 1024]
    launch_gemm<128>(hhi, hlo, w1h, w1l, thi, tlo, 0, bnb, bng, bnbt, bnm, bnv,
                     NN, D_CAT, IN_C, IN_C, D_CAT, EPI_BNRELU);
    // conv mm2 A: cat[:, 0:512] = ReLU(t[:, 0:512] @ w2a)
    launch_gemm<128>(thi, tlo, w2ah, w2al, chi, clo, 0, b2a, 0, 0, 0, 0,
                     NN, HID, HID, D_CAT, D_CAT, EPI_RELU);
    // conv mm2 B: cat[:, 512:1024] = ReLU(t[:, 512:1024] @ w2b)
    launch_gemm<128>(thi + HID, tlo + HID, w2bh, w2bl, chi + HID, clo + HID, 0, b2b,
                     0, 0, 0, 0, NN, HID, HID, D_CAT, D_CAT, EPI_RELU);
    // head fc
    launch_gemm<128>(chi, clo, wfh, wfl, fhi, flo, 0, fcb, 0, 0, 0, 0,
                     NN, D_FC, D_CAT, D_CAT, D_FC, EPI_LEAKY);
    // folded tail (N=64 kernel)
    launch_gemm<64>(fhi, flo, wallh, walll, 0, 0, out, ball, 0, 0, 0, 0,
                    NN, OUT_C, D_FC, D_FC, OUT_C, EPI_SIGMOID);
}

// round 10
// speedup vs baseline: 5.0198x; 1.1069x over previous
#include <cuda_runtime.h>
#include <cuda_bf16.h>
#include <math.h>
#include <stdint.h>

#define NN      60000
#define IN_C    128
#define HID     512
#define D_CAT   1024
#define D_FC    2048
#define D_L1    4096
#define OUT_C   64
#define BN_EPS  1e-5f

#define EPI_NONE    0
#define EPI_RELU    1
#define EPI_BNRELU  2
#define EPI_LEAKY   3
#define EPI_SIGMOID 4

typedef __nv_bfloat16 bf16;

// ---------------------------------------------------------------------------
// Scratch (__device__ globals; no allocations allowed)
// ---------------------------------------------------------------------------
__device__ float g_h[(size_t)NN * IN_C];
__device__ bf16  g_h_hi [(size_t)NN * IN_C ],  g_h_lo [(size_t)NN * IN_C ];
__device__ bf16  g_t_hi [(size_t)NN * D_CAT],  g_t_lo [(size_t)NN * D_CAT];
__device__ bf16  g_c_hi [(size_t)NN * D_CAT],  g_c_lo [(size_t)NN * D_CAT];
__device__ bf16  g_fc_hi[(size_t)NN * D_FC ],  g_fc_lo[(size_t)NN * D_FC ];
// transposed weights [N,K] hi/lo
__device__ bf16 g_w1ab_hi[D_CAT * IN_C], g_w1ab_lo[D_CAT * IN_C];
__device__ bf16 g_w2a_hi[HID * HID],    g_w2a_lo[HID * HID];
__device__ bf16 g_w2b_hi[HID * HID],    g_w2b_lo[HID * HID];
__device__ bf16 g_wfc_hi[D_FC * D_CAT], g_wfc_lo[D_FC * D_CAT];
__device__ bf16 g_wl1_hi[(size_t)D_FC * D_L1], g_wl1_lo[(size_t)D_FC * D_L1];
__device__ bf16 g_wl2_hi[(size_t)D_L1 * D_FC], g_wl2_lo[(size_t)D_L1 * D_FC];
__device__ bf16 g_wo_hi [OUT_C * D_FC], g_wo_lo [OUT_C * D_FC];
// fold intermediates / results
__device__ bf16  g_w2c_hi [OUT_C * D_L1],  g_w2c_lo [OUT_C * D_L1];
__device__ bf16  g_wall_hi[OUT_C * D_FC],  g_wall_lo[OUT_C * D_FC];
__device__ float g_bias1[D_FC];
__device__ float g_ball [OUT_C];
__device__ float g_zerobias[D_L1];
// concatenated BN params
__device__ float g_bnb[D_CAT], g_bng[D_CAT], g_bnbt[D_CAT], g_bnm[D_CAT], g_bnv[D_CAT];

// ---------------------------------------------------------------------------
// helpers
// ---------------------------------------------------------------------------
__device__ __forceinline__ uint32_t smem_u32(const void* p) {
    uint32_t a;
    asm("{ .reg .u64 t; cvta.to.shared.u64 t, %1; cvt.u32.u64 %0, t; }" : "=r"(a) : "l"(p));
    return a;
}

#define LDSM4(r, a) \
    asm volatile("ldmatrix.sync.aligned.m8n8.x4.shared.b16 {%0,%1,%2,%3}, [%4];" \
        : "=r"((r)[0]), "=r"((r)[1]), "=r"((r)[2]), "=r"((r)[3]) : "r"(a))

#define MMA_BF16(d, a, b) \
    asm volatile("mma.sync.aligned.m16n8k16.row.col.f32.bf16.bf16.f32 " \
        "{%0,%1,%2,%3}, {%4,%5,%6,%7}, {%8,%9}, {%0,%1,%2,%3};" \
        : "+f"((d)[0]), "+f"((d)[1]), "+f"((d)[2]), "+f"((d)[3]) \
        : "r"((a)[0]), "r"((a)[1]), "r"((a)[2]), "r"((a)[3]), "r"((b)[0]), "r"((b)[1]))

#define CP_ASYNC(dst, src, ok) \
    asm volatile("cp.async.cg.shared.global [%0], [%1], 16, %2;" \
        :: "r"(dst), "l"(src), "r"(ok) : "memory")
#define CP_COMMIT()  asm volatile("cp.async.commit_group;" ::: "memory")
#define CP_WAIT2()   asm volatile("cp.async.wait_group 2;" ::: "memory")

// ---------------------------------------------------------------------------
// small kernels
// ---------------------------------------------------------------------------
__global__ void copy_x_kernel(const float4* __restrict__ x, float4* __restrict__ h, int n4) {
    int i = blockIdx.x * blockDim.x + threadIdx.x;
    if (i < n4) h[i] = x[i];
}

__global__ void edge_agg_kernel(const float* __restrict__ x, const int* __restrict__ ei,
                                float* __restrict__ h, int n_edges) {
    int warp = (blockIdx.x * blockDim.x + threadIdx.x) >> 5;
    int lane = threadIdx.x & 31;
    if (warp >= n_edges) return;
    int src = ei[warp];
    int dst = ei[n_edges + warp];
    const float4 v = *reinterpret_cast<const float4*>(x + (size_t)src * IN_C + lane * 4);
    float* d = h + (size_t)dst * IN_C + lane * 4;
    asm volatile("red.global.add.v4.f32 [%0], {%1, %2, %3, %4};"
                 :: "l"(d), "f"(v.x), "f"(v.y), "f"(v.z), "f"(v.w) : "memory");
}

__global__ void split_kernel(const float* __restrict__ in, bf16* __restrict__ hi,
                             bf16* __restrict__ lo, int n) {
    int i = blockIdx.x * blockDim.x + threadIdx.x;
    if (i >= n) return;
    float v = in[i];
    bf16 h = __float2bfloat16(v);
    hi[i] = h;
    lo[i] = __float2bfloat16(v - __bfloat162float(h));
}

// two plain splits in one launch
__global__ void split2_kernel(const float* __restrict__ a, const float* __restrict__ b,
                              bf16* __restrict__ ahi, bf16* __restrict__ alo,
                              bf16* __restrict__ bhi, bf16* __restrict__ blo, int n) {
    int i = blockIdx.x * blockDim.x + threadIdx.x;
    const float* src; bf16 *hi, *lo; int idx;
    if (i < n)            { src = a; hi = ahi; lo = alo; idx = i; }
    else if (i < 2 * n)   { src = b; hi = bhi; lo = blo; idx = i - n; }
    else return;
    float v = src[idx];
    bf16 h = __float2bfloat16(v);
    hi[idx] = h;
    lo[idx] = __float2bfloat16(v - __bfloat162float(h));
}

// paired transpose-split: z selects (W, dst)
__global__ void wtrans2_kernel(const float* __restrict__ W0, const float* __restrict__ W1,
                               bf16* hi0, bf16* lo0, bf16* hi1, bf16* lo1, int K, int N) {
    const float* W = blockIdx.z ? W1 : W0;
    bf16* hi = blockIdx.z ? hi1 : hi0;
    bf16* lo = blockIdx.z ? lo1 : lo0;
    __shared__ float t[32][33];
    int n0 = blockIdx.x * 32, k0 = blockIdx.y * 32;
#pragma unroll
    for (int dy = 0; dy < 32; dy += 8) {
        int k = k0 + threadIdx.y + dy, n = n0 + threadIdx.x;
        t[threadIdx.y + dy][threadIdx.x] = (k < K && n < N) ? W[(size_t)k * N + n] : 0.f;
    }
    __syncthreads();
#pragma unroll
    for (int dy = 0; dy < 32; dy += 8) {
        int n = n0 + threadIdx.y + dy, k = k0 + threadIdx.x;
        if (n < N && k < K) {
            float v = t[threadIdx.x][threadIdx.y + dy];
            bf16 h = __float2bfloat16(v);
            hi[(size_t)n * K + k] = h;
            lo[(size_t)n * K + k] = __float2bfloat16(v - __bfloat162float(h));
        }
    }
}

__global__ void wtrans_kernel(const float* __restrict__ W, bf16* __restrict__ hi,
                              bf16* __restrict__ lo, int K, int N) {
    __shared__ float t[32][33];
    int n0 = blockIdx.x * 32, k0 = blockIdx.y * 32;
#pragma unroll
    for (int dy = 0; dy < 32; dy += 8) {
        int k = k0 + threadIdx.y + dy, n = n0 + threadIdx.x;
        t[threadIdx.y + dy][threadIdx.x] = (k < K && n < N) ? W[(size_t)k * N + n] : 0.f;
    }
    __syncthreads();
#pragma unroll
    for (int dy = 0; dy < 32; dy += 8) {
        int n = n0 + threadIdx.y + dy, k = k0 + threadIdx.x;
        if (n < N && k < K) {
            float v = t[threadIdx.x][threadIdx.y + dy];
            bf16 h = __float2bfloat16(v);
            hi[(size_t)n * K + k] = h;
            lo[(size_t)n * K + k] = __float2bfloat16(v - __bfloat162float(h));
        }
    }
}

__global__ void concat_bn_kernel(const float* b1a, const float* b1b,
                                 const float* ga,  const float* gb,
                                 const float* bea, const float* beb,
                                 const float* ma,  const float* mb,
                                 const float* va,  const float* vb) {
    int i = threadIdx.x + blockIdx.x * blockDim.x;
    if (i >= HID) return;
    g_bnb [i] = b1a[i];  g_bnb [HID + i] = b1b[i];
    g_bng [i] = ga[i];   g_bng [HID + i] = gb[i];
    g_bnbt[i] = bea[i];  g_bnbt[HID + i] = beb[i];
    g_bnm [i] = ma[i];   g_bnm [HID + i] = mb[i];
    g_bnv [i] = va[i];   g_bnv [HID + i] = vb[i];
}

__global__ void bias_fold_kernel(const float* __restrict__ l1b,
                                 const float* __restrict__ l2w,
                                 const float* __restrict__ l2b,
                                 float* __restrict__ outb) {
    int n = blockIdx.x * blockDim.x + threadIdx.x;
    if (n >= D_FC) return;
    float s = l2b[n];
    for (int k = 0; k < D_L1; k++)
        s += l1b[k] * l2w[(size_t)k * D_FC + n];
    outb[n] = s;
}

__global__ void bias_fold2_kernel(const float* __restrict__ b1,
                                  const float* __restrict__ ow,
                                  const float* __restrict__ outb,
                                  float* __restrict__ ball) {
    int j = threadIdx.x;
    if (j >= OUT_C) return;
    float s = outb[j];
    for (int n = 0; n < D_FC; n++)
        s += b1[n] * ow[(size_t)n * OUT_C + j];
    ball[j] = s;
}

// ---------------------------------------------------------------------------
// bf16x3 mma.sync GEMM: C[M,N] = A[M,K](lda) @ Bt[N,K]^T
// BM_T in {256,128}, BN_T in {128,64}; 256 threads, warp grid 4Mx2N, 4 stages
// ---------------------------------------------------------------------------
#define STAGES 4

template <int BM_T, int BN_T>
__global__ __launch_bounds__(256, 1)
void gemm_mma_kernel(const bf16* __restrict__ Ah_g, const bf16* __restrict__ Al_g,
                     const bf16* __restrict__ Bh_g, const bf16* __restrict__ Bl_g,
                     bf16* __restrict__ Ch, bf16* __restrict__ Cl,
                     float* __restrict__ Cf,
                     const float* __restrict__ bias,
                     const float* __restrict__ gamma, const float* __restrict__ beta,
                     const float* __restrict__ mean,  const float* __restrict__ var,
                     int M, int N, int K, int lda, int ldc, int epi)
{
    constexpr int A_BY   = BM_T * 64;
    constexpr int B_BY   = BN_T * 64;
    constexpr int OFF_AL = A_BY;
    constexpr int OFF_BH = 2 * A_BY;
    constexpr int OFF_BL = 2 * A_BY + B_BY;
    constexpr int STG_B  = 2 * A_BY + 2 * B_BY;
    constexpr int NI     = BM_T / 64;
    constexpr int NJ     = BN_T / 16;
    constexpr int NJJ    = BN_T / 32;
    constexpr int A_IDS  = BM_T * 8;
    constexpr int PER    = (BM_T * 8 + BN_T * 8) / 256;

    extern __shared__ __align__(128) char smem[];
    const uint32_t sb = smem_u32(smem);
    const int tid = threadIdx.x;
    const int lid = tid & 31, wid = tid >> 5;
    const int warpM = wid >> 1, warpN = wid & 1;
    const int m0 = blockIdx.y * BM_T, n0 = blockIdx.x * BN_T;
    const int NC = K >> 5;

    float acc[NI][NJ][4];
#pragma unroll
    for (int i = 0; i < NI; i++)
#pragma unroll
        for (int j = 0; j < NJ; j++)
#pragma unroll
            for (int q = 0; q < 4; q++) acc[i][j][q] = 0.0f;

    auto issue_stage = [&](int c, int s) {
        const int k0 = c << 5;
        const uint32_t stb = sb + s * STG_B;
#pragma unroll
        for (int q = 0; q < PER; q++) {
            int id = q * 256 + tid;
            const bf16* base;
            uint32_t toff;
            int row, ch, gr, rmax, ld;
            if (id < A_IDS) {
                int half = id / (BM_T * 4);
                int idx = id % (BM_T * 4);
                row = idx >> 2; ch = idx & 3;
                base = half ? Al_g : Ah_g;
                toff = half ? (uint32_t)OFF_AL : 0u;
                gr = m0 + row; rmax = M; ld = lda;
            } else {
                int idB = id - A_IDS;
                int half = idB / (BN_T * 4);
                int idx = idB % (BN_T * 4);
                row = idx >> 2; ch = idx & 3;
                base = half ? Bl_g : Bh_g;
                toff = half ? (uint32_t)OFF_BL : (uint32_t)OFF_BH;
                gr = n0 + row; rmax = N; ld = K;
            }
            unsigned ok = (gr < rmax) ? 16u : 0u;
            int rc = (gr < rmax) ? gr : 0;
            const char* src = (const char*)(base + (size_t)rc * ld + k0) + ch * 16;
            uint32_t dst = stb + toff + row * 64 + ((ch ^ ((row >> 1) & 3)) << 4);
            CP_ASYNC(dst, src, ok);
        }
        CP_COMMIT();
    };

    issue_stage(0, 0);
    issue_stage(1, 1);
    issue_stage(2, 2);

    const int grp = lid >> 3, lr = lid & 7;

    int s = 0;
    for (int c = 0; c < NC; c++) {
        CP_WAIT2();
        __syncthreads();
        if (c + 3 < NC) issue_stage(c + 3, (s + 3) & 3);
        else CP_COMMIT();

        const uint32_t stb = sb + s * STG_B;
#pragma unroll
        for (int ks = 0; ks < 2; ks++) {
            uint32_t ah[NI][4];
#pragma unroll
            for (int i = 0; i < NI; i++) {
                int row = warpM * (BM_T / 4) + i * 16 + lr + ((grp & 1) << 3);
                int chk = 2 * ks + (grp >> 1);
                uint32_t ad = stb + row * 64 + ((chk ^ ((row >> 1) & 3)) << 4);
                LDSM4(ah[i], ad);
            }
            uint32_t bh[NJ][2];
#pragma unroll
            for (int jj = 0; jj < NJJ; jj++) {
                int row = warpN * (BN_T / 2) + jj * 16 + lr + ((grp >= 2) ? 8 : 0);
                int chk = 2 * ks + (grp & 1);
                uint32_t bd = stb + OFF_BH + row * 64 + ((chk ^ ((row >> 1) & 3)) << 4);
                uint32_t r[4];
                LDSM4(r, bd);
                bh[2 * jj][0] = r[0]; bh[2 * jj][1] = r[1];
                bh[2 * jj + 1][0] = r[2]; bh[2 * jj + 1][1] = r[3];
            }
#pragma unroll
            for (int i = 0; i < NI; i++)
#pragma unroll
                for (int j = 0; j < NJ; j++)
                    MMA_BF16(acc[i][j], ah[i], bh[j]);
            uint32_t al[NI][4];
#pragma unroll
            for (int i = 0; i < NI; i++) {
                int row = warpM * (BM_T / 4) + i * 16 + lr + ((grp & 1) << 3);
                int chk = 2 * ks + (grp >> 1);
                uint32_t ad = stb + OFF_AL + row * 64 + ((chk ^ ((row >> 1) & 3)) << 4);
                LDSM4(al[i], ad);
            }
            uint32_t bl[NJ][2];
#pragma unroll
            for (int jj = 0; jj < NJJ; jj++) {
                int row = warpN * (BN_T / 2) + jj * 16 + lr + ((grp >= 2) ? 8 : 0);
                int chk = 2 * ks + (grp & 1);
                uint32_t bd = stb + OFF_BL + row * 64 + ((chk ^ ((row >> 1) & 3)) << 4);
                uint32_t r[4];
                LDSM4(r, bd);
                bl[2 * jj][0] = r[0]; bl[2 * jj][1] = r[1];
                bl[2 * jj + 1][0] = r[2]; bl[2 * jj + 1][1] = r[3];
            }
#pragma unroll
            for (int i = 0; i < NI; i++)
#pragma unroll
                for (int j = 0; j < NJ; j++) {
                    MMA_BF16(acc[i][j], ah[i], bl[j]);
                    MMA_BF16(acc[i][j], al[i], bh[j]);
                }
        }
        s = (s + 1) & 3;
    }

    // ---- epilogue ----
    const int r_base = m0 + warpM * (BM_T / 4) + (lid >> 2);
    const int c_base = n0 + warpN * (BN_T / 2) + (lid & 3) * 2;
#pragma unroll
    for (int i = 0; i < NI; i++) {
#pragma unroll
        for (int half = 0; half < 2; half++) {
            int row = r_base + i * 16 + half * 8;
            if (row >= M) continue;
#pragma unroll
            for (int j = 0; j < NJ; j++) {
                int col = c_base + j * 8;
                if (col >= N) continue;
                float v0 = acc[i][j][half * 2 + 0] + bias[col];
                float v1 = acc[i][j][half * 2 + 1] + bias[col + 1];
                if (epi == EPI_BNRELU) {
                    v0 = (v0 - mean[col])     * rsqrtf(var[col] + BN_EPS)     * gamma[col]     + beta[col];
                    v1 = (v1 - mean[col + 1]) * rsqrtf(var[col + 1] + BN_EPS) * gamma[col + 1] + beta[col + 1];
                    v0 = fmaxf(v0, 0.0f); v1 = fmaxf(v1, 0.0f);
                } else if (epi == EPI_RELU) {
                    v0 = fmaxf(v0, 0.0f); v1 = fmaxf(v1, 0.0f);
                } else if (epi == EPI_LEAKY) {
                    v0 = (v0 > 0.0f) ? v0 : 0.01f * v0;
                    v1 = (v1 > 0.0f) ? v1 : 0.01f * v1;
                }
                if (epi == EPI_SIGMOID) {
                    float2 o;
                    o.x = 1.0f / (1.0f + expf(-v0));
                    o.y = 1.0f / (1.0f + expf(-v1));
                    *(float2*)(Cf + (size_t)row * ldc + col) = o;
                } else {
                    bf16 h0 = __float2bfloat16(v0);
                    bf16 h1 = __float2bfloat16(v1);
                    *(__nv_bfloat162*)(Ch + (size_t)row * ldc + col) = __nv_bfloat162(h0, h1);
                    *(__nv_bfloat162*)(Cl + (size_t)row * ldc + col) = __nv_bfloat162(
                        __float2bfloat16(v0 - __bfloat162float(h0)),
                        __float2bfloat16(v1 - __bfloat162float(h1)));
                }
            }
        }
    }
}

// ---------------------------------------------------------------------------
// launch helpers
// ---------------------------------------------------------------------------
template <int BM_T, int BN_T>
static void launch_gemm(cudaStream_t st,
                        const bf16* Ah, const bf16* Al, const bf16* Bh, const bf16* Bl,
                        bf16* Ch, bf16* Cl, float* Cf, const float* bias,
                        const float* ga, const float* be, const float* me, const float* va,
                        int M, int N, int K, int lda, int ldc, int epi) {
    dim3 grid((N + BN_T - 1) / BN_T, (M + BM_T - 1) / BM_T);
    int smem = STAGES * (2 * BM_T * 64 + 2 * BN_T * 64);
    gemm_mma_kernel<BM_T, BN_T><<<grid, 256, smem, st>>>(Ah, Al, Bh, Bl, Ch, Cl, Cf, bias,
                                                         ga, be, me, va, M, N, K, lda, ldc, epi);
}

template <typename T> static T* sym(T* symbol) {
    void* p = nullptr;
    cudaGetSymbolAddress(&p, (const void*)symbol);
    return (T*)p;
}

extern "C" void kernel_launch(void* const* d_in, const int* in_sizes, int n_in,
                              void* d_out, int out_size) {
    const float* x  = (const float*)d_in[0];
    const int*   ei = (const int*)d_in[1];
    const float *w1a = (const float*)d_in[2],  *b1a = (const float*)d_in[3];
    const float *ga  = (const float*)d_in[4],  *bea = (const float*)d_in[5];
    const float *ma  = (const float*)d_in[6],  *va  = (const float*)d_in[7];
    const float *w2a = (const float*)d_in[8],  *b2a = (const float*)d_in[9];
    const float *w1b = (const float*)d_in[10], *b1b = (const float*)d_in[11];
    const float *gb  = (const float*)d_in[12], *beb = (const float*)d_in[13];
    const float *mb  = (const float*)d_in[14], *vb  = (const float*)d_in[15];
    const float *w2b = (const float*)d_in[16], *b2b = (const float*)d_in[17];
    const float *fcw = (const float*)d_in[18], *fcb = (const float*)d_in[19];
    const float *l1w = (const float*)d_in[20], *l1b = (const float*)d_in[21];
    const float *l2w = (const float*)d_in[22], *l2b = (const float*)d_in[23];
    const float *ow  = (const float*)d_in[24], *ob  = (const float*)d_in[25];
    float* out = (float*)d_out;

    // one-time host-handle setup (no device memory)
    static cudaStream_t s2 = nullptr;
    static cudaEvent_t e1 = nullptr, e2 = nullptr;
    static bool attr = false;
    if (!attr) {
        cudaFuncSetAttribute(gemm_mma_kernel<256, 128>,
                             cudaFuncAttributeMaxDynamicSharedMemorySize,
                             STAGES * (2 * 256 * 64 + 2 * 128 * 64));
        cudaFuncSetAttribute(gemm_mma_kernel<128, 128>,
                             cudaFuncAttributeMaxDynamicSharedMemorySize,
                             STAGES * (2 * 128 * 64 + 2 * 128 * 64));
        cudaFuncSetAttribute(gemm_mma_kernel<128, 64>,
                             cudaFuncAttributeMaxDynamicSharedMemorySize,
                             STAGES * (2 * 128 * 64 + 2 * 64 * 64));
        cudaStreamCreateWithFlags(&s2, cudaStreamNonBlocking);
        cudaEventCreateWithFlags(&e1, cudaEventDisableTiming);
        cudaEventCreateWithFlags(&e2, cudaEventDisableTiming);
        attr = true;
    }

    float* h = sym(g_h);
    bf16 *hhi = sym(g_h_hi), *hlo = sym(g_h_lo);
    bf16 *thi = sym(g_t_hi), *tlo = sym(g_t_lo);
    bf16 *chi = sym(g_c_hi), *clo = sym(g_c_lo);
    bf16 *fhi = sym(g_fc_hi), *flo = sym(g_fc_lo);
    bf16 *w1h = sym(g_w1ab_hi), *w1l = sym(g_w1ab_lo);
    bf16 *w2ah = sym(g_w2a_hi), *w2al = sym(g_w2a_lo);
    bf16 *w2bh = sym(g_w2b_hi), *w2bl = sym(g_w2b_lo);
    bf16 *wfh = sym(g_wfc_hi), *wfl = sym(g_wfc_lo);
    bf16 *wl1h = sym(g_wl1_hi), *wl1l = sym(g_wl1_lo);
    bf16 *wl2h = sym(g_wl2_hi), *wl2l = sym(g_wl2_lo);
    bf16 *woh = sym(g_wo_hi), *wol = sym(g_wo_lo);
    bf16 *w2ch = sym(g_w2c_hi), *w2cl = sym(g_w2c_lo);
    bf16 *wallh = sym(g_wall_hi), *walll = sym(g_wall_lo);
    float *bias1 = sym(g_bias1), *ball = sym(g_ball), *zerob = sym(g_zerobias);
    float *bnb = sym(g_bnb), *bng = sym(g_bng), *bnbt = sym(g_bnbt);
    float *bnm = sym(g_bnm), *bnv = sym(g_bnv);

    const int n_edges = in_sizes[1] / 2;
    cudaStream_t ms = 0;   // main (default) stream

    // fork point
    cudaEventRecord(e1, ms);

    // ---- main chain: x-dependent path up through mm1 ----
    {
        int n4 = NN * IN_C / 4;
        copy_x_kernel<<<(n4 + 255) / 256, 256, 0, ms>>>((const float4*)x, (float4*)h, n4);
        long long nthreads = (long long)n_edges * 32;
        edge_agg_kernel<<<(int)((nthreads + 255) / 256), 256, 0, ms>>>(x, ei, h, n_edges);
        int n = NN * IN_C;
        split_kernel<<<(n + 255) / 256, 256, 0, ms>>>(h, hhi, hlo, n);
    }
    {
        dim3 b(32, 8);
        wtrans2_kernel<<<dim3(HID / 32, IN_C / 32, 2), b, 0, ms>>>(
            w1a, w1b, w1h, w1l, w1h + HID * IN_C, w1l + HID * IN_C, IN_C, HID);
        concat_bn_kernel<<<2, 256, 0, ms>>>(b1a, b1b, ga, gb, bea, beb, ma, mb, va, vb);
    }
    // merged conv mm1: t = BNReLU(h @ [w1a|w1b])   [NN, 1024]    (kernel launch #6)
    launch_gemm<256, 128>(ms, hhi, hlo, w1h, w1l, thi, tlo, 0, bnb, bng, bnbt, bnm, bnv,
                          NN, D_CAT, IN_C, IN_C, D_CAT, EPI_BNRELU);

    // ---- side chain (s2): all weight prep independent of x ----
    cudaStreamWaitEvent(s2, e1, 0);
    {
        dim3 b(32, 8);
        wtrans2_kernel<<<dim3(HID / 32, HID / 32, 2), b, 0, s2>>>(
            w2a, w2b, w2ah, w2al, w2bh, w2bl, HID, HID);
        wtrans_kernel<<<dim3(D_FC / 32, D_CAT / 32), b, 0, s2>>>(fcw, wfh, wfl, D_CAT, D_FC);
        wtrans_kernel<<<dim3(OUT_C / 32, D_FC / 32), b, 0, s2>>>(ow, woh, wol, D_FC, OUT_C);
        int n1 = D_FC * D_L1;
        split2_kernel<<<(2 * n1 + 255) / 256, 256, 0, s2>>>(l1w, l2w, wl1h, wl1l, wl2h, wl2l, n1);
        bias_fold_kernel<<<D_FC / 256, 256, 0, s2>>>(l1b, l2w, l2b, bias1);
        bias_fold2_kernel<<<1, OUT_C, 0, s2>>>(bias1, ow, ob, ball);
        // fold GEMMs (M=64 -> BM=128 halves wasted rows)
        launch_gemm<128, 128>(s2, woh, wol, wl2h, wl2l, w2ch, w2cl, 0, zerob, 0, 0, 0, 0,
                              OUT_C, D_L1, D_FC, D_FC, D_L1, EPI_NONE);
        launch_gemm<128, 128>(s2, w2ch, w2cl, wl1h, wl1l, wallh, walll, 0, zerob, 0, 0, 0, 0,
                              OUT_C, D_FC, D_L1, D_L1, D_FC, EPI_NONE);
    }
    cudaEventRecord(e2, s2);

    // ---- join, then the rest of the main chain ----
    cudaStreamWaitEvent(ms, e2, 0);

    // conv mm2 A/B (column slices of t)
    launch_gemm<256, 128>(ms, thi, tlo, w2ah, w2al, chi, clo, 0, b2a, 0, 0, 0, 0,
                          NN, HID, HID, D_CAT, D_CAT, EPI_RELU);
    launch_gemm<256, 128>(ms, thi + HID, tlo + HID, w2bh, w2bl, chi + HID, clo + HID, 0, b2b,
                          0, 0, 0, 0, NN, HID, HID, D_CAT, D_CAT, EPI_RELU);
    // head fc
    launch_gemm<256, 128>(ms, chi, clo, wfh, wfl, fhi, flo, 0, fcb, 0, 0, 0, 0,
                          NN, D_FC, D_CAT, D_CAT, D_FC, EPI_LEAKY);
    // folded tail (BM=128 for wave balance: 470 CTAs)
    launch_gemm<128, 64>(ms, fhi, flo, wallh, walll, 0, 0, out, ball, 0, 0, 0, 0,
                         NN, OUT_C, D_FC, D_FC, OUT_C, EPI_SIGMOID);
}

// round 11
// speedup vs baseline: 5.4944x; 1.0946x over previous
#include <cuda_runtime.h>
#include <cuda_bf16.h>
#include <math.h>
#include <stdint.h>

#define NN      60000
#define IN_C    128
#define HID     512
#define D_CAT   1024
#define D_FC    2048
#define D_L1    4096
#define OUT_C   64
#define BN_EPS  1e-5f

#define EPI_NONE    0
#define EPI_RELU    1
#define EPI_BNRELU  2
#define EPI_LEAKY   3
#define EPI_SIGMOID 4

typedef __nv_bfloat16 bf16;

// ---------------------------------------------------------------------------
// Scratch (__device__ globals; no allocations allowed)
// ---------------------------------------------------------------------------
__device__ float g_h[(size_t)NN * IN_C];
__device__ bf16  g_h_hi [(size_t)NN * IN_C ],  g_h_lo [(size_t)NN * IN_C ];
__device__ bf16  g_t_hi [(size_t)NN * D_CAT],  g_t_lo [(size_t)NN * D_CAT];
__device__ bf16  g_c_hi [(size_t)NN * D_CAT],  g_c_lo [(size_t)NN * D_CAT];
__device__ bf16  g_fc_hi[(size_t)NN * D_FC ],  g_fc_lo[(size_t)NN * D_FC ];
// transposed weights [N,K] hi/lo
__device__ bf16 g_w1ab_hi[D_CAT * IN_C], g_w1ab_lo[D_CAT * IN_C];
__device__ bf16 g_w2a_hi[HID * HID],    g_w2a_lo[HID * HID];
__device__ bf16 g_w2b_hi[HID * HID],    g_w2b_lo[HID * HID];
__device__ bf16 g_wfc_hi[D_FC * D_CAT], g_wfc_lo[D_FC * D_CAT];
__device__ bf16 g_wl1_hi[(size_t)D_FC * D_L1], g_wl1_lo[(size_t)D_FC * D_L1];
__device__ bf16 g_wl2_hi[(size_t)D_L1 * D_FC], g_wl2_lo[(size_t)D_L1 * D_FC];
__device__ bf16 g_wo_hi [OUT_C * D_FC], g_wo_lo [OUT_C * D_FC];
// fold intermediates / results
__device__ bf16  g_w2c_hi [OUT_C * D_L1],  g_w2c_lo [OUT_C * D_L1];
__device__ bf16  g_wall_hi[OUT_C * D_FC],  g_wall_lo[OUT_C * D_FC];
__device__ float g_bias1[D_FC];
__device__ float g_ball [OUT_C];
__device__ float g_zerobias[D_L1];
// concatenated BN params
__device__ float g_bnb[D_CAT], g_bng[D_CAT], g_bnbt[D_CAT], g_bnm[D_CAT], g_bnv[D_CAT];

// ---------------------------------------------------------------------------
// helpers
// ---------------------------------------------------------------------------
__device__ __forceinline__ uint32_t smem_u32(const void* p) {
    uint32_t a;
    asm("{ .reg .u64 t; cvta.to.shared.u64 t, %1; cvt.u32.u64 %0, t; }" : "=r"(a) : "l"(p));
    return a;
}

#define LDSM4(r, a) \
    asm volatile("ldmatrix.sync.aligned.m8n8.x4.shared.b16 {%0,%1,%2,%3}, [%4];" \
        : "=r"((r)[0]), "=r"((r)[1]), "=r"((r)[2]), "=r"((r)[3]) : "r"(a))

#define MMA_BF16(d, a, b) \
    asm volatile("mma.sync.aligned.m16n8k16.row.col.f32.bf16.bf16.f32 " \
        "{%0,%1,%2,%3}, {%4,%5,%6,%7}, {%8,%9}, {%0,%1,%2,%3};" \
        : "+f"((d)[0]), "+f"((d)[1]), "+f"((d)[2]), "+f"((d)[3]) \
        : "r"((a)[0]), "r"((a)[1]), "r"((a)[2]), "r"((a)[3]), "r"((b)[0]), "r"((b)[1]))

#define CP_ASYNC(dst, src, ok) \
    asm volatile("cp.async.cg.shared.global [%0], [%1], 16, %2;" \
        :: "r"(dst), "l"(src), "r"(ok) : "memory")
#define CP_COMMIT()  asm volatile("cp.async.commit_group;" ::: "memory")
#define CP_WAIT2()   asm volatile("cp.async.wait_group 2;" ::: "memory")

// ---------------------------------------------------------------------------
// small kernels
// ---------------------------------------------------------------------------
__global__ void copy_x_kernel(const float4* __restrict__ x, float4* __restrict__ h, int n4) {
    int i = blockIdx.x * blockDim.x + threadIdx.x;
    if (i < n4) h[i] = x[i];
}

__global__ void edge_agg_kernel(const float* __restrict__ x, const int* __restrict__ ei,
                                float* __restrict__ h, int n_edges) {
    int warp = (blockIdx.x * blockDim.x + threadIdx.x) >> 5;
    int lane = threadIdx.x & 31;
    if (warp >= n_edges) return;
    int src = ei[warp];
    int dst = ei[n_edges + warp];
    const float4 v = *reinterpret_cast<const float4*>(x + (size_t)src * IN_C + lane * 4);
    float* d = h + (size_t)dst * IN_C + lane * 4;
    asm volatile("red.global.add.v4.f32 [%0], {%1, %2, %3, %4};"
                 :: "l"(d), "f"(v.x), "f"(v.y), "f"(v.z), "f"(v.w) : "memory");
}

__global__ void split_kernel(const float* __restrict__ in, bf16* __restrict__ hi,
                             bf16* __restrict__ lo, int n) {
    int i = blockIdx.x * blockDim.x + threadIdx.x;
    if (i >= n) return;
    float v = in[i];
    bf16 h = __float2bfloat16(v);
    hi[i] = h;
    lo[i] = __float2bfloat16(v - __bfloat162float(h));
}

__global__ void split2_kernel(const float* __restrict__ a, const float* __restrict__ b,
                              bf16* __restrict__ ahi, bf16* __restrict__ alo,
                              bf16* __restrict__ bhi, bf16* __restrict__ blo, int n) {
    int i = blockIdx.x * blockDim.x + threadIdx.x;
    const float* src; bf16 *hi, *lo; int idx;
    if (i < n)            { src = a; hi = ahi; lo = alo; idx = i; }
    else if (i < 2 * n)   { src = b; hi = bhi; lo = blo; idx = i - n; }
    else return;
    float v = src[idx];
    bf16 h = __float2bfloat16(v);
    hi[idx] = h;
    lo[idx] = __float2bfloat16(v - __bfloat162float(h));
}

__global__ void wtrans2_kernel(const float* __restrict__ W0, const float* __restrict__ W1,
                               bf16* hi0, bf16* lo0, bf16* hi1, bf16* lo1, int K, int N) {
    const float* W = blockIdx.z ? W1 : W0;
    bf16* hi = blockIdx.z ? hi1 : hi0;
    bf16* lo = blockIdx.z ? lo1 : lo0;
    __shared__ float t[32][33];
    int n0 = blockIdx.x * 32, k0 = blockIdx.y * 32;
#pragma unroll
    for (int dy = 0; dy < 32; dy += 8) {
        int k = k0 + threadIdx.y + dy, n = n0 + threadIdx.x;
        t[threadIdx.y + dy][threadIdx.x] = (k < K && n < N) ? W[(size_t)k * N + n] : 0.f;
    }
    __syncthreads();
#pragma unroll
    for (int dy = 0; dy < 32; dy += 8) {
        int n = n0 + threadIdx.y + dy, k = k0 + threadIdx.x;
        if (n < N && k < K) {
            float v = t[threadIdx.x][threadIdx.y + dy];
            bf16 h = __float2bfloat16(v);
            hi[(size_t)n * K + k] = h;
            lo[(size_t)n * K + k] = __float2bfloat16(v - __bfloat162float(h));
        }
    }
}

__global__ void wtrans_kernel(const float* __restrict__ W, bf16* __restrict__ hi,
                              bf16* __restrict__ lo, int K, int N) {
    __shared__ float t[32][33];
    int n0 = blockIdx.x * 32, k0 = blockIdx.y * 32;
#pragma unroll
    for (int dy = 0; dy < 32; dy += 8) {
        int k = k0 + threadIdx.y + dy, n = n0 + threadIdx.x;
        t[threadIdx.y + dy][threadIdx.x] = (k < K && n < N) ? W[(size_t)k * N + n] : 0.f;
    }
    __syncthreads();
#pragma unroll
    for (int dy = 0; dy < 32; dy += 8) {
        int n = n0 + threadIdx.y + dy, k = k0 + threadIdx.x;
        if (n < N && k < K) {
            float v = t[threadIdx.x][threadIdx.y + dy];
            bf16 h = __float2bfloat16(v);
            hi[(size_t)n * K + k] = h;
            lo[(size_t)n * K + k] = __float2bfloat16(v - __bfloat162float(h));
        }
    }
}

__global__ void concat_bn_kernel(const float* b1a, const float* b1b,
                                 const float* ga,  const float* gb,
                                 const float* bea, const float* beb,
                                 const float* ma,  const float* mb,
                                 const float* va,  const float* vb) {
    int i = threadIdx.x + blockIdx.x * blockDim.x;
    if (i >= HID) return;
    g_bnb [i] = b1a[i];  g_bnb [HID + i] = b1b[i];
    g_bng [i] = ga[i];   g_bng [HID + i] = gb[i];
    g_bnbt[i] = bea[i];  g_bnbt[HID + i] = beb[i];
    g_bnm [i] = ma[i];   g_bnm [HID + i] = mb[i];
    g_bnv [i] = va[i];   g_bnv [HID + i] = vb[i];
}

__global__ void bias_fold_kernel(const float* __restrict__ l1b,
                                 const float* __restrict__ l2w,
                                 const float* __restrict__ l2b,
                                 float* __restrict__ outb) {
    int n = blockIdx.x * blockDim.x + threadIdx.x;
    if (n >= D_FC) return;
    float s = l2b[n];
    for (int k = 0; k < D_L1; k++)
        s += l1b[k] * l2w[(size_t)k * D_FC + n];
    outb[n] = s;
}

__global__ void bias_fold2_kernel(const float* __restrict__ b1,
                                  const float* __restrict__ ow,
                                  const float* __restrict__ outb,
                                  float* __restrict__ ball) {
    int j = threadIdx.x;
    if (j >= OUT_C) return;
    float s = outb[j];
    for (int n = 0; n < D_FC; n++)
        s += b1[n] * ow[(size_t)n * OUT_C + j];
    ball[j] = s;
}

// ---------------------------------------------------------------------------
// bf16x3 mma.sync GEMM: C[M,N] = A[M,K](lda) @ Bt[N,K]^T
// ---------------------------------------------------------------------------
#define STAGES 4

template <int BM_T, int BN_T>
__global__ __launch_bounds__(256, 1)
void gemm_mma_kernel(const bf16* __restrict__ Ah_g, const bf16* __restrict__ Al_g,
                     const bf16* __restrict__ Bh_g, const bf16* __restrict__ Bl_g,
                     bf16* __restrict__ Ch, bf16* __restrict__ Cl,
                     float* __restrict__ Cf,
                     const float* __restrict__ bias,
                     const float* __restrict__ gamma, const float* __restrict__ beta,
                     const float* __restrict__ mean,  const float* __restrict__ var,
                     int M, int N, int K, int lda, int ldc, int epi)
{
    constexpr int A_BY   = BM_T * 64;
    constexpr int B_BY   = BN_T * 64;
    constexpr int OFF_AL = A_BY;
    constexpr int OFF_BH = 2 * A_BY;
    constexpr int OFF_BL = 2 * A_BY + B_BY;
    constexpr int STG_B  = 2 * A_BY + 2 * B_BY;
    constexpr int NI     = BM_T / 64;
    constexpr int NJ     = BN_T / 16;
    constexpr int NJJ    = BN_T / 32;
    constexpr int A_IDS  = BM_T * 8;
    constexpr int PER    = (BM_T * 8 + BN_T * 8) / 256;

    extern __shared__ __align__(128) char smem[];
    const uint32_t sb = smem_u32(smem);
    const int tid = threadIdx.x;
    const int lid = tid & 31, wid = tid >> 5;
    const int warpM = wid >> 1, warpN = wid & 1;
    const int m0 = blockIdx.y * BM_T, n0 = blockIdx.x * BN_T;
    const int NC = K >> 5;

    float acc[NI][NJ][4];
#pragma unroll
    for (int i = 0; i < NI; i++)
#pragma unroll
        for (int j = 0; j < NJ; j++)
#pragma unroll
            for (int q = 0; q < 4; q++) acc[i][j][q] = 0.0f;

    auto issue_stage = [&](int c, int s) {
        const int k0 = c << 5;
        const uint32_t stb = sb + s * STG_B;
#pragma unroll
        for (int q = 0; q < PER; q++) {
            int id = q * 256 + tid;
            const bf16* base;
            uint32_t toff;
            int row, ch, gr, rmax, ld;
            if (id < A_IDS) {
                int half = id / (BM_T * 4);
                int idx = id % (BM_T * 4);
                row = idx >> 2; ch = idx & 3;
                base = half ? Al_g : Ah_g;
                toff = half ? (uint32_t)OFF_AL : 0u;
                gr = m0 + row; rmax = M; ld = lda;
            } else {
                int idB = id - A_IDS;
                int half = idB / (BN_T * 4);
                int idx = idB % (BN_T * 4);
                row = idx >> 2; ch = idx & 3;
                base = half ? Bl_g : Bh_g;
                toff = half ? (uint32_t)OFF_BL : (uint32_t)OFF_BH;
                gr = n0 + row; rmax = N; ld = K;
            }
            unsigned ok = (gr < rmax) ? 16u : 0u;
            int rc = (gr < rmax) ? gr : 0;
            const char* src = (const char*)(base + (size_t)rc * ld + k0) + ch * 16;
            uint32_t dst = stb + toff + row * 64 + ((ch ^ ((row >> 1) & 3)) << 4);
            CP_ASYNC(dst, src, ok);
        }
        CP_COMMIT();
    };

    issue_stage(0, 0);
    issue_stage(1, 1);
    issue_stage(2, 2);

    const int grp = lid >> 3, lr = lid & 7;

    int s = 0;
    for (int c = 0; c < NC; c++) {
        CP_WAIT2();
        __syncthreads();
        if (c + 3 < NC) issue_stage(c + 3, (s + 3) & 3);
        else CP_COMMIT();

        const uint32_t stb = sb + s * STG_B;
#pragma unroll
        for (int ks = 0; ks < 2; ks++) {
            uint32_t ah[NI][4];
#pragma unroll
            for (int i = 0; i < NI; i++) {
                int row = warpM * (BM_T / 4) + i * 16 + lr + ((grp & 1) << 3);
                int chk = 2 * ks + (grp >> 1);
                uint32_t ad = stb + row * 64 + ((chk ^ ((row >> 1) & 3)) << 4);
                LDSM4(ah[i], ad);
            }
            uint32_t bh[NJ][2];
#pragma unroll
            for (int jj = 0; jj < NJJ; jj++) {
                int row = warpN * (BN_T / 2) + jj * 16 + lr + ((grp >= 2) ? 8 : 0);
                int chk = 2 * ks + (grp & 1);
                uint32_t bd = stb + OFF_BH + row * 64 + ((chk ^ ((row >> 1) & 3)) << 4);
                uint32_t r[4];
                LDSM4(r, bd);
                bh[2 * jj][0] = r[0]; bh[2 * jj][1] = r[1];
                bh[2 * jj + 1][0] = r[2]; bh[2 * jj + 1][1] = r[3];
            }
#pragma unroll
            for (int i = 0; i < NI; i++)
#pragma unroll
                for (int j = 0; j < NJ; j++)
                    MMA_BF16(acc[i][j], ah[i], bh[j]);
            uint32_t al[NI][4];
#pragma unroll
            for (int i = 0; i < NI; i++) {
                int row = warpM * (BM_T / 4) + i * 16 + lr + ((grp & 1) << 3);
                int chk = 2 * ks + (grp >> 1);
                uint32_t ad = stb + OFF_AL + row * 64 + ((chk ^ ((row >> 1) & 3)) << 4);
                LDSM4(al[i], ad);
            }
            uint32_t bl[NJ][2];
#pragma unroll
            for (int jj = 0; jj < NJJ; jj++) {
                int row = warpN * (BN_T / 2) + jj * 16 + lr + ((grp >= 2) ? 8 : 0);
                int chk = 2 * ks + (grp & 1);
                uint32_t bd = stb + OFF_BL + row * 64 + ((chk ^ ((row >> 1) & 3)) << 4);
                uint32_t r[4];
                LDSM4(r, bd);
                bl[2 * jj][0] = r[0]; bl[2 * jj][1] = r[1];
                bl[2 * jj + 1][0] = r[2]; bl[2 * jj + 1][1] = r[3];
            }
#pragma unroll
            for (int i = 0; i < NI; i++)
#pragma unroll
                for (int j = 0; j < NJ; j++) {
                    MMA_BF16(acc[i][j], ah[i], bl[j]);
                    MMA_BF16(acc[i][j], al[i], bh[j]);
                }
        }
        s = (s + 1) & 3;
    }

    // ---- epilogue ----
    const int r_base = m0 + warpM * (BM_T / 4) + (lid >> 2);
    const int c_base = n0 + warpN * (BN_T / 2) + (lid & 3) * 2;
#pragma unroll
    for (int i = 0; i < NI; i++) {
#pragma unroll
        for (int half = 0; half < 2; half++) {
            int row = r_base + i * 16 + half * 8;
            if (row >= M) continue;
#pragma unroll
            for (int j = 0; j < NJ; j++) {
                int col = c_base + j * 8;
                if (col >= N) continue;
                float v0 = acc[i][j][half * 2 + 0] + bias[col];
                float v1 = acc[i][j][half * 2 + 1] + bias[col + 1];
                if (epi == EPI_BNRELU) {
                    v0 = (v0 - mean[col])     * rsqrtf(var[col] + BN_EPS)     * gamma[col]     + beta[col];
                    v1 = (v1 - mean[col + 1]) * rsqrtf(var[col + 1] + BN_EPS) * gamma[col + 1] + beta[col + 1];
                    v0 = fmaxf(v0, 0.0f); v1 = fmaxf(v1, 0.0f);
                } else if (epi == EPI_RELU) {
                    v0 = fmaxf(v0, 0.0f); v1 = fmaxf(v1, 0.0f);
                } else if (epi == EPI_LEAKY) {
                    v0 = (v0 > 0.0f) ? v0 : 0.01f * v0;
                    v1 = (v1 > 0.0f) ? v1 : 0.01f * v1;
                }
                if (epi == EPI_SIGMOID) {
                    float2 o;
                    o.x = 1.0f / (1.0f + expf(-v0));
                    o.y = 1.0f / (1.0f + expf(-v1));
                    *(float2*)(Cf + (size_t)row * ldc + col) = o;
                } else {
                    bf16 h0 = __float2bfloat16(v0);
                    bf16 h1 = __float2bfloat16(v1);
                    *(__nv_bfloat162*)(Ch + (size_t)row * ldc + col) = __nv_bfloat162(h0, h1);
                    *(__nv_bfloat162*)(Cl + (size_t)row * ldc + col) = __nv_bfloat162(
                        __float2bfloat16(v0 - __bfloat162float(h0)),
                        __float2bfloat16(v1 - __bfloat162float(h1)));
                }
            }
        }
    }
}

// ---------------------------------------------------------------------------
// launch helpers
// ---------------------------------------------------------------------------
template <int BM_T, int BN_T>
static void launch_gemm(cudaStream_t st,
                        const bf16* Ah, const bf16* Al, const bf16* Bh, const bf16* Bl,
                        bf16* Ch, bf16* Cl, float* Cf, const float* bias,
                        const float* ga, const float* be, const float* me, const float* va,
                        int M, int N, int K, int lda, int ldc, int epi) {
    dim3 grid((N + BN_T - 1) / BN_T, (M + BM_T - 1) / BM_T);
    int smem = STAGES * (2 * BM_T * 64 + 2 * BN_T * 64);
    gemm_mma_kernel<BM_T, BN_T><<<grid, 256, smem, st>>>(Ah, Al, Bh, Bl, Ch, Cl, Cf, bias,
                                                         ga, be, me, va, M, N, K, lda, ldc, epi);
}

template <typename T> static T* sym(T* symbol) {
    void* p = nullptr;
    cudaGetSymbolAddress(&p, (const void*)symbol);
    return (T*)p;
}

extern "C" void kernel_launch(void* const* d_in, const int* in_sizes, int n_in,
                              void* d_out, int out_size) {
    const float* x  = (const float*)d_in[0];
    const int*   ei = (const int*)d_in[1];
    const float *w1a = (const float*)d_in[2],  *b1a = (const float*)d_in[3];
    const float *ga  = (const float*)d_in[4],  *bea = (const float*)d_in[5];
    const float *ma  = (const float*)d_in[6],  *va  = (const float*)d_in[7];
    const float *w2a = (const float*)d_in[8],  *b2a = (const float*)d_in[9];
    const float *w1b = (const float*)d_in[10], *b1b = (const float*)d_in[11];
    const float *gb  = (const float*)d_in[12], *beb = (const float*)d_in[13];
    const float *mb  = (const float*)d_in[14], *vb  = (const float*)d_in[15];
    const float *w2b = (const float*)d_in[16], *b2b = (const float*)d_in[17];
    const float *fcw = (const float*)d_in[18], *fcb = (const float*)d_in[19];
    const float *l1w = (const float*)d_in[20], *l1b = (const float*)d_in[21];
    const float *l2w = (const float*)d_in[22], *l2b = (const float*)d_in[23];
    const float *ow  = (const float*)d_in[24], *ob  = (const float*)d_in[25];
    float* out = (float*)d_out;

    // one-time host-handle setup (no device memory)
    static cudaStream_t s2 = nullptr, s3 = nullptr;
    static cudaEvent_t e1 = nullptr, e2 = nullptr, eW2 = nullptr, eFC = nullptr,
                       eM1 = nullptr, eB = nullptr;
    static bool attr = false;
    if (!attr) {
        cudaFuncSetAttribute(gemm_mma_kernel<256, 128>,
                             cudaFuncAttributeMaxDynamicSharedMemorySize,
                             STAGES * (2 * 256 * 64 + 2 * 128 * 64));
        cudaFuncSetAttribute(gemm_mma_kernel<128, 64>,
                             cudaFuncAttributeMaxDynamicSharedMemorySize,
                             STAGES * (2 * 128 * 64 + 2 * 64 * 64));
        cudaStreamCreateWithFlags(&s2, cudaStreamNonBlocking);
        cudaStreamCreateWithFlags(&s3, cudaStreamNonBlocking);
        cudaEventCreateWithFlags(&e1,  cudaEventDisableTiming);
        cudaEventCreateWithFlags(&e2,  cudaEventDisableTiming);
        cudaEventCreateWithFlags(&eW2, cudaEventDisableTiming);
        cudaEventCreateWithFlags(&eFC, cudaEventDisableTiming);
        cudaEventCreateWithFlags(&eM1, cudaEventDisableTiming);
        cudaEventCreateWithFlags(&eB,  cudaEventDisableTiming);
        attr = true;
    }

    float* h = sym(g_h);
    bf16 *hhi = sym(g_h_hi), *hlo = sym(g_h_lo);
    bf16 *thi = sym(g_t_hi), *tlo = sym(g_t_lo);
    bf16 *chi = sym(g_c_hi), *clo = sym(g_c_lo);
    bf16 *fhi = sym(g_fc_hi), *flo = sym(g_fc_lo);
    bf16 *w1h = sym(g_w1ab_hi), *w1l = sym(g_w1ab_lo);
    bf16 *w2ah = sym(g_w2a_hi), *w2al = sym(g_w2a_lo);
    bf16 *w2bh = sym(g_w2b_hi), *w2bl = sym(g_w2b_lo);
    bf16 *wfh = sym(g_wfc_hi), *wfl = sym(g_wfc_lo);
    bf16 *wl1h = sym(g_wl1_hi), *wl1l = sym(g_wl1_lo);
    bf16 *wl2h = sym(g_wl2_hi), *wl2l = sym(g_wl2_lo);
    bf16 *woh = sym(g_wo_hi), *wol = sym(g_wo_lo);
    bf16 *w2ch = sym(g_w2c_hi), *w2cl = sym(g_w2c_lo);
    bf16 *wallh = sym(g_wall_hi), *walll = sym(g_wall_lo);
    float *bias1 = sym(g_bias1), *ball = sym(g_ball), *zerob = sym(g_zerobias);
    float *bnb = sym(g_bnb), *bng = sym(g_bng), *bnbt = sym(g_bnbt);
    float *bnm = sym(g_bnm), *bnv = sym(g_bnv);

    const int n_edges = in_sizes[1] / 2;
    cudaStream_t ms = 0;   // main (default) stream

    // fork point
    cudaEventRecord(e1, ms);

    // ---- side chain (s2): weight prep, finest-grained events ----
    cudaStreamWaitEvent(s2, e1, 0);
    {
        dim3 b(32, 8);
        // 1) w2 transposes — needed first (by mm2)
        wtrans2_kernel<<<dim3(HID / 32, HID / 32, 2), b, 0, s2>>>(
            w2a, w2b, w2ah, w2al, w2bh, w2bl, HID, HID);
        cudaEventRecord(eW2, s2);
        // 2) fc weight — needed by fc
        wtrans_kernel<<<dim3(D_FC / 32, D_CAT / 32), b, 0, s2>>>(fcw, wfh, wfl, D_CAT, D_FC);
        cudaEventRecord(eFC, s2);
        // 3) tail fold chain — needed only by the last GEMM
        wtrans_kernel<<<dim3(OUT_C / 32, D_FC / 32), b, 0, s2>>>(ow, woh, wol, D_FC, OUT_C);
        int n1 = D_FC * D_L1;
        split2_kernel<<<(2 * n1 + 255) / 256, 256, 0, s2>>>(l1w, l2w, wl1h, wl1l, wl2h, wl2l, n1);
        bias_fold_kernel<<<D_FC / 256, 256, 0, s2>>>(l1b, l2w, l2b, bias1);
        bias_fold2_kernel<<<1, OUT_C, 0, s2>>>(bias1, ow, ob, ball);
        launch_gemm<128, 64>(s2, woh, wol, wl2h, wl2l, w2ch, w2cl, 0, zerob, 0, 0, 0, 0,
                             OUT_C, D_L1, D_FC, D_FC, D_L1, EPI_NONE);
        launch_gemm<128, 64>(s2, w2ch, w2cl, wl1h, wl1l, wallh, walll, 0, zerob, 0, 0, 0, 0,
                             OUT_C, D_FC, D_L1, D_L1, D_FC, EPI_NONE);
        cudaEventRecord(e2, s2);
    }

    // ---- main chain: x-dependent path ----
    {
        int n4 = NN * IN_C / 4;
        copy_x_kernel<<<(n4 + 255) / 256, 256, 0, ms>>>((const float4*)x, (float4*)h, n4);
        long long nthreads = (long long)n_edges * 32;
        edge_agg_kernel<<<(int)((nthreads + 255) / 256), 256, 0, ms>>>(x, ei, h, n_edges);
        int n = NN * IN_C;
        split_kernel<<<(n + 255) / 256, 256, 0, ms>>>(h, hhi, hlo, n);
        dim3 b(32, 8);
        wtrans2_kernel<<<dim3(HID / 32, IN_C / 32, 2), b, 0, ms>>>(
            w1a, w1b, w1h, w1l, w1h + HID * IN_C, w1l + HID * IN_C, IN_C, HID);
        concat_bn_kernel<<<2, 256, 0, ms>>>(b1a, b1b, ga, gb, bea, beb, ma, mb, va, vb);
    }
    // mm1: t = BNReLU(h @ [w1a|w1b])
    launch_gemm<256, 128>(ms, hhi, hlo, w1h, w1l, thi, tlo, 0, bnb, bng, bnbt, bnm, bnv,
                          NN, D_CAT, IN_C, IN_C, D_CAT, EPI_BNRELU);
    cudaEventRecord(eM1, ms);

    // mm2b on s3 (parallel with mm2a on ms)
    cudaStreamWaitEvent(s3, eM1, 0);
    cudaStreamWaitEvent(s3, eW2, 0);
    launch_gemm<256, 128>(s3, thi + HID, tlo + HID, w2bh, w2bl, chi + HID, clo + HID, 0, b2b,
                          0, 0, 0, 0, NN, HID, HID, D_CAT, D_CAT, EPI_RELU);
    cudaEventRecord(eB, s3);

    // mm2a on ms
    cudaStreamWaitEvent(ms, eW2, 0);
    launch_gemm<256, 128>(ms, thi, tlo, w2ah, w2al, chi, clo, 0, b2a, 0, 0, 0, 0,
                          NN, HID, HID, D_CAT, D_CAT, EPI_RELU);

    // fc (needs mm2a [stream], mm2b [eB], fc weights [eFC])
    cudaStreamWaitEvent(ms, eB, 0);
    cudaStreamWaitEvent(ms, eFC, 0);
    launch_gemm<256, 128>(ms, chi, clo, wfh, wfl, fhi, flo, 0, fcb, 0, 0, 0, 0,
                          NN, D_FC, D_CAT, D_CAT, D_FC, EPI_LEAKY);

    // folded tail (needs fc [stream] + folds [e2])
    cudaStreamWaitEvent(ms, e2, 0);
    launch_gemm<128, 64>(ms, fhi, flo, wallh, walll, 0, 0, out, ball, 0, 0, 0, 0,
                         NN, OUT_C, D_FC, D_FC, OUT_C, EPI_SIGMOID);
}

// round 12
// speedup vs baseline: 5.5638x; 1.0126x over previous
#include <cuda_runtime.h>
#include <cuda_bf16.h>
#include <math.h>
#include <stdint.h>

#define NN      60000
#define IN_C    128
#define HID     512
#define D_CAT   1024
#define D_FC    2048
#define D_L1    4096
#define OUT_C   64
#define BN_EPS  1e-5f

#define EPI_NONE    0
#define EPI_RELU    1
#define EPI_BNRELU  2
#define EPI_LEAKY   3
#define EPI_SIGMOID 4

typedef __nv_bfloat16 bf16;

// ---------------------------------------------------------------------------
// Scratch (__device__ globals; no allocations allowed)
// ---------------------------------------------------------------------------
__device__ float g_h[(size_t)NN * IN_C];
__device__ bf16  g_h_hi [(size_t)NN * IN_C ],  g_h_lo [(size_t)NN * IN_C ];
__device__ bf16  g_t_hi [(size_t)NN * D_CAT],  g_t_lo [(size_t)NN * D_CAT];
__device__ bf16  g_c_hi [(size_t)NN * D_CAT],  g_c_lo [(size_t)NN * D_CAT];
__device__ bf16  g_fc_hi[(size_t)NN * D_FC ],  g_fc_lo[(size_t)NN * D_FC ];
// transposed weights [N,K] hi/lo
__device__ bf16 g_w1ab_hi[D_CAT * IN_C], g_w1ab_lo[D_CAT * IN_C];
__device__ bf16 g_w2a_hi[HID * HID],    g_w2a_lo[HID * HID];
__device__ bf16 g_w2b_hi[HID * HID],    g_w2b_lo[HID * HID];
__device__ bf16 g_wfc_hi[D_FC * D_CAT], g_wfc_lo[D_FC * D_CAT];
__device__ bf16 g_wl1_hi[(size_t)D_FC * D_L1], g_wl1_lo[(size_t)D_FC * D_L1];
__device__ bf16 g_wl2_hi[(size_t)D_L1 * D_FC], g_wl2_lo[(size_t)D_L1 * D_FC];
__device__ bf16 g_wo_hi [OUT_C * D_FC], g_wo_lo [OUT_C * D_FC];
// fold intermediates / results
__device__ bf16  g_w2c_hi [OUT_C * D_L1],  g_w2c_lo [OUT_C * D_L1];
__device__ bf16  g_wall_hi[OUT_C * D_FC],  g_wall_lo[OUT_C * D_FC];
__device__ float g_bias1[D_FC];
__device__ float g_ball [OUT_C];
__device__ float g_zerobias[D_L1];
// concatenated BN params
__device__ float g_bnb[D_CAT], g_bng[D_CAT], g_bnbt[D_CAT], g_bnm[D_CAT], g_bnv[D_CAT];

// ---------------------------------------------------------------------------
// helpers
// ---------------------------------------------------------------------------
__device__ __forceinline__ uint32_t smem_u32(const void* p) {
    uint32_t a;
    asm("{ .reg .u64 t; cvta.to.shared.u64 t, %1; cvt.u32.u64 %0, t; }" : "=r"(a) : "l"(p));
    return a;
}

#define LDSM4(r, a) \
    asm volatile("ldmatrix.sync.aligned.m8n8.x4.shared.b16 {%0,%1,%2,%3}, [%4];" \
        : "=r"((r)[0]), "=r"((r)[1]), "=r"((r)[2]), "=r"((r)[3]) : "r"(a))

#define MMA_BF16(d, a, b) \
    asm volatile("mma.sync.aligned.m16n8k16.row.col.f32.bf16.bf16.f32 " \
        "{%0,%1,%2,%3}, {%4,%5,%6,%7}, {%8,%9}, {%0,%1,%2,%3};" \
        : "+f"((d)[0]), "+f"((d)[1]), "+f"((d)[2]), "+f"((d)[3]) \
        : "r"((a)[0]), "r"((a)[1]), "r"((a)[2]), "r"((a)[3]), "r"((b)[0]), "r"((b)[1]))

#define CP_ASYNC(dst, src, ok) \
    asm volatile("cp.async.cg.shared.global [%0], [%1], 16, %2;" \
        :: "r"(dst), "l"(src), "r"(ok) : "memory")
#define CP_COMMIT()  asm volatile("cp.async.commit_group;" ::: "memory")
#define CP_WAIT2()   asm volatile("cp.async.wait_group 2;" ::: "memory")

// ---------------------------------------------------------------------------
// small kernels
// ---------------------------------------------------------------------------
__global__ void copy_x_kernel(const float4* __restrict__ x, float4* __restrict__ h, int n4) {
    int i = blockIdx.x * blockDim.x + threadIdx.x;
    if (i < n4) h[i] = x[i];
}

__global__ void edge_agg_kernel(const float* __restrict__ x, const int* __restrict__ ei,
                                float* __restrict__ h, int n_edges) {
    int warp = (blockIdx.x * blockDim.x + threadIdx.x) >> 5;
    int lane = threadIdx.x & 31;
    if (warp >= n_edges) return;
    int src = ei[warp];
    int dst = ei[n_edges + warp];
    const float4 v = *reinterpret_cast<const float4*>(x + (size_t)src * IN_C + lane * 4);
    float* d = h + (size_t)dst * IN_C + lane * 4;
    asm volatile("red.global.add.v4.f32 [%0], {%1, %2, %3, %4};"
                 :: "l"(d), "f"(v.x), "f"(v.y), "f"(v.z), "f"(v.w) : "memory");
}

// vectorized split: 4 floats / thread
__device__ __forceinline__ void split4(float4 v, uint2& hiw, uint2& low) {
    __nv_bfloat162 h01(__float2bfloat16(v.x), __float2bfloat16(v.y));
    __nv_bfloat162 h23(__float2bfloat16(v.z), __float2bfloat16(v.w));
    __nv_bfloat162 l01(__float2bfloat16(v.x - __bfloat162float(h01.x)),
                       __float2bfloat16(v.y - __bfloat162float(h01.y)));
    __nv_bfloat162 l23(__float2bfloat16(v.z - __bfloat162float(h23.x)),
                       __float2bfloat16(v.w - __bfloat162float(h23.y)));
    hiw.x = *(uint32_t*)&h01; hiw.y = *(uint32_t*)&h23;
    low.x = *(uint32_t*)&l01; low.y = *(uint32_t*)&l23;
}

__global__ void split_kernel(const float4* __restrict__ in, uint2* __restrict__ hi,
                             uint2* __restrict__ lo, int n4) {
    int i = blockIdx.x * blockDim.x + threadIdx.x;
    if (i >= n4) return;
    uint2 H, L;
    split4(in[i], H, L);
    hi[i] = H; lo[i] = L;
}

__global__ void split2_kernel(const float4* __restrict__ a, const float4* __restrict__ b,
                              uint2* __restrict__ ahi, uint2* __restrict__ alo,
                              uint2* __restrict__ bhi, uint2* __restrict__ blo, int n4) {
    int i = blockIdx.x * blockDim.x + threadIdx.x;
    const float4* src; uint2 *hi, *lo; int idx;
    if (i < n4)            { src = a; hi = ahi; lo = alo; idx = i; }
    else if (i < 2 * n4)   { src = b; hi = bhi; lo = blo; idx = i - n4; }
    else return;
    uint2 H, L;
    split4(src[idx], H, L);
    hi[idx] = H; lo[idx] = L;
}

__global__ void wtrans2_kernel(const float* __restrict__ W0, const float* __restrict__ W1,
                               bf16* hi0, bf16* lo0, bf16* hi1, bf16* lo1, int K, int N) {
    const float* W = blockIdx.z ? W1 : W0;
    bf16* hi = blockIdx.z ? hi1 : hi0;
    bf16* lo = blockIdx.z ? lo1 : lo0;
    __shared__ float t[32][33];
    int n0 = blockIdx.x * 32, k0 = blockIdx.y * 32;
#pragma unroll
    for (int dy = 0; dy < 32; dy += 8) {
        int k = k0 + threadIdx.y + dy, n = n0 + threadIdx.x;
        t[threadIdx.y + dy][threadIdx.x] = (k < K && n < N) ? W[(size_t)k * N + n] : 0.f;
    }
    __syncthreads();
#pragma unroll
    for (int dy = 0; dy < 32; dy += 8) {
        int n = n0 + threadIdx.y + dy, k = k0 + threadIdx.x;
        if (n < N && k < K) {
            float v = t[threadIdx.x][threadIdx.y + dy];
            bf16 h = __float2bfloat16(v);
            hi[(size_t)n * K + k] = h;
            lo[(size_t)n * K + k] = __float2bfloat16(v - __bfloat162float(h));
        }
    }
}

__global__ void wtrans_kernel(const float* __restrict__ W, bf16* __restrict__ hi,
                              bf16* __restrict__ lo, int K, int N) {
    __shared__ float t[32][33];
    int n0 = blockIdx.x * 32, k0 = blockIdx.y * 32;
#pragma unroll
    for (int dy = 0; dy < 32; dy += 8) {
        int k = k0 + threadIdx.y + dy, n = n0 + threadIdx.x;
        t[threadIdx.y + dy][threadIdx.x] = (k < K && n < N) ? W[(size_t)k * N + n] : 0.f;
    }
    __syncthreads();
#pragma unroll
    for (int dy = 0; dy < 32; dy += 8) {
        int n = n0 + threadIdx.y + dy, k = k0 + threadIdx.x;
        if (n < N && k < K) {
            float v = t[threadIdx.x][threadIdx.y + dy];
            bf16 h = __float2bfloat16(v);
            hi[(size_t)n * K + k] = h;
            lo[(size_t)n * K + k] = __float2bfloat16(v - __bfloat162float(h));
        }
    }
}

__global__ void concat_bn_kernel(const float* b1a, const float* b1b,
                                 const float* ga,  const float* gb,
                                 const float* bea, const float* beb,
                                 const float* ma,  const float* mb,
                                 const float* va,  const float* vb) {
    int i = threadIdx.x + blockIdx.x * blockDim.x;
    if (i >= HID) return;
    g_bnb [i] = b1a[i];  g_bnb [HID + i] = b1b[i];
    g_bng [i] = ga[i];   g_bng [HID + i] = gb[i];
    g_bnbt[i] = bea[i];  g_bnbt[HID + i] = beb[i];
    g_bnm [i] = ma[i];   g_bnm [HID + i] = mb[i];
    g_bnv [i] = va[i];   g_bnv [HID + i] = vb[i];
}

__global__ void bias_fold_kernel(const float* __restrict__ l1b,
                                 const float* __restrict__ l2w,
                                 const float* __restrict__ l2b,
                                 float* __restrict__ outb) {
    int n = blockIdx.x * blockDim.x + threadIdx.x;
    if (n >= D_FC) return;
    float s = l2b[n];
    for (int k = 0; k < D_L1; k++)
        s += l1b[k] * l2w[(size_t)k * D_FC + n];
    outb[n] = s;
}

__global__ void bias_fold2_kernel(const float* __restrict__ b1,
                                  const float* __restrict__ ow,
                                  const float* __restrict__ outb,
                                  float* __restrict__ ball) {
    int j = threadIdx.x;
    if (j >= OUT_C) return;
    float s = outb[j];
    for (int n = 0; n < D_FC; n++)
        s += b1[n] * ow[(size_t)n * OUT_C + j];
    ball[j] = s;
}

// ---------------------------------------------------------------------------
// bf16x3 mma.sync GEMM: C[M,N] = A[M,K](lda) @ Bt[N,K]^T
// template: BM_T x BN_T tile, TH threads (TH/64 M-warps x 2 N-warps)
// ---------------------------------------------------------------------------
#define STAGES 4

template <int BM_T, int BN_T, int TH>
__global__ __launch_bounds__(TH, 1)
void gemm_mma_kernel(const bf16* __restrict__ Ah_g, const bf16* __restrict__ Al_g,
                     const bf16* __restrict__ Bh_g, const bf16* __restrict__ Bl_g,
                     bf16* __restrict__ Ch, bf16* __restrict__ Cl,
                     float* __restrict__ Cf,
                     const float* __restrict__ bias,
                     const float* __restrict__ gamma, const float* __restrict__ beta,
                     const float* __restrict__ mean,  const float* __restrict__ var,
                     int M, int N, int K, int lda, int ldc, int epi)
{
    constexpr int A_BY   = BM_T * 64;
    constexpr int B_BY   = BN_T * 64;
    constexpr int OFF_AL = A_BY;
    constexpr int OFF_BH = 2 * A_BY;
    constexpr int OFF_BL = 2 * A_BY + B_BY;
    constexpr int STG_B  = 2 * A_BY + 2 * B_BY;
    constexpr int WM     = TH / 64;          // M-warps
    constexpr int WTM    = BM_T / WM;        // warp tile M
    constexpr int NI     = WTM / 16;
    constexpr int NJ     = BN_T / 16;
    constexpr int NJJ    = BN_T / 32;
    constexpr int A_IDS  = BM_T * 8;
    constexpr int PER    = (BM_T * 8 + BN_T * 8) / TH;

    extern __shared__ __align__(128) char smem[];
    const uint32_t sb = smem_u32(smem);
    const int tid = threadIdx.x;
    const int lid = tid & 31, wid = tid >> 5;
    const int warpM = wid >> 1, warpN = wid & 1;
    const int m0 = blockIdx.y * BM_T, n0 = blockIdx.x * BN_T;
    const int NC = K >> 5;

    float acc[NI][NJ][4];
#pragma unroll
    for (int i = 0; i < NI; i++)
#pragma unroll
        for (int j = 0; j < NJ; j++)
#pragma unroll
            for (int q = 0; q < 4; q++) acc[i][j][q] = 0.0f;

    auto issue_stage = [&](int c, int s) {
        const int k0 = c << 5;
        const uint32_t stb = sb + s * STG_B;
#pragma unroll
        for (int q = 0; q < PER; q++) {
            int id = q * TH + tid;
            const bf16* base;
            uint32_t toff;
            int row, ch, gr, rmax, ld;
            if (id < A_IDS) {
                int half = id / (BM_T * 4);
                int idx = id % (BM_T * 4);
                row = idx >> 2; ch = idx & 3;
                base = half ? Al_g : Ah_g;
                toff = half ? (uint32_t)OFF_AL : 0u;
                gr = m0 + row; rmax = M; ld = lda;
            } else {
                int idB = id - A_IDS;
                int half = idB / (BN_T * 4);
                int idx = idB % (BN_T * 4);
                row = idx >> 2; ch = idx & 3;
                base = half ? Bl_g : Bh_g;
                toff = half ? (uint32_t)OFF_BL : (uint32_t)OFF_BH;
                gr = n0 + row; rmax = N; ld = K;
            }
            unsigned ok = (gr < rmax) ? 16u : 0u;
            int rc = (gr < rmax) ? gr : 0;
            const char* src = (const char*)(base + (size_t)rc * ld + k0) + ch * 16;
            uint32_t dst = stb + toff + row * 64 + ((ch ^ ((row >> 1) & 3)) << 4);
            CP_ASYNC(dst, src, ok);
        }
        CP_COMMIT();
    };

    issue_stage(0, 0);
    issue_stage(1, 1);
    issue_stage(2, 2);

    const int grp = lid >> 3, lr = lid & 7;

    int s = 0;
    for (int c = 0; c < NC; c++) {
        CP_WAIT2();
        __syncthreads();
        if (c + 3 < NC) issue_stage(c + 3, (s + 3) & 3);
        else CP_COMMIT();

        const uint32_t stb = sb + s * STG_B;
#pragma unroll
        for (int ks = 0; ks < 2; ks++) {
            uint32_t ah[NI][4];
#pragma unroll
            for (int i = 0; i < NI; i++) {
                int row = warpM * WTM + i * 16 + lr + ((grp & 1) << 3);
                int chk = 2 * ks + (grp >> 1);
                uint32_t ad = stb + row * 64 + ((chk ^ ((row >> 1) & 3)) << 4);
                LDSM4(ah[i], ad);
            }
            uint32_t bh[NJ][2];
#pragma unroll
            for (int jj = 0; jj < NJJ; jj++) {
                int row = warpN * (BN_T / 2) + jj * 16 + lr + ((grp >= 2) ? 8 : 0);
                int chk = 2 * ks + (grp & 1);
                uint32_t bd = stb + OFF_BH + row * 64 + ((chk ^ ((row >> 1) & 3)) << 4);
                uint32_t r[4];
                LDSM4(r, bd);
                bh[2 * jj][0] = r[0]; bh[2 * jj][1] = r[1];
                bh[2 * jj + 1][0] = r[2]; bh[2 * jj + 1][1] = r[3];
            }
#pragma unroll
            for (int i = 0; i < NI; i++)
#pragma unroll
                for (int j = 0; j < NJ; j++)
                    MMA_BF16(acc[i][j], ah[i], bh[j]);
            uint32_t al[NI][4];
#pragma unroll
            for (int i = 0; i < NI; i++) {
                int row = warpM * WTM + i * 16 + lr + ((grp & 1) << 3);
                int chk = 2 * ks + (grp >> 1);
                uint32_t ad = stb + OFF_AL + row * 64 + ((chk ^ ((row >> 1) & 3)) << 4);
                LDSM4(al[i], ad);
            }
            uint32_t bl[NJ][2];
#pragma unroll
            for (int jj = 0; jj < NJJ; jj++) {
                int row = warpN * (BN_T / 2) + jj * 16 + lr + ((grp >= 2) ? 8 : 0);
                int chk = 2 * ks + (grp & 1);
                uint32_t bd = stb + OFF_BL + row * 64 + ((chk ^ ((row >> 1) & 3)) << 4);
                uint32_t r[4];
                LDSM4(r, bd);
                bl[2 * jj][0] = r[0]; bl[2 * jj][1] = r[1];
                bl[2 * jj + 1][0] = r[2]; bl[2 * jj + 1][1] = r[3];
            }
#pragma unroll
            for (int i = 0; i < NI; i++)
#pragma unroll
                for (int j = 0; j < NJ; j++) {
                    MMA_BF16(acc[i][j], ah[i], bl[j]);
                    MMA_BF16(acc[i][j], al[i], bh[j]);
                }
        }
        s = (s + 1) & 3;
    }

    // ---- epilogue ----
    const int r_base = m0 + warpM * WTM + (lid >> 2);
    const int c_base = n0 + warpN * (BN_T / 2) + (lid & 3) * 2;
#pragma unroll
    for (int i = 0; i < NI; i++) {
#pragma unroll
        for (int half = 0; half < 2; half++) {
            int row = r_base + i * 16 + half * 8;
            if (row >= M) continue;
#pragma unroll
            for (int j = 0; j < NJ; j++) {
                int col = c_base + j * 8;
                if (col >= N) continue;
                float v0 = acc[i][j][half * 2 + 0] + bias[col];
                float v1 = acc[i][j][half * 2 + 1] + bias[col + 1];
                if (epi == EPI_BNRELU) {
                    v0 = (v0 - mean[col])     * rsqrtf(var[col] + BN_EPS)     * gamma[col]     + beta[col];
                    v1 = (v1 - mean[col + 1]) * rsqrtf(var[col + 1] + BN_EPS) * gamma[col + 1] + beta[col + 1];
                    v0 = fmaxf(v0, 0.0f); v1 = fmaxf(v1, 0.0f);
                } else if (epi == EPI_RELU) {
                    v0 = fmaxf(v0, 0.0f); v1 = fmaxf(v1, 0.0f);
                } else if (epi == EPI_LEAKY) {
                    v0 = (v0 > 0.0f) ? v0 : 0.01f * v0;
                    v1 = (v1 > 0.0f) ? v1 : 0.01f * v1;
                }
                if (epi == EPI_SIGMOID) {
                    float2 o;
                    o.x = 1.0f / (1.0f + expf(-v0));
                    o.y = 1.0f / (1.0f + expf(-v1));
                    *(float2*)(Cf + (size_t)row * ldc + col) = o;
                } else {
                    bf16 h0 = __float2bfloat16(v0);
                    bf16 h1 = __float2bfloat16(v1);
                    *(__nv_bfloat162*)(Ch + (size_t)row * ldc + col) = __nv_bfloat162(h0, h1);
                    *(__nv_bfloat162*)(Cl + (size_t)row * ldc + col) = __nv_bfloat162(
                        __float2bfloat16(v0 - __bfloat162float(h0)),
                        __float2bfloat16(v1 - __bfloat162float(h1)));
                }
            }
        }
    }
}

// ---------------------------------------------------------------------------
// launch helpers
// ---------------------------------------------------------------------------
template <int BM_T, int BN_T, int TH>
static void launch_gemm(cudaStream_t st,
                        const bf16* Ah, const bf16* Al, const bf16* Bh, const bf16* Bl,
                        bf16* Ch, bf16* Cl, float* Cf, const float* bias,
                        const float* ga, const float* be, const float* me, const float* va,
                        int M, int N, int K, int lda, int ldc, int epi) {
    dim3 grid((N + BN_T - 1) / BN_T, (M + BM_T - 1) / BM_T);
    int smem = STAGES * (2 * BM_T * 64 + 2 * BN_T * 64);
    gemm_mma_kernel<BM_T, BN_T, TH><<<grid, TH, smem, st>>>(Ah, Al, Bh, Bl, Ch, Cl, Cf, bias,
                                                            ga, be, me, va, M, N, K, lda, ldc, epi);
}

template <typename T> static T* sym(T* symbol) {
    void* p = nullptr;
    cudaGetSymbolAddress(&p, (const void*)symbol);
    return (T*)p;
}

extern "C" void kernel_launch(void* const* d_in, const int* in_sizes, int n_in,
                              void* d_out, int out_size) {
    const float* x  = (const float*)d_in[0];
    const int*   ei = (const int*)d_in[1];
    const float *w1a = (const float*)d_in[2],  *b1a = (const float*)d_in[3];
    const float *ga  = (const float*)d_in[4],  *bea = (const float*)d_in[5];
    const float *ma  = (const float*)d_in[6],  *va  = (const float*)d_in[7];
    const float *w2a = (const float*)d_in[8],  *b2a = (const float*)d_in[9];
    const float *w1b = (const float*)d_in[10], *b1b = (const float*)d_in[11];
    const float *gb  = (const float*)d_in[12], *beb = (const float*)d_in[13];
    const float *mb  = (const float*)d_in[14], *vb  = (const float*)d_in[15];
    const float *w2b = (const float*)d_in[16], *b2b = (const float*)d_in[17];
    const float *fcw = (const float*)d_in[18], *fcb = (const float*)d_in[19];
    const float *l1w = (const float*)d_in[20], *l1b = (const float*)d_in[21];
    const float *l2w = (const float*)d_in[22], *l2b = (const float*)d_in[23];
    const float *ow  = (const float*)d_in[24], *ob  = (const float*)d_in[25];
    float* out = (float*)d_out;

    // one-time host-handle setup (no device memory)
    static cudaStream_t s2 = nullptr, s3 = nullptr;
    static cudaEvent_t e1 = nullptr, e2 = nullptr, eW2 = nullptr, eFC = nullptr,
                       eM1 = nullptr, eB = nullptr;
    static bool attr = false;
    if (!attr) {
        cudaFuncSetAttribute(gemm_mma_kernel<256, 128, 512>,
                             cudaFuncAttributeMaxDynamicSharedMemorySize,
                             STAGES * (2 * 256 * 64 + 2 * 128 * 64));
        cudaFuncSetAttribute(gemm_mma_kernel<128, 64, 256>,
                             cudaFuncAttributeMaxDynamicSharedMemorySize,
                             STAGES * (2 * 128 * 64 + 2 * 64 * 64));
        cudaStreamCreateWithFlags(&s2, cudaStreamNonBlocking);
        cudaStreamCreateWithFlags(&s3, cudaStreamNonBlocking);
        cudaEventCreateWithFlags(&e1,  cudaEventDisableTiming);
        cudaEventCreateWithFlags(&e2,  cudaEventDisableTiming);
        cudaEventCreateWithFlags(&eW2, cudaEventDisableTiming);
        cudaEventCreateWithFlags(&eFC, cudaEventDisableTiming);
        cudaEventCreateWithFlags(&eM1, cudaEventDisableTiming);
        cudaEventCreateWithFlags(&eB,  cudaEventDisableTiming);
        attr = true;
    }

    float* h = sym(g_h);
    bf16 *hhi = sym(g_h_hi), *hlo = sym(g_h_lo);
    bf16 *thi = sym(g_t_hi), *tlo = sym(g_t_lo);
    bf16 *chi = sym(g_c_hi), *clo = sym(g_c_lo);
    bf16 *fhi = sym(g_fc_hi), *flo = sym(g_fc_lo);
    bf16 *w1h = sym(g_w1ab_hi), *w1l = sym(g_w1ab_lo);
    bf16 *w2ah = sym(g_w2a_hi), *w2al = sym(g_w2a_lo);
    bf16 *w2bh = sym(g_w2b_hi), *w2bl = sym(g_w2b_lo);
    bf16 *wfh = sym(g_wfc_hi), *wfl = sym(g_wfc_lo);
    bf16 *wl1h = sym(g_wl1_hi), *wl1l = sym(g_wl1_lo);
    bf16 *wl2h = sym(g_wl2_hi), *wl2l = sym(g_wl2_lo);
    bf16 *woh = sym(g_wo_hi), *wol = sym(g_wo_lo);
    bf16 *w2ch = sym(g_w2c_hi), *w2cl = sym(g_w2c_lo);
    bf16 *wallh = sym(g_wall_hi), *walll = sym(g_wall_lo);
    float *bias1 = sym(g_bias1), *ball = sym(g_ball), *zerob = sym(g_zerobias);
    float *bnb = sym(g_bnb), *bng = sym(g_bng), *bnbt = sym(g_bnbt);
    float *bnm = sym(g_bnm), *bnv = sym(g_bnv);

    const int n_edges = in_sizes[1] / 2;
    cudaStream_t ms = 0;   // main (default) stream

    // fork point
    cudaEventRecord(e1, ms);

    // ---- side chain (s2): weight prep ----
    cudaStreamWaitEvent(s2, e1, 0);
    {
        dim3 b(32, 8);
        wtrans2_kernel<<<dim3(HID / 32, HID / 32, 2), b, 0, s2>>>(
            w2a, w2b, w2ah, w2al, w2bh, w2bl, HID, HID);
        cudaEventRecord(eW2, s2);
        wtrans_kernel<<<dim3(D_FC / 32, D_CAT / 32), b, 0, s2>>>(fcw, wfh, wfl, D_CAT, D_FC);
        cudaEventRecord(eFC, s2);
        wtrans_kernel<<<dim3(OUT_C / 32, D_FC / 32), b, 0, s2>>>(ow, woh, wol, D_FC, OUT_C);
        int n14 = D_FC * D_L1 / 4;
        split2_kernel<<<(2 * n14 + 255) / 256, 256, 0, s2>>>(
            (const float4*)l1w, (const float4*)l2w,
            (uint2*)wl1h, (uint2*)wl1l, (uint2*)wl2h, (uint2*)wl2l, n14);
        bias_fold_kernel<<<D_FC / 256, 256, 0, s2>>>(l1b, l2w, l2b, bias1);
        bias_fold2_kernel<<<1, OUT_C, 0, s2>>>(bias1, ow, ob, ball);
        launch_gemm<128, 64, 256>(s2, woh, wol, wl2h, wl2l, w2ch, w2cl, 0, zerob, 0, 0, 0, 0,
                                  OUT_C, D_L1, D_FC, D_FC, D_L1, EPI_NONE);
        launch_gemm<128, 64, 256>(s2, w2ch, w2cl, wl1h, wl1l, wallh, walll, 0, zerob, 0, 0, 0, 0,
                                  OUT_C, D_FC, D_L1, D_L1, D_FC, EPI_NONE);
        cudaEventRecord(e2, s2);
    }

    // ---- main chain: x-dependent path ----
    {
        int n4 = NN * IN_C / 4;
        copy_x_kernel<<<(n4 + 255) / 256, 256, 0, ms>>>((const float4*)x, (float4*)h, n4);
        long long nthreads = (long long)n_edges * 32;
        edge_agg_kernel<<<(int)((nthreads + 255) / 256), 256, 0, ms>>>(x, ei, h, n_edges);
        split_kernel<<<(n4 + 255) / 256, 256, 0, ms>>>(
            (const float4*)h, (uint2*)hhi, (uint2*)hlo, n4);
        dim3 b(32, 8);
        wtrans2_kernel<<<dim3(HID / 32, IN_C / 32, 2), b, 0, ms>>>(
            w1a, w1b, w1h, w1l, w1h + HID * IN_C, w1l + HID * IN_C, IN_C, HID);
        concat_bn_kernel<<<2, 256, 0, ms>>>(b1a, b1b, ga, gb, bea, beb, ma, mb, va, vb);
    }
    // mm1
    launch_gemm<256, 128, 512>(ms, hhi, hlo, w1h, w1l, thi, tlo, 0, bnb, bng, bnbt, bnm, bnv,
                               NN, D_CAT, IN_C, IN_C, D_CAT, EPI_BNRELU);
    cudaEventRecord(eM1, ms);

    // mm2b on s3
    cudaStreamWaitEvent(s3, eM1, 0);
    cudaStreamWaitEvent(s3, eW2, 0);
    launch_gemm<256, 128, 512>(s3, thi + HID, tlo + HID, w2bh, w2bl, chi + HID, clo + HID, 0, b2b,
                               0, 0, 0, 0, NN, HID, HID, D_CAT, D_CAT, EPI_RELU);
    cudaEventRecord(eB, s3);

    // mm2a on ms
    cudaStreamWaitEvent(ms, eW2, 0);
    launch_gemm<256, 128, 512>(ms, thi, tlo, w2ah, w2al, chi, clo, 0, b2a, 0, 0, 0, 0,
                               NN, HID, HID, D_CAT, D_CAT, EPI_RELU);

    // fc
    cudaStreamWaitEvent(ms, eB, 0);
    cudaStreamWaitEvent(ms, eFC, 0);
    launch_gemm<256, 128, 512>(ms, chi, clo, wfh, wfl, fhi, flo, 0, fcb, 0, 0, 0, 0,
                               NN, D_FC, D_CAT, D_CAT, D_FC, EPI_LEAKY);

    // folded tail
    cudaStreamWaitEvent(ms, e2, 0);
    launch_gemm<128, 64, 256>(ms, fhi, flo, wallh, walll, 0, 0, out, ball, 0, 0, 0, 0,
                              NN, OUT_C, D_FC, D_FC, OUT_C, EPI_SIGMOID);
}

// round 13
// speedup vs baseline: 7.5619x; 1.3591x over previous
#include <cuda_runtime.h>
#include <cuda_fp16.h>
#include <math.h>
#include <stdint.h>

#define NN      60000
#define IN_C    128
#define HID     512
#define D_CAT   1024
#define D_FC    2048
#define D_L1    4096
#define OUT_C   64
#define BN_EPS  1e-5f

#define EPI_NONE    0
#define EPI_RELU    1
#define EPI_BNRELU  2
#define EPI_LEAKY   3
#define EPI_SIGMOID 4

typedef __half f16;

// ---------------------------------------------------------------------------
// Scratch (__device__ globals; no allocations allowed)
// ---------------------------------------------------------------------------
__device__ float g_h[(size_t)NN * IN_C];
__device__ f16  g_h_hi [(size_t)NN * IN_C ],  g_h_lo [(size_t)NN * IN_C ];
__device__ f16  g_t_hi [(size_t)NN * D_CAT],  g_t_lo [(size_t)NN * D_CAT];
__device__ f16  g_c_hi [(size_t)NN * D_CAT],  g_c_lo [(size_t)NN * D_CAT];
__device__ f16  g_fc_hi[(size_t)NN * D_FC ],  g_fc_lo[(size_t)NN * D_FC ];
// B-side weights: single fp16 [N,K]
__device__ f16 g_w1ab[D_CAT * IN_C];
__device__ f16 g_w2a[HID * HID];
__device__ f16 g_w2b[HID * HID];
__device__ f16 g_wfc[D_FC * D_CAT];
__device__ f16 g_wl1[(size_t)D_FC * D_L1];   // l1_w plain [2048,4096]
__device__ f16 g_wl2[(size_t)D_L1 * D_FC];   // l2_w plain [4096,2048]
// A-side weight: out_w^T split
__device__ f16 g_wo_hi[OUT_C * D_FC], g_wo_lo[OUT_C * D_FC];
// fold intermediates / results
__device__ f16  g_w2c_hi [OUT_C * D_L1],  g_w2c_lo [OUT_C * D_L1];   // (l2@out)^T
__device__ f16  g_wall_hi[OUT_C * D_FC],  g_wall_lo[OUT_C * D_FC];   // W_all^T
__device__ float g_bias1[D_FC];
__device__ float g_ball [OUT_C];
__device__ float g_zerobias[D_L1];
// concatenated BN params
__device__ float g_bnb[D_CAT], g_bng[D_CAT], g_bnbt[D_CAT], g_bnm[D_CAT], g_bnv[D_CAT];

// ---------------------------------------------------------------------------
// helpers
// ---------------------------------------------------------------------------
__device__ __forceinline__ uint32_t smem_u32(const void* p) {
    uint32_t a;
    asm("{ .reg .u64 t; cvta.to.shared.u64 t, %1; cvt.u32.u64 %0, t; }" : "=r"(a) : "l"(p));
    return a;
}

#define LDSM4(r, a) \
    asm volatile("ldmatrix.sync.aligned.m8n8.x4.shared.b16 {%0,%1,%2,%3}, [%4];" \
        : "=r"((r)[0]), "=r"((r)[1]), "=r"((r)[2]), "=r"((r)[3]) : "r"(a))

#define MMA_F16(d, a, b) \
    asm volatile("mma.sync.aligned.m16n8k16.row.col.f32.f16.f16.f32 " \
        "{%0,%1,%2,%3}, {%4,%5,%6,%7}, {%8,%9}, {%0,%1,%2,%3};" \
        : "+f"((d)[0]), "+f"((d)[1]), "+f"((d)[2]), "+f"((d)[3]) \
        : "r"((a)[0]), "r"((a)[1]), "r"((a)[2]), "r"((a)[3]), "r"((b)[0]), "r"((b)[1]))

#define CP_ASYNC(dst, src, ok) \
    asm volatile("cp.async.cg.shared.global [%0], [%1], 16, %2;" \
        :: "r"(dst), "l"(src), "r"(ok) : "memory")
#define CP_COMMIT()  asm volatile("cp.async.commit_group;" ::: "memory")
#define CP_WAIT2()   asm volatile("cp.async.wait_group 2;" ::: "memory")

// ---------------------------------------------------------------------------
// small kernels
// ---------------------------------------------------------------------------
__global__ void copy_x_kernel(const float4* __restrict__ x, float4* __restrict__ h, int n4) {
    int i = blockIdx.x * blockDim.x + threadIdx.x;
    if (i < n4) h[i] = x[i];
}

__global__ void edge_agg_kernel(const float* __restrict__ x, const int* __restrict__ ei,
                                float* __restrict__ h, int n_edges) {
    int warp = (blockIdx.x * blockDim.x + threadIdx.x) >> 5;
    int lane = threadIdx.x & 31;
    if (warp >= n_edges) return;
    int src = ei[warp];
    int dst = ei[n_edges + warp];
    const float4 v = *reinterpret_cast<const float4*>(x + (size_t)src * IN_C + lane * 4);
    float* d = h + (size_t)dst * IN_C + lane * 4;
    asm volatile("red.global.add.v4.f32 [%0], {%1, %2, %3, %4};"
                 :: "l"(d), "f"(v.x), "f"(v.y), "f"(v.z), "f"(v.w) : "memory");
}

// vectorized fp16 split: 4 floats / thread -> hi, lo
__device__ __forceinline__ void split4(float4 v, uint2& hiw, uint2& low) {
    __half2 h01 = __floats2half2_rn(v.x, v.y);
    __half2 h23 = __floats2half2_rn(v.z, v.w);
    __half2 l01 = __floats2half2_rn(v.x - __half2float(__low2half(h01)),
                                    v.y - __half2float(__high2half(h01)));
    __half2 l23 = __floats2half2_rn(v.z - __half2float(__low2half(h23)),
                                    v.w - __half2float(__high2half(h23)));
    hiw.x = *(uint32_t*)&h01; hiw.y = *(uint32_t*)&h23;
    low.x = *(uint32_t*)&l01; low.y = *(uint32_t*)&l23;
}

__global__ void split_kernel(const float4* __restrict__ in, uint2* __restrict__ hi,
                             uint2* __restrict__ lo, int n4) {
    int i = blockIdx.x * blockDim.x + threadIdx.x;
    if (i >= n4) return;
    uint2 H, L;
    split4(in[i], H, L);
    hi[i] = H; lo[i] = L;
}

// two plain fp32 -> single-fp16 conversions in one launch (B weights)
__global__ void conv2_kernel(const float4* __restrict__ a, const float4* __restrict__ b,
                             uint2* __restrict__ ao, uint2* __restrict__ bo, int n4) {
    int i = blockIdx.x * blockDim.x + threadIdx.x;
    const float4* src; uint2* dst; int idx;
    if (i < n4)          { src = a; dst = ao; idx = i; }
    else if (i < 2 * n4) { src = b; dst = bo; idx = i - n4; }
    else return;
    float4 v = src[idx];
    __half2 h01 = __floats2half2_rn(v.x, v.y);
    __half2 h23 = __floats2half2_rn(v.z, v.w);
    uint2 o; o.x = *(uint32_t*)&h01; o.y = *(uint32_t*)&h23;
    dst[idx] = o;
}

// paired transpose -> single fp16 (B weights): z selects (W, dst)
__global__ void wtrans2_kernel(const float* __restrict__ W0, const float* __restrict__ W1,
                               f16* o0, f16* o1, int K, int N) {
    const float* W = blockIdx.z ? W1 : W0;
    f16* o = blockIdx.z ? o1 : o0;
    __shared__ float t[32][33];
    int n0 = blockIdx.x * 32, k0 = blockIdx.y * 32;
#pragma unroll
    for (int dy = 0; dy < 32; dy += 8) {
        int k = k0 + threadIdx.y + dy, n = n0 + threadIdx.x;
        t[threadIdx.y + dy][threadIdx.x] = (k < K && n < N) ? W[(size_t)k * N + n] : 0.f;
    }
    __syncthreads();
#pragma unroll
    for (int dy = 0; dy < 32; dy += 8) {
        int n = n0 + threadIdx.y + dy, k = k0 + threadIdx.x;
        if (n < N && k < K)
            o[(size_t)n * K + k] = __float2half(t[threadIdx.x][threadIdx.y + dy]);
    }
}

// transpose -> single fp16 (B weight)
__global__ void wtrans_kernel(const float* __restrict__ W, f16* __restrict__ o, int K, int N) {
    __shared__ float t[32][33];
    int n0 = blockIdx.x * 32, k0 = blockIdx.y * 32;
#pragma unroll
    for (int dy = 0; dy < 32; dy += 8) {
        int k = k0 + threadIdx.y + dy, n = n0 + threadIdx.x;
        t[threadIdx.y + dy][threadIdx.x] = (k < K && n < N) ? W[(size_t)k * N + n] : 0.f;
    }
    __syncthreads();
#pragma unroll
    for (int dy = 0; dy < 32; dy += 8) {
        int n = n0 + threadIdx.y + dy, k = k0 + threadIdx.x;
        if (n < N && k < K)
            o[(size_t)n * K + k] = __float2half(t[threadIdx.x][threadIdx.y + dy]);
    }
}

// transpose -> fp16 split (A weight: out_w^T)
__global__ void wtrans_split_kernel(const float* __restrict__ W, f16* __restrict__ hi,
                                    f16* __restrict__ lo, int K, int N) {
    __shared__ float t[32][33];
    int n0 = blockIdx.x * 32, k0 = blockIdx.y * 32;
#pragma unroll
    for (int dy = 0; dy < 32; dy += 8) {
        int k = k0 + threadIdx.y + dy, n = n0 + threadIdx.x;
        t[threadIdx.y + dy][threadIdx.x] = (k < K && n < N) ? W[(size_t)k * N + n] : 0.f;
    }
    __syncthreads();
#pragma unroll
    for (int dy = 0; dy < 32; dy += 8) {
        int n = n0 + threadIdx.y + dy, k = k0 + threadIdx.x;
        if (n < N && k < K) {
            float v = t[threadIdx.x][threadIdx.y + dy];
            f16 h = __float2half(v);
            hi[(size_t)n * K + k] = h;
            lo[(size_t)n * K + k] = __float2half(v - __half2float(h));
        }
    }
}

__global__ void concat_bn_kernel(const float* b1a, const float* b1b,
                                 const float* ga,  const float* gb,
                                 const float* bea, const float* beb,
                                 const float* ma,  const float* mb,
                                 const float* va,  const float* vb) {
    int i = threadIdx.x + blockIdx.x * blockDim.x;
    if (i >= HID) return;
    g_bnb [i] = b1a[i];  g_bnb [HID + i] = b1b[i];
    g_bng [i] = ga[i];   g_bng [HID + i] = gb[i];
    g_bnbt[i] = bea[i];  g_bnbt[HID + i] = beb[i];
    g_bnm [i] = ma[i];   g_bnm [HID + i] = mb[i];
    g_bnv [i] = va[i];   g_bnv [HID + i] = vb[i];
}

__global__ void bias_fold_kernel(const float* __restrict__ l1b,
                                 const float* __restrict__ l2w,
                                 const float* __restrict__ l2b,
                                 float* __restrict__ outb) {
    int n = blockIdx.x * blockDim.x + threadIdx.x;
    if (n >= D_FC) return;
    float s = l2b[n];
    for (int k = 0; k < D_L1; k++)
        s += l1b[k] * l2w[(size_t)k * D_FC + n];
    outb[n] = s;
}

__global__ void bias_fold2_kernel(const float* __restrict__ b1,
                                  const float* __restrict__ ow,
                                  const float* __restrict__ outb,
                                  float* __restrict__ ball) {
    int j = threadIdx.x;
    if (j >= OUT_C) return;
    float s = outb[j];
    for (int n = 0; n < D_FC; n++)
        s += b1[n] * ow[(size_t)n * OUT_C + j];
    ball[j] = s;
}

// ---------------------------------------------------------------------------
// fp16x2 mma.sync GEMM: C[M,N] = (Ah+Al)[M,K](lda) @ B[N,K]^T  (B single fp16)
// template: BM_T x BN_T tile, TH threads (TH/64 M-warps x 2 N-warps)
// ---------------------------------------------------------------------------
#define STAGES 4

template <int BM_T, int BN_T, int TH>
__global__ __launch_bounds__(TH, 1)
void gemm_mma_kernel(const f16* __restrict__ Ah_g, const f16* __restrict__ Al_g,
                     const f16* __restrict__ Bh_g,
                     f16* __restrict__ Ch, f16* __restrict__ Cl,
                     float* __restrict__ Cf,
                     const float* __restrict__ bias,
                     const float* __restrict__ gamma, const float* __restrict__ beta,
                     const float* __restrict__ mean,  const float* __restrict__ var,
                     int M, int N, int K, int lda, int ldc, int epi)
{
    constexpr int A_BY   = BM_T * 64;
    constexpr int B_BY   = BN_T * 64;
    constexpr int OFF_AL = A_BY;
    constexpr int OFF_BH = 2 * A_BY;
    constexpr int STG_B  = 2 * A_BY + B_BY;
    constexpr int WM     = TH / 64;
    constexpr int WTM    = BM_T / WM;
    constexpr int NI     = WTM / 16;
    constexpr int NJ     = BN_T / 16;
    constexpr int NJJ    = BN_T / 32;
    constexpr int A_IDS  = BM_T * 8;          // hi + lo chunks
    constexpr int PER    = (BM_T * 8 + BN_T * 4) / TH;

    extern __shared__ __align__(128) char smem[];
    const uint32_t sb = smem_u32(smem);
    const int tid = threadIdx.x;
    const int lid = tid & 31, wid = tid >> 5;
    const int warpM = wid >> 1, warpN = wid & 1;
    const int m0 = blockIdx.y * BM_T, n0 = blockIdx.x * BN_T;
    const int NC = K >> 5;

    float acc[NI][NJ][4];
#pragma unroll
    for (int i = 0; i < NI; i++)
#pragma unroll
        for (int j = 0; j < NJ; j++)
#pragma unroll
            for (int q = 0; q < 4; q++) acc[i][j][q] = 0.0f;

    auto issue_stage = [&](int c, int s) {
        const int k0 = c << 5;
        const uint32_t stb = sb + s * STG_B;
#pragma unroll
        for (int q = 0; q < PER; q++) {
            int id = q * TH + tid;
            const f16* base;
            uint32_t toff;
            int row, ch, gr, rmax, ld;
            if (id < A_IDS) {
                int half_sel = id / (BM_T * 4);
                int idx = id % (BM_T * 4);
                row = idx >> 2; ch = idx & 3;
                base = half_sel ? Al_g : Ah_g;
                toff = half_sel ? (uint32_t)OFF_AL : 0u;
                gr = m0 + row; rmax = M; ld = lda;
            } else {
                int idx = id - A_IDS;     // 0 .. BN_T*4-1
                row = idx >> 2; ch = idx & 3;
                base = Bh_g;
                toff = (uint32_t)OFF_BH;
                gr = n0 + row; rmax = N; ld = K;
            }
            unsigned ok = (gr < rmax) ? 16u : 0u;
            int rc = (gr < rmax) ? gr : 0;
            const char* src = (const char*)(base + (size_t)rc * ld + k0) + ch * 16;
            uint32_t dst = stb + toff + row * 64 + ((ch ^ ((row >> 1) & 3)) << 4);
            CP_ASYNC(dst, src, ok);
        }
        CP_COMMIT();
    };

    issue_stage(0, 0);
    issue_stage(1, 1);
    issue_stage(2, 2);

    const int grp = lid >> 3, lr = lid & 7;

    int s = 0;
    for (int c = 0; c < NC; c++) {
        CP_WAIT2();
        __syncthreads();
        if (c + 3 < NC) issue_stage(c + 3, (s + 3) & 3);
        else CP_COMMIT();

        const uint32_t stb = sb + s * STG_B;
#pragma unroll
        for (int ks = 0; ks < 2; ks++) {
            uint32_t ah[NI][4];
#pragma unroll
            for (int i = 0; i < NI; i++) {
                int row = warpM * WTM + i * 16 + lr + ((grp & 1) << 3);
                int chk = 2 * ks + (grp >> 1);
                uint32_t ad = stb + row * 64 + ((chk ^ ((row >> 1) & 3)) << 4);
                LDSM4(ah[i], ad);
            }
            uint32_t bh[NJ][2];
#pragma unroll
            for (int jj = 0; jj < NJJ; jj++) {
                int row = warpN * (BN_T / 2) + jj * 16 + lr + ((grp >= 2) ? 8 : 0);
                int chk = 2 * ks + (grp & 1);
                uint32_t bd = stb + OFF_BH + row * 64 + ((chk ^ ((row >> 1) & 3)) << 4);
                uint32_t r[4];
                LDSM4(r, bd);
                bh[2 * jj][0] = r[0]; bh[2 * jj][1] = r[1];
                bh[2 * jj + 1][0] = r[2]; bh[2 * jj + 1][1] = r[3];
            }
#pragma unroll
            for (int i = 0; i < NI; i++)
#pragma unroll
                for (int j = 0; j < NJ; j++)
                    MMA_F16(acc[i][j], ah[i], bh[j]);
            uint32_t al[NI][4];
#pragma unroll
            for (int i = 0; i < NI; i++) {
                int row = warpM * WTM + i * 16 + lr + ((grp & 1) << 3);
                int chk = 2 * ks + (grp >> 1);
                uint32_t ad = stb + OFF_AL + row * 64 + ((chk ^ ((row >> 1) & 3)) << 4);
                LDSM4(al[i], ad);
            }
#pragma unroll
            for (int i = 0; i < NI; i++)
#pragma unroll
                for (int j = 0; j < NJ; j++)
                    MMA_F16(acc[i][j], al[i], bh[j]);
        }
        s = (s + 1) & 3;
    }

    // ---- epilogue ----
    const int r_base = m0 + warpM * WTM + (lid >> 2);
    const int c_base = n0 + warpN * (BN_T / 2) + (lid & 3) * 2;
#pragma unroll
    for (int i = 0; i < NI; i++) {
#pragma unroll
        for (int half_r = 0; half_r < 2; half_r++) {
            int row = r_base + i * 16 + half_r * 8;
            if (row >= M) continue;
#pragma unroll
            for (int j = 0; j < NJ; j++) {
                int col = c_base + j * 8;
                if (col >= N) continue;
                float v0 = acc[i][j][half_r * 2 + 0] + bias[col];
                float v1 = acc[i][j][half_r * 2 + 1] + bias[col + 1];
                if (epi == EPI_BNRELU) {
                    v0 = (v0 - mean[col])     * rsqrtf(var[col] + BN_EPS)     * gamma[col]     + beta[col];
                    v1 = (v1 - mean[col + 1]) * rsqrtf(var[col + 1] + BN_EPS) * gamma[col + 1] + beta[col + 1];
                    v0 = fmaxf(v0, 0.0f); v1 = fmaxf(v1, 0.0f);
                } else if (epi == EPI_RELU) {
                    v0 = fmaxf(v0, 0.0f); v1 = fmaxf(v1, 0.0f);
                } else if (epi == EPI_LEAKY) {
                    v0 = (v0 > 0.0f) ? v0 : 0.01f * v0;
                    v1 = (v1 > 0.0f) ? v1 : 0.01f * v1;
                }
                if (epi == EPI_SIGMOID) {
                    float2 o;
                    o.x = 1.0f / (1.0f + expf(-v0));
                    o.y = 1.0f / (1.0f + expf(-v1));
                    *(float2*)(Cf + (size_t)row * ldc + col) = o;
                } else {
                    __half2 H = __floats2half2_rn(v0, v1);
                    __half2 L = __floats2half2_rn(v0 - __half2float(__low2half(H)),
                                                  v1 - __half2float(__high2half(H)));
                    *(__half2*)(Ch + (size_t)row * ldc + col) = H;
                    *(__half2*)(Cl + (size_t)row * ldc + col) = L;
                }
            }
        }
    }
}

// ---------------------------------------------------------------------------
// launch helpers
// ---------------------------------------------------------------------------
template <int BM_T, int BN_T, int TH>
static void launch_gemm(cudaStream_t st,
                        const f16* Ah, const f16* Al, const f16* Bh,
                        f16* Ch, f16* Cl, float* Cf, const float* bias,
                        const float* ga, const float* be, const float* me, const float* va,
                        int M, int N, int K, int lda, int ldc, int epi) {
    dim3 grid((N + BN_T - 1) / BN_T, (M + BM_T - 1) / BM_T);
    int smem = STAGES * (2 * BM_T * 64 + BN_T * 64);
    gemm_mma_kernel<BM_T, BN_T, TH><<<grid, TH, smem, st>>>(Ah, Al, Bh, Ch, Cl, Cf, bias,
                                                            ga, be, me, va, M, N, K, lda, ldc, epi);
}

template <typename T> static T* sym(T* symbol) {
    void* p = nullptr;
    cudaGetSymbolAddress(&p, (const void*)symbol);
    return (T*)p;
}

extern "C" void kernel_launch(void* const* d_in, const int* in_sizes, int n_in,
                              void* d_out, int out_size) {
    const float* x  = (const float*)d_in[0];
    const int*   ei = (const int*)d_in[1];
    const float *w1a = (const float*)d_in[2],  *b1a = (const float*)d_in[3];
    const float *ga  = (const float*)d_in[4],  *bea = (const float*)d_in[5];
    const float *ma  = (const float*)d_in[6],  *va  = (const float*)d_in[7];
    const float *w2a = (const float*)d_in[8],  *b2a = (const float*)d_in[9];
    const float *w1b = (const float*)d_in[10], *b1b = (const float*)d_in[11];
    const float *gb  = (const float*)d_in[12], *beb = (const float*)d_in[13];
    const float *mb  = (const float*)d_in[14], *vb  = (const float*)d_in[15];
    const float *w2b = (const float*)d_in[16], *b2b = (const float*)d_in[17];
    const float *fcw = (const float*)d_in[18], *fcb = (const float*)d_in[19];
    const float *l1w = (const float*)d_in[20], *l1b = (const float*)d_in[21];
    const float *l2w = (const float*)d_in[22], *l2b = (const float*)d_in[23];
    const float *ow  = (const float*)d_in[24], *ob  = (const float*)d_in[25];
    float* out = (float*)d_out;

    // one-time host-handle setup (no device memory)
    static cudaStream_t s2 = nullptr, s3 = nullptr;
    static cudaEvent_t e1 = nullptr, e2 = nullptr, eW2 = nullptr, eFC = nullptr,
                       eM1 = nullptr, eB = nullptr;
    static bool attr = false;
    if (!attr) {
        cudaFuncSetAttribute(gemm_mma_kernel<256, 128, 512>,
                             cudaFuncAttributeMaxDynamicSharedMemorySize,
                             STAGES * (2 * 256 * 64 + 128 * 64));
        cudaFuncSetAttribute(gemm_mma_kernel<128, 64, 256>,
                             cudaFuncAttributeMaxDynamicSharedMemorySize,
                             STAGES * (2 * 128 * 64 + 64 * 64));
        cudaStreamCreateWithFlags(&s2, cudaStreamNonBlocking);
        cudaStreamCreateWithFlags(&s3, cudaStreamNonBlocking);
        cudaEventCreateWithFlags(&e1,  cudaEventDisableTiming);
        cudaEventCreateWithFlags(&e2,  cudaEventDisableTiming);
        cudaEventCreateWithFlags(&eW2, cudaEventDisableTiming);
        cudaEventCreateWithFlags(&eFC, cudaEventDisableTiming);
        cudaEventCreateWithFlags(&eM1, cudaEventDisableTiming);
        cudaEventCreateWithFlags(&eB,  cudaEventDisableTiming);
        attr = true;
    }

    float* h = sym(g_h);
    f16 *hhi = sym(g_h_hi), *hlo = sym(g_h_lo);
    f16 *thi = sym(g_t_hi), *tlo = sym(g_t_lo);
    f16 *chi = sym(g_c_hi), *clo = sym(g_c_lo);
    f16 *fhi = sym(g_fc_hi), *flo = sym(g_fc_lo);
    f16 *w1s = sym(g_w1ab);
    f16 *w2as = sym(g_w2a), *w2bs = sym(g_w2b);
    f16 *wfs = sym(g_wfc);
    f16 *wl1s = sym(g_wl1), *wl2s = sym(g_wl2);
    f16 *woh = sym(g_wo_hi), *wol = sym(g_wo_lo);
    f16 *w2ch = sym(g_w2c_hi), *w2cl = sym(g_w2c_lo);
    f16 *wallh = sym(g_wall_hi), *walll = sym(g_wall_lo);
    float *bias1 = sym(g_bias1), *ball = sym(g_ball), *zerob = sym(g_zerobias);
    float *bnb = sym(g_bnb), *bng = sym(g_bng), *bnbt = sym(g_bnbt);
    float *bnm = sym(g_bnm), *bnv = sym(g_bnv);

    const int n_edges = in_sizes[1] / 2;
    cudaStream_t ms = 0;

    cudaEventRecord(e1, ms);

    // ---- side chain (s2): weight prep ----
    cudaStreamWaitEvent(s2, e1, 0);
    {
        dim3 b(32, 8);
        wtrans2_kernel<<<dim3(HID / 32, HID / 32, 2), b, 0, s2>>>(
            w2a, w2b, w2as, w2bs, HID, HID);
        cudaEventRecord(eW2, s2);
        wtrans_kernel<<<dim3(D_FC / 32, D_CAT / 32), b, 0, s2>>>(fcw, wfs, D_CAT, D_FC);
        cudaEventRecord(eFC, s2);
        wtrans_split_kernel<<<dim3(OUT_C / 32, D_FC / 32), b, 0, s2>>>(ow, woh, wol, D_FC, OUT_C);
        int n14 = D_FC * D_L1 / 4;
        conv2_kernel<<<(2 * n14 + 255) / 256, 256, 0, s2>>>(
            (const float4*)l1w, (const float4*)l2w, (uint2*)wl1s, (uint2*)wl2s, n14);
        bias_fold_kernel<<<D_FC / 256, 256, 0, s2>>>(l1b, l2w, l2b, bias1);
        bias_fold2_kernel<<<1, OUT_C, 0, s2>>>(bias1, ow, ob, ball);
        // fold1: w2c = (out_w^T) @ l2_w^T   [64, 4096]
        launch_gemm<128, 64, 256>(s2, woh, wol, wl2s, w2ch, w2cl, 0, zerob, 0, 0, 0, 0,
                                  OUT_C, D_L1, D_FC, D_FC, D_L1, EPI_NONE);
        // fold2: wall = w2c @ l1_w^T   [64, 2048]
        launch_gemm<128, 64, 256>(s2, w2ch, w2cl, wl1s, wallh, walll, 0, zerob, 0, 0, 0, 0,
                                  OUT_C, D_FC, D_L1, D_L1, D_FC, EPI_NONE);
        cudaEventRecord(e2, s2);
    }

    // ---- main chain: x-dependent path ----
    {
        int n4 = NN * IN_C / 4;
        copy_x_kernel<<<(n4 + 255) / 256, 256, 0, ms>>>((const float4*)x, (float4*)h, n4);
        long long nthreads = (long long)n_edges * 32;
        edge_agg_kernel<<<(int)((nthreads + 255) / 256), 256, 0, ms>>>(x, ei, h, n_edges);
        split_kernel<<<(n4 + 255) / 256, 256, 0, ms>>>(
            (const float4*)h, (uint2*)hhi, (uint2*)hlo, n4);
        dim3 b(32, 8);
        wtrans2_kernel<<<dim3(HID / 32, IN_C / 32, 2), b, 0, ms>>>(
            w1a, w1b, w1s, w1s + HID * IN_C, IN_C, HID);
        concat_bn_kernel<<<2, 256, 0, ms>>>(b1a, b1b, ga, gb, bea, beb, ma, mb, va, vb);
    }
    // mm1
    launch_gemm<256, 128, 512>(ms, hhi, hlo, w1s, thi, tlo, 0, bnb, bng, bnbt, bnm, bnv,
                               NN, D_CAT, IN_C, IN_C, D_CAT, EPI_BNRELU);
    cudaEventRecord(eM1, ms);

    // mm2b on s3
    cudaStreamWaitEvent(s3, eM1, 0);
    cudaStreamWaitEvent(s3, eW2, 0);
    launch_gemm<256, 128, 512>(s3, thi + HID, tlo + HID, w2bs, chi + HID, clo + HID, 0, b2b,
                               0, 0, 0, 0, NN, HID, HID, D_CAT, D_CAT, EPI_RELU);
    cudaEventRecord(eB, s3);

    // mm2a on ms
    cudaStreamWaitEvent(ms, eW2, 0);
    launch_gemm<256, 128, 512>(ms, thi, tlo, w2as, chi, clo, 0, b2a, 0, 0, 0, 0,
                               NN, HID, HID, D_CAT, D_CAT, EPI_RELU);

    // fc
    cudaStreamWaitEvent(ms, eB, 0);
    cudaStreamWaitEvent(ms, eFC, 0);
    launch_gemm<256, 128, 512>(ms, chi, clo, wfs, fhi, flo, 0, fcb, 0, 0, 0, 0,
                               NN, D_FC, D_CAT, D_CAT, D_FC, EPI_LEAKY);

    // folded tail (B = wall hi plane)
    cudaStreamWaitEvent(ms, e2, 0);
    launch_gemm<128, 64, 256>(ms, fhi, flo, wallh, 0, 0, out, ball, 0, 0, 0, 0,
                              NN, OUT_C, D_FC, D_FC, OUT_C, EPI_SIGMOID);
}

// round 14
// speedup vs baseline: 11.8066x; 1.5613x over previous
#include <cuda_runtime.h>
#include <cuda_fp16.h>
#include <math.h>
#include <stdint.h>

#define NN      60000
#define IN_C    128
#define HID     512
#define D_CAT   1024
#define D_FC    2048
#define D_L1    4096
#define OUT_C   64
#define BN_EPS  1e-5f

#define EPI_NONE    0
#define EPI_RELU    1
#define EPI_BNRELU  2
#define EPI_LEAKY   3
#define EPI_SIGMOID 4

typedef __half f16;

// ---------------------------------------------------------------------------
// Scratch (__device__ globals; no allocations allowed)
// ---------------------------------------------------------------------------
__device__ float g_h[(size_t)NN * IN_C];
__device__ f16  g_hf [(size_t)NN * IN_C ];
__device__ f16  g_t  [(size_t)NN * D_CAT];
__device__ f16  g_c  [(size_t)NN * D_CAT];
__device__ f16  g_fc [(size_t)NN * D_FC ];
// weights fp16 [N,K]
__device__ f16 g_w1ab[D_CAT * IN_C];
__device__ f16 g_w2a[HID * HID];
__device__ f16 g_w2b[HID * HID];
__device__ f16 g_wfc[D_FC * D_CAT];
__device__ f16 g_wl1[(size_t)D_FC * D_L1];   // l1_w plain [2048,4096]
__device__ f16 g_wl2[(size_t)D_L1 * D_FC];   // l2_w plain [4096,2048]
__device__ f16 g_wo [OUT_C * D_FC];          // out_w^T
// fold intermediates / results
__device__ f16  g_w2c [OUT_C * D_L1];        // (l2@out)^T
__device__ f16  g_wall[OUT_C * D_FC];        // W_all^T
__device__ float g_bias1[D_FC];
__device__ float g_ball [OUT_C];
__device__ float g_zerobias[D_L1];
// concatenated BN params
__device__ float g_bnb[D_CAT], g_bng[D_CAT], g_bnbt[D_CAT], g_bnm[D_CAT], g_bnv[D_CAT];

// ---------------------------------------------------------------------------
// helpers
// ---------------------------------------------------------------------------
__device__ __forceinline__ uint32_t smem_u32(const void* p) {
    uint32_t a;
    asm("{ .reg .u64 t; cvta.to.shared.u64 t, %1; cvt.u32.u64 %0, t; }" : "=r"(a) : "l"(p));
    return a;
}

#define LDSM4(r, a) \
    asm volatile("ldmatrix.sync.aligned.m8n8.x4.shared.b16 {%0,%1,%2,%3}, [%4];" \
        : "=r"((r)[0]), "=r"((r)[1]), "=r"((r)[2]), "=r"((r)[3]) : "r"(a))

#define MMA_F16(d, a, b) \
    asm volatile("mma.sync.aligned.m16n8k16.row.col.f32.f16.f16.f32 " \
        "{%0,%1,%2,%3}, {%4,%5,%6,%7}, {%8,%9}, {%0,%1,%2,%3};" \
        : "+f"((d)[0]), "+f"((d)[1]), "+f"((d)[2]), "+f"((d)[3]) \
        : "r"((a)[0]), "r"((a)[1]), "r"((a)[2]), "r"((a)[3]), "r"((b)[0]), "r"((b)[1]))

#define CP_ASYNC(dst, src, ok) \
    asm volatile("cp.async.cg.shared.global [%0], [%1], 16, %2;" \
        :: "r"(dst), "l"(src), "r"(ok) : "memory")
#define CP_COMMIT()  asm volatile("cp.async.commit_group;" ::: "memory")
#define CP_WAIT2()   asm volatile("cp.async.wait_group 2;" ::: "memory")

// ---------------------------------------------------------------------------
// small kernels
// ---------------------------------------------------------------------------
__global__ void copy_x_kernel(const float4* __restrict__ x, float4* __restrict__ h, int n4) {
    int i = blockIdx.x * blockDim.x + threadIdx.x;
    if (i < n4) h[i] = x[i];
}

__global__ void edge_agg_kernel(const float* __restrict__ x, const int* __restrict__ ei,
                                float* __restrict__ h, int n_edges) {
    int warp = (blockIdx.x * blockDim.x + threadIdx.x) >> 5;
    int lane = threadIdx.x & 31;
    if (warp >= n_edges) return;
    int src = ei[warp];
    int dst = ei[n_edges + warp];
    const float4 v = *reinterpret_cast<const float4*>(x + (size_t)src * IN_C + lane * 4);
    float* d = h + (size_t)dst * IN_C + lane * 4;
    asm volatile("red.global.add.v4.f32 [%0], {%1, %2, %3, %4};"
                 :: "l"(d), "f"(v.x), "f"(v.y), "f"(v.z), "f"(v.w) : "memory");
}

// fp32 -> fp16 convert, 4 / thread
__global__ void conv_kernel(const float4* __restrict__ in, uint2* __restrict__ o, int n4) {
    int i = blockIdx.x * blockDim.x + threadIdx.x;
    if (i >= n4) return;
    float4 v = in[i];
    __half2 h01 = __floats2half2_rn(v.x, v.y);
    __half2 h23 = __floats2half2_rn(v.z, v.w);
    uint2 u; u.x = *(uint32_t*)&h01; u.y = *(uint32_t*)&h23;
    o[i] = u;
}

// two fp32 -> fp16 converts in one launch
__global__ void conv2_kernel(const float4* __restrict__ a, const float4* __restrict__ b,
                             uint2* __restrict__ ao, uint2* __restrict__ bo, int n4) {
    int i = blockIdx.x * blockDim.x + threadIdx.x;
    const float4* src; uint2* dst; int idx;
    if (i < n4)          { src = a; dst = ao; idx = i; }
    else if (i < 2 * n4) { src = b; dst = bo; idx = i - n4; }
    else return;
    float4 v = src[idx];
    __half2 h01 = __floats2half2_rn(v.x, v.y);
    __half2 h23 = __floats2half2_rn(v.z, v.w);
    uint2 u; u.x = *(uint32_t*)&h01; u.y = *(uint32_t*)&h23;
    dst[idx] = u;
}

// paired transpose -> fp16: z selects (W, dst)
__global__ void wtrans2_kernel(const float* __restrict__ W0, const float* __restrict__ W1,
                               f16* o0, f16* o1, int K, int N) {
    const float* W = blockIdx.z ? W1 : W0;
    f16* o = blockIdx.z ? o1 : o0;
    __shared__ float t[32][33];
    int n0 = blockIdx.x * 32, k0 = blockIdx.y * 32;
#pragma unroll
    for (int dy = 0; dy < 32; dy += 8) {
        int k = k0 + threadIdx.y + dy, n = n0 + threadIdx.x;
        t[threadIdx.y + dy][threadIdx.x] = (k < K && n < N) ? W[(size_t)k * N + n] : 0.f;
    }
    __syncthreads();
#pragma unroll
    for (int dy = 0; dy < 32; dy += 8) {
        int n = n0 + threadIdx.y + dy, k = k0 + threadIdx.x;
        if (n < N && k < K)
            o[(size_t)n * K + k] = __float2half(t[threadIdx.x][threadIdx.y + dy]);
    }
}

__global__ void wtrans_kernel(const float* __restrict__ W, f16* __restrict__ o, int K, int N) {
    __shared__ float t[32][33];
    int n0 = blockIdx.x * 32, k0 = blockIdx.y * 32;
#pragma unroll
    for (int dy = 0; dy < 32; dy += 8) {
        int k = k0 + threadIdx.y + dy, n = n0 + threadIdx.x;
        t[threadIdx.y + dy][threadIdx.x] = (k < K && n < N) ? W[(size_t)k * N + n] : 0.f;
    }
    __syncthreads();
#pragma unroll
    for (int dy = 0; dy < 32; dy += 8) {
        int n = n0 + threadIdx.y + dy, k = k0 + threadIdx.x;
        if (n < N && k < K)
            o[(size_t)n * K + k] = __float2half(t[threadIdx.x][threadIdx.y + dy]);
    }
}

__global__ void concat_bn_kernel(const float* b1a, const float* b1b,
                                 const float* ga,  const float* gb,
                                 const float* bea, const float* beb,
                                 const float* ma,  const float* mb,
                                 const float* va,  const float* vb) {
    int i = threadIdx.x + blockIdx.x * blockDim.x;
    if (i >= HID) return;
    g_bnb [i] = b1a[i];  g_bnb [HID + i] = b1b[i];
    g_bng [i] = ga[i];   g_bng [HID + i] = gb[i];
    g_bnbt[i] = bea[i];  g_bnbt[HID + i] = beb[i];
    g_bnm [i] = ma[i];   g_bnm [HID + i] = mb[i];
    g_bnv [i] = va[i];   g_bnv [HID + i] = vb[i];
}

__global__ void bias_fold_kernel(const float* __restrict__ l1b,
                                 const float* __restrict__ l2w,
                                 const float* __restrict__ l2b,
                                 float* __restrict__ outb) {
    int n = blockIdx.x * blockDim.x + threadIdx.x;
    if (n >= D_FC) return;
    float s = l2b[n];
    for (int k = 0; k < D_L1; k++)
        s += l1b[k] * l2w[(size_t)k * D_FC + n];
    outb[n] = s;
}

__global__ void bias_fold2_kernel(const float* __restrict__ b1,
                                  const float* __restrict__ ow,
                                  const float* __restrict__ outb,
                                  float* __restrict__ ball) {
    int j = threadIdx.x;
    if (j >= OUT_C) return;
    float s = outb[j];
    for (int n = 0; n < D_FC; n++)
        s += b1[n] * ow[(size_t)n * OUT_C + j];
    ball[j] = s;
}

// ---------------------------------------------------------------------------
// fp16 mma.sync GEMM: C[M,N] = A[M,K](lda) @ B[N,K]^T, fp32 accumulate
// template: BM_T x BN_T tile, TH threads (TH/64 M-warps x 2 N-warps)
// ---------------------------------------------------------------------------
#define STAGES 4

template <int BM_T, int BN_T, int TH>
__global__ __launch_bounds__(TH, 1)
void gemm_mma_kernel(const f16* __restrict__ A_g, const f16* __restrict__ B_g,
                     f16* __restrict__ C16, float* __restrict__ Cf,
                     const float* __restrict__ bias,
                     const float* __restrict__ gamma, const float* __restrict__ beta,
                     const float* __restrict__ mean,  const float* __restrict__ var,
                     int M, int N, int K, int lda, int ldc, int epi)
{
    constexpr int A_BY   = BM_T * 64;
    constexpr int B_BY   = BN_T * 64;
    constexpr int OFF_B  = A_BY;
    constexpr int STG_B  = A_BY + B_BY;
    constexpr int WM     = TH / 64;
    constexpr int WTM    = BM_T / WM;
    constexpr int NI     = WTM / 16;
    constexpr int NJ     = BN_T / 16;
    constexpr int NJJ    = BN_T / 32;
    constexpr int A_IDS  = BM_T * 4;
    constexpr int PER    = (BM_T * 4 + BN_T * 4) / TH;

    extern __shared__ __align__(128) char smem[];
    const uint32_t sb = smem_u32(smem);
    const int tid = threadIdx.x;
    const int lid = tid & 31, wid = tid >> 5;
    const int warpM = wid >> 1, warpN = wid & 1;
    const int m0 = blockIdx.y * BM_T, n0 = blockIdx.x * BN_T;
    const int NC = K >> 5;

    float acc[NI][NJ][4];
#pragma unroll
    for (int i = 0; i < NI; i++)
#pragma unroll
        for (int j = 0; j < NJ; j++)
#pragma unroll
            for (int q = 0; q < 4; q++) acc[i][j][q] = 0.0f;

    auto issue_stage = [&](int c, int s) {
        const int k0 = c << 5;
        const uint32_t stb = sb + s * STG_B;
#pragma unroll
        for (int q = 0; q < PER; q++) {
            int id = q * TH + tid;
            const f16* base;
            uint32_t toff;
            int row, ch, gr, rmax, ld;
            if (id < A_IDS) {
                row = id >> 2; ch = id & 3;
                base = A_g; toff = 0u;
                gr = m0 + row; rmax = M; ld = lda;
            } else {
                int idx = id - A_IDS;
                row = idx >> 2; ch = idx & 3;
                base = B_g; toff = (uint32_t)OFF_B;
                gr = n0 + row; rmax = N; ld = K;
            }
            unsigned ok = (gr < rmax) ? 16u : 0u;
            int rc = (gr < rmax) ? gr : 0;
            const char* src = (const char*)(base + (size_t)rc * ld + k0) + ch * 16;
            uint32_t dst = stb + toff + row * 64 + ((ch ^ ((row >> 1) & 3)) << 4);
            CP_ASYNC(dst, src, ok);
        }
        CP_COMMIT();
    };

    issue_stage(0, 0);
    issue_stage(1, 1);
    issue_stage(2, 2);

    const int grp = lid >> 3, lr = lid & 7;

    int s = 0;
    for (int c = 0; c < NC; c++) {
        CP_WAIT2();
        __syncthreads();
        if (c + 3 < NC) issue_stage(c + 3, (s + 3) & 3);
        else CP_COMMIT();

        const uint32_t stb = sb + s * STG_B;
#pragma unroll
        for (int ks = 0; ks < 2; ks++) {
            uint32_t a[NI][4];
#pragma unroll
            for (int i = 0; i < NI; i++) {
                int row = warpM * WTM + i * 16 + lr + ((grp & 1) << 3);
                int chk = 2 * ks + (grp >> 1);
                uint32_t ad = stb + row * 64 + ((chk ^ ((row >> 1) & 3)) << 4);
                LDSM4(a[i], ad);
            }
            uint32_t b[NJ][2];
#pragma unroll
            for (int jj = 0; jj < NJJ; jj++) {
                int row = warpN * (BN_T / 2) + jj * 16 + lr + ((grp >= 2) ? 8 : 0);
                int chk = 2 * ks + (grp & 1);
                uint32_t bd = stb + OFF_B + row * 64 + ((chk ^ ((row >> 1) & 3)) << 4);
                uint32_t r[4];
                LDSM4(r, bd);
                b[2 * jj][0] = r[0]; b[2 * jj][1] = r[1];
                b[2 * jj + 1][0] = r[2]; b[2 * jj + 1][1] = r[3];
            }
#pragma unroll
            for (int i = 0; i < NI; i++)
#pragma unroll
                for (int j = 0; j < NJ; j++)
                    MMA_F16(acc[i][j], a[i], b[j]);
        }
        s = (s + 1) & 3;
    }

    // ---- epilogue ----
    const int r_base = m0 + warpM * WTM + (lid >> 2);
    const int c_base = n0 + warpN * (BN_T / 2) + (lid & 3) * 2;
#pragma unroll
    for (int i = 0; i < NI; i++) {
#pragma unroll
        for (int half_r = 0; half_r < 2; half_r++) {
            int row = r_base + i * 16 + half_r * 8;
            if (row >= M) continue;
#pragma unroll
            for (int j = 0; j < NJ; j++) {
                int col = c_base + j * 8;
                if (col >= N) continue;
                float v0 = acc[i][j][half_r * 2 + 0] + bias[col];
                float v1 = acc[i][j][half_r * 2 + 1] + bias[col + 1];
                if (epi == EPI_BNRELU) {
                    v0 = (v0 - mean[col])     * rsqrtf(var[col] + BN_EPS)     * gamma[col]     + beta[col];
                    v1 = (v1 - mean[col + 1]) * rsqrtf(var[col + 1] + BN_EPS) * gamma[col + 1] + beta[col + 1];
                    v0 = fmaxf(v0, 0.0f); v1 = fmaxf(v1, 0.0f);
                } else if (epi == EPI_RELU) {
                    v0 = fmaxf(v0, 0.0f); v1 = fmaxf(v1, 0.0f);
                } else if (epi == EPI_LEAKY) {
                    v0 = (v0 > 0.0f) ? v0 : 0.01f * v0;
                    v1 = (v1 > 0.0f) ? v1 : 0.01f * v1;
                }
                if (epi == EPI_SIGMOID) {
                    float2 o;
                    o.x = 1.0f / (1.0f + expf(-v0));
                    o.y = 1.0f / (1.0f + expf(-v1));
                    *(float2*)(Cf + (size_t)row * ldc + col) = o;
                } else {
                    *(__half2*)(C16 + (size_t)row * ldc + col) = __floats2half2_rn(v0, v1);
                }
            }
        }
    }
}

// ---------------------------------------------------------------------------
// launch helpers
// ---------------------------------------------------------------------------
template <int BM_T, int BN_T, int TH>
static void launch_gemm(cudaStream_t st,
                        const f16* A, const f16* B,
                        f16* C16, float* Cf, const float* bias,
                        const float* ga, const float* be, const float* me, const float* va,
                        int M, int N, int K, int lda, int ldc, int epi) {
    dim3 grid((N + BN_T - 1) / BN_T, (M + BM_T - 1) / BM_T);
    int smem = STAGES * (BM_T * 64 + BN_T * 64);
    gemm_mma_kernel<BM_T, BN_T, TH><<<grid, TH, smem, st>>>(A, B, C16, Cf, bias,
                                                            ga, be, me, va, M, N, K, lda, ldc, epi);
}

template <typename T> static T* sym(T* symbol) {
    void* p = nullptr;
    cudaGetSymbolAddress(&p, (const void*)symbol);
    return (T*)p;
}

extern "C" void kernel_launch(void* const* d_in, const int* in_sizes, int n_in,
                              void* d_out, int out_size) {
    const float* x  = (const float*)d_in[0];
    const int*   ei = (const int*)d_in[1];
    const float *w1a = (const float*)d_in[2],  *b1a = (const float*)d_in[3];
    const float *ga  = (const float*)d_in[4],  *bea = (const float*)d_in[5];
    const float *ma  = (const float*)d_in[6],  *va  = (const float*)d_in[7];
    const float *w2a = (const float*)d_in[8],  *b2a = (const float*)d_in[9];
    const float *w1b = (const float*)d_in[10], *b1b = (const float*)d_in[11];
    const float *gb  = (const float*)d_in[12], *beb = (const float*)d_in[13];
    const float *mb  = (const float*)d_in[14], *vb  = (const float*)d_in[15];
    const float *w2b = (const float*)d_in[16], *b2b = (const float*)d_in[17];
    const float *fcw = (const float*)d_in[18], *fcb = (const float*)d_in[19];
    const float *l1w = (const float*)d_in[20], *l1b = (const float*)d_in[21];
    const float *l2w = (const float*)d_in[22], *l2b = (const float*)d_in[23];
    const float *ow  = (const float*)d_in[24], *ob  = (const float*)d_in[25];
    float* out = (float*)d_out;

    // one-time host-handle setup (no device memory)
    static cudaStream_t s2 = nullptr, s3 = nullptr;
    static cudaEvent_t e1 = nullptr, e2 = nullptr, eW2 = nullptr, eFC = nullptr,
                       eM1 = nullptr, eB = nullptr;
    static bool attr = false;
    if (!attr) {
        cudaFuncSetAttribute(gemm_mma_kernel<256, 128, 512>,
                             cudaFuncAttributeMaxDynamicSharedMemorySize,
                             STAGES * (256 * 64 + 128 * 64));
        cudaFuncSetAttribute(gemm_mma_kernel<128, 64, 256>,
                             cudaFuncAttributeMaxDynamicSharedMemorySize,
                             STAGES * (128 * 64 + 64 * 64));
        cudaStreamCreateWithFlags(&s2, cudaStreamNonBlocking);
        cudaStreamCreateWithFlags(&s3, cudaStreamNonBlocking);
        cudaEventCreateWithFlags(&e1,  cudaEventDisableTiming);
        cudaEventCreateWithFlags(&e2,  cudaEventDisableTiming);
        cudaEventCreateWithFlags(&eW2, cudaEventDisableTiming);
        cudaEventCreateWithFlags(&eFC, cudaEventDisableTiming);
        cudaEventCreateWithFlags(&eM1, cudaEventDisableTiming);
        cudaEventCreateWithFlags(&eB,  cudaEventDisableTiming);
        attr = true;
    }

    float* h = sym(g_h);
    f16 *hf  = sym(g_hf);
    f16 *t   = sym(g_t);
    f16 *c   = sym(g_c);
    f16 *fcv = sym(g_fc);
    f16 *w1s = sym(g_w1ab);
    f16 *w2as = sym(g_w2a), *w2bs = sym(g_w2b);
    f16 *wfs = sym(g_wfc);
    f16 *wl1s = sym(g_wl1), *wl2s = sym(g_wl2);
    f16 *wos = sym(g_wo);
    f16 *w2c = sym(g_w2c);
    f16 *wall = sym(g_wall);
    float *bias1 = sym(g_bias1), *ball = sym(g_ball), *zerob = sym(g_zerobias);
    float *bnb = sym(g_bnb), *bng = sym(g_bng), *bnbt = sym(g_bnbt);
    float *bnm = sym(g_bnm), *bnv = sym(g_bnv);

    const int n_edges = in_sizes[1] / 2;
    cudaStream_t ms = 0;

    cudaEventRecord(e1, ms);

    // ---- side chain (s2): weight prep ----
    cudaStreamWaitEvent(s2, e1, 0);
    {
        dim3 b(32, 8);
        wtrans2_kernel<<<dim3(HID / 32, HID / 32, 2), b, 0, s2>>>(
            w2a, w2b, w2as, w2bs, HID, HID);
        cudaEventRecord(eW2, s2);
        wtrans_kernel<<<dim3(D_FC / 32, D_CAT / 32), b, 0, s2>>>(fcw, wfs, D_CAT, D_FC);
        cudaEventRecord(eFC, s2);
        wtrans_kernel<<<dim3(OUT_C / 32, D_FC / 32), b, 0, s2>>>(ow, wos, D_FC, OUT_C);
        int n14 = D_FC * D_L1 / 4;
        conv2_kernel<<<(2 * n14 + 255) / 256, 256, 0, s2>>>(
            (const float4*)l1w, (const float4*)l2w, (uint2*)wl1s, (uint2*)wl2s, n14);
        bias_fold_kernel<<<D_FC / 256, 256, 0, s2>>>(l1b, l2w, l2b, bias1);
        bias_fold2_kernel<<<1, OUT_C, 0, s2>>>(bias1, ow, ob, ball);
        // fold1: w2c = (out_w^T) @ l2_w^T   [64, 4096]
        launch_gemm<128, 64, 256>(s2, wos, wl2s, w2c, 0, zerob, 0, 0, 0, 0,
                                  OUT_C, D_L1, D_FC, D_FC, D_L1, EPI_NONE);
        // fold2: wall = w2c @ l1_w^T   [64, 2048]
        launch_gemm<128, 64, 256>(s2, w2c, wl1s, wall, 0, zerob, 0, 0, 0, 0,
                                  OUT_C, D_FC, D_L1, D_L1, D_FC, EPI_NONE);
        cudaEventRecord(e2, s2);
    }

    // ---- main chain: x-dependent path ----
    {
        int n4 = NN * IN_C / 4;
        copy_x_kernel<<<(n4 + 255) / 256, 256, 0, ms>>>((const float4*)x, (float4*)h, n4);
        long long nthreads = (long long)n_edges * 32;
        edge_agg_kernel<<<(int)((nthreads + 255) / 256), 256, 0, ms>>>(x, ei, h, n_edges);
        conv_kernel<<<(n4 + 255) / 256, 256, 0, ms>>>((const float4*)h, (uint2*)hf, n4);
        dim3 b(32, 8);
        wtrans2_kernel<<<dim3(HID / 32, IN_C / 32, 2), b, 0, ms>>>(
            w1a, w1b, w1s, w1s + HID * IN_C, IN_C, HID);
        concat_bn_kernel<<<2, 256, 0, ms>>>(b1a, b1b, ga, gb, bea, beb, ma, mb, va, vb);
    }
    // mm1
    launch_gemm<256, 128, 512>(ms, hf, w1s, t, 0, bnb, bng, bnbt, bnm, bnv,
                               NN, D_CAT, IN_C, IN_C, D_CAT, EPI_BNRELU);
    cudaEventRecord(eM1, ms);

    // mm2b on s3
    cudaStreamWaitEvent(s3, eM1, 0);
    cudaStreamWaitEvent(s3, eW2, 0);
    launch_gemm<256, 128, 512>(s3, t + HID, w2bs, c + HID, 0, b2b,
                               0, 0, 0, 0, NN, HID, HID, D_CAT, D_CAT, EPI_RELU);
    cudaEventRecord(eB, s3);

    // mm2a on ms
    cudaStreamWaitEvent(ms, eW2, 0);
    launch_gemm<256, 128, 512>(ms, t, w2as, c, 0, b2a, 0, 0, 0, 0,
                               NN, HID, HID, D_CAT, D_CAT, EPI_RELU);

    // fc
    cudaStreamWaitEvent(ms, eB, 0);
    cudaStreamWaitEvent(ms, eFC, 0);
    launch_gemm<256, 128, 512>(ms, c, wfs, fcv, 0, fcb, 0, 0, 0, 0,
                               NN, D_FC, D_CAT, D_CAT, D_FC, EPI_LEAKY);

    // folded tail
    cudaStreamWaitEvent(ms, e2, 0);
    launch_gemm<128, 64, 256>(ms, fcv, wall, 0, out, ball, 0, 0, 0, 0,
                              NN, OUT_C, D_FC, D_FC, OUT_C, EPI_SIGMOID);
}